// round 1
// baseline (speedup 1.0000x reference)
#include <cuda_runtime.h>
#include <math.h>

#define B_ 2
#define T_ 2048
#define DM 768
#define NH 12
#define NKV 4
#define DH 64
#define WIN 512
#define GLB 64
#define MROWS (B_*T_)          // 4096

// ---------------- scratch (no dynamic allocation allowed) ----------------
__device__ float g_qf[MROWS*DM];          // x@wq   [4096,768]
__device__ float g_kf[MROWS*NKV*DH];      // x@wk   [4096,256]
__device__ float g_vf[MROWS*NKV*DH];      // x@wv   [4096,256]
__device__ float g_qr[(size_t)B_*NH*T_*DH];   // roped q [B,H,T,D]
__device__ float g_ao[MROWS*DM];          // attention out [B*T, H*D]
__device__ float g_kr[(size_t)B_*NKV*T_*DH];  // fallback k out
__device__ float g_vr[(size_t)B_*NKV*T_*DH];  // fallback v out

// ---------------- tiled fp32 GEMM: C[M,N] = A[M,K] @ B[K,N] ----------------
// 64x64 tile, K-step 32, 256 threads, 4x4 per thread.
__global__ void gemm_kernel(const float* __restrict__ A, const float* __restrict__ Bm,
                            float* __restrict__ C, int M, int N, int K) {
    __shared__ float As[64][33];                 // As[m][kk], pad -> conflict-free
    __shared__ __align__(16) float Bs[32][64];   // Bs[kk][n]
    int bm = blockIdx.y * 64, bn = blockIdx.x * 64;
    int tid = threadIdx.x;
    int ty = tid >> 4, tx = tid & 15;
    float acc[4][4] = {};

    for (int k0 = 0; k0 < K; k0 += 32) {
        #pragma unroll
        for (int r = 0; r < 8; r++) {            // load A 64x32 (coalesced rows)
            int e = tid + r * 256;
            int m = e >> 5, kk = e & 31;
            As[m][kk] = A[(size_t)(bm + m) * K + k0 + kk];
        }
        #pragma unroll
        for (int r = 0; r < 8; r++) {            // load B 32x64 (coalesced rows)
            int e = tid + r * 256;
            int kk = e >> 6, n = e & 63;
            Bs[kk][n] = Bm[(size_t)(k0 + kk) * N + bn + n];
        }
        __syncthreads();
        #pragma unroll
        for (int kk = 0; kk < 32; kk++) {
            float a0 = As[ty*4+0][kk], a1 = As[ty*4+1][kk];
            float a2 = As[ty*4+2][kk], a3 = As[ty*4+3][kk];
            float4 b4 = *reinterpret_cast<const float4*>(&Bs[kk][tx*4]);
            acc[0][0] += a0*b4.x; acc[0][1] += a0*b4.y; acc[0][2] += a0*b4.z; acc[0][3] += a0*b4.w;
            acc[1][0] += a1*b4.x; acc[1][1] += a1*b4.y; acc[1][2] += a1*b4.z; acc[1][3] += a1*b4.w;
            acc[2][0] += a2*b4.x; acc[2][1] += a2*b4.y; acc[2][2] += a2*b4.z; acc[2][3] += a2*b4.w;
            acc[3][0] += a3*b4.x; acc[3][1] += a3*b4.y; acc[3][2] += a3*b4.z; acc[3][3] += a3*b4.w;
        }
        __syncthreads();
    }
    #pragma unroll
    for (int i = 0; i < 4; i++) {
        float4 v = make_float4(acc[i][0], acc[i][1], acc[i][2], acc[i][3]);
        *reinterpret_cast<float4*>(&C[(size_t)(bm + ty*4 + i) * N + bn + tx*4]) = v;
    }
}

// ---------------- RoPE + transpose ----------------
// one block per (b,t); 384 threads. q pre-scaled by 1/sqrt(DH).
__global__ void rope_kernel(const float* __restrict__ qf, const float* __restrict__ kf,
                            const float* __restrict__ vf,
                            float* __restrict__ qr, float* __restrict__ kout,
                            float* __restrict__ vout) {
    int bt = blockIdx.x;
    int b = bt >> 11, t = bt & (T_ - 1);
    int tid = threadIdx.x;
    {   // q: 12 heads x 32 pairs = 384 threads
        int h = tid >> 5, m = tid & 31;
        float inv = powf(10000.0f, -(float)m / 32.0f);
        float ang = (float)t * inv;
        float s, c; sincosf(ang, &s, &c);
        float x0 = qf[(size_t)bt * DM + h * DH + m];
        float x1 = qf[(size_t)bt * DM + h * DH + m + 32];
        size_t base = ((size_t)(b * NH + h) * T_ + t) * DH;
        qr[base + m]      = (x0 * c - x1 * s) * 0.125f;
        qr[base + m + 32] = (x1 * c + x0 * s) * 0.125f;
    }
    if (tid < NKV * 32) {   // k rope
        int h = tid >> 5, m = tid & 31;
        float inv = powf(10000.0f, -(float)m / 32.0f);
        float ang = (float)t * inv;
        float s, c; sincosf(ang, &s, &c);
        float x0 = kf[(size_t)bt * (NKV*DH) + h * DH + m];
        float x1 = kf[(size_t)bt * (NKV*DH) + h * DH + m + 32];
        size_t base = ((size_t)(b * NKV + h) * T_ + t) * DH;
        kout[base + m]      = x0 * c - x1 * s;
        kout[base + m + 32] = x1 * c + x0 * s;
    }
    if (tid < NKV * DH) {   // v transpose copy
        int h = tid >> 6, d = tid & 63;
        size_t base = ((size_t)(b * NKV + h) * T_ + t) * DH;
        vout[base + d] = vf[(size_t)bt * (NKV*DH) + tid];
    }
}

// ---------------- windowed flash attention ----------------
// block = (b, h, 8-query tile); 8 warps, warp w owns query qbase+w.
// 32-key chunks staged in smem; online softmax; GQA: q head h -> kv head h/3.
__global__ void attn_kernel(const float* __restrict__ qr, const float* __restrict__ kc,
                            const float* __restrict__ vc, float* __restrict__ ao) {
    int blk = blockIdx.x;
    int qt = blk & 255;               // T/8 = 256 tiles
    int h  = (blk >> 8) % NH;
    int b  = blk / (256 * NH);
    int kvh = h / (NH / NKV);
    int qbase = qt * 8;
    int tid = threadIdx.x, w = tid >> 5, lane = tid & 31;
    int i = qbase + w;

    __shared__ float Ksm[32][65];
    __shared__ float Vsm[32][65];
    __shared__ float qsm[8][64];

    const float* qrow = qr + ((size_t)(b * NH + h) * T_ + i) * DH;
    qsm[w][lane]      = qrow[lane];
    qsm[w][lane + 32] = qrow[lane + 32];
    __syncwarp();

    const float* Kb = kc + (size_t)(b * NKV + kvh) * T_ * DH;
    const float* Vb = vc + (size_t)(b * NKV + kvh) * T_ * DH;

    float m = -1e30f, l = 0.f, acc0 = 0.f, acc1 = 0.f;

    int wlo = qbase - WIN + 1; if (wlo < GLB) wlo = GLB;
    wlo &= ~31;                        // stays >= 64
    int wend = qbase + 8;

    for (int phase = 0; phase < 2; phase++) {
        int c0s = phase ? wlo : 0;
        int c0e = phase ? wend : GLB;
        for (int c0 = c0s; c0 < c0e; c0 += 32) {
            __syncthreads();
            #pragma unroll
            for (int r = 0; r < 8; r++) {           // stage 32 keys + values
                int e = tid + r * 256;
                int j = e >> 6, d = e & 63;
                Ksm[j][d] = Kb[(size_t)(c0 + j) * DH + d];
                Vsm[j][d] = Vb[(size_t)(c0 + j) * DH + d];
            }
            __syncthreads();

            int kj = c0 + lane;
            bool allowed = (kj <= i) && (phase == 0 || kj > i - WIN);
            float s = 0.f;
            #pragma unroll
            for (int d = 0; d < 64; d++) s += qsm[w][d] * Ksm[lane][d];
            float sm_ = allowed ? s : -1e30f;

            float cm = sm_;
            #pragma unroll
            for (int o = 16; o > 0; o >>= 1) cm = fmaxf(cm, __shfl_xor_sync(0xffffffffu, cm, o));
            float mn = fmaxf(m, cm);
            float p = allowed ? __expf(sm_ - mn) : 0.f;
            float cs = p;
            #pragma unroll
            for (int o = 16; o > 0; o >>= 1) cs += __shfl_xor_sync(0xffffffffu, cs, o);
            float scale = __expf(m - mn);
            l = l * scale + cs;
            acc0 *= scale; acc1 *= scale;
            m = mn;
            #pragma unroll
            for (int j = 0; j < 32; j++) {
                float pj = __shfl_sync(0xffffffffu, p, j);
                acc0 += pj * Vsm[j][lane];
                acc1 += pj * Vsm[j][lane + 32];
            }
        }
    }
    float invl = 1.0f / l;
    size_t o = ((size_t)b * T_ + i) * DM + h * DH + lane;
    ao[o]      = acc0 * invl;
    ao[o + 32] = acc1 * invl;
}

extern "C" void kernel_launch(void* const* d_in, const int* in_sizes, int n_in,
                              void* d_out, int out_size) {
    const float* x  = (const float*)d_in[0];
    const float* wq = (const float*)d_in[1];
    const float* wk = (const float*)d_in[2];
    const float* wv = (const float*)d_in[3];
    const float* wo = (const float*)d_in[4];
    float* out = (float*)d_out;

    float *qf, *kf, *vf, *qr, *ao, *kr, *vr;
    cudaGetSymbolAddress((void**)&qf, g_qf);
    cudaGetSymbolAddress((void**)&kf, g_kf);
    cudaGetSymbolAddress((void**)&vf, g_vf);
    cudaGetSymbolAddress((void**)&qr, g_qr);
    cudaGetSymbolAddress((void**)&ao, g_ao);
    cudaGetSymbolAddress((void**)&kr, g_kr);
    cudaGetSymbolAddress((void**)&vr, g_vr);

    const int out_elems = B_ * T_ * DM;            // 3145728
    const int kv_elems  = B_ * NKV * T_ * DH;      // 1048576
    float* kout = kr; float* vout = vr;
    if (out_size >= out_elems + 2 * kv_elems) {    // tuple-flattened output
        kout = out + out_elems;
        vout = out + out_elems + kv_elems;
    }

    gemm_kernel<<<dim3(DM/64,       MROWS/64), 256>>>(x, wq, qf, MROWS, DM,     DM);
    gemm_kernel<<<dim3((NKV*DH)/64, MROWS/64), 256>>>(x, wk, kf, MROWS, NKV*DH, DM);
    gemm_kernel<<<dim3((NKV*DH)/64, MROWS/64), 256>>>(x, wv, vf, MROWS, NKV*DH, DM);
    rope_kernel<<<MROWS, 384>>>(qf, kf, vf, qr, kout, vout);
    attn_kernel<<<B_ * NH * (T_/8), 256>>>(qr, kout, vout, ao);
    gemm_kernel<<<dim3(DM/64, MROWS/64), 256>>>(ao, wo, out, MROWS, DM, DM);
}

// round 5
// speedup vs baseline: 1.7813x; 1.7813x over previous
#include <cuda_runtime.h>
#include <cuda_bf16.h>
#include <stdint.h>
#include <cstdint>
#include <math.h>

#define B_ 2
#define T_ 2048
#define DM 768
#define NH 12
#define NKV 4
#define DH 64
#define WIN 512
#define GLB 64
#define MROWS (B_*T_)          // 4096
#define K3 (3*DM)              // 2304 stacked-K for bf16x3 trick

// ---------------- scratch ----------------
__device__ __nv_bfloat16 g_ax[(size_t)MROWS*K3];       // split activations [4096][2304]
__device__ __nv_bfloat16 g_wt1[(size_t)1280*K3];       // split+transposed [wq|wk|wv] : [1280][2304]
__device__ __nv_bfloat16 g_wt2[(size_t)DM*K3];         // split+transposed wo : [768][2304]
__device__ float g_qkv[(size_t)MROWS*1280];            // fused qkv proj out [4096][1280]
__device__ float g_qr[(size_t)B_*NH*T_*DH];            // roped q [B,H,T,D]
__device__ float g_ao[(size_t)MROWS*DM];               // attention out [B*T, H*D]
__device__ float g_kr[(size_t)B_*NKV*T_*DH];           // fallback k out
__device__ float g_vr[(size_t)B_*NKV*T_*DH];           // fallback v out

// ---------------- helpers ----------------
__device__ __forceinline__ void cp16(void* smem, const void* gmem) {
    uint32_t s = (uint32_t)__cvta_generic_to_shared(smem);
    asm volatile("cp.async.cg.shared.global [%0], [%1], 16;\n" :: "r"(s), "l"(gmem));
}
__device__ __forceinline__ void cp_commit() { asm volatile("cp.async.commit_group;\n"); }

// ---------------- split kernels (bf16 hi/lo, stacked-K layout) ----------------
// A' row r: cols [0,768)=hi(x), [768,1536)=lo(x), [1536,2304)=hi(x)
__global__ void split_act_kernel(const float* __restrict__ src, __nv_bfloat16* __restrict__ dst) {
    int idx = blockIdx.x * blockDim.x + threadIdx.x;       // over 4096*768
    if (idx >= MROWS * DM) return;
    int r = idx / DM, c = idx % DM;
    float x = src[idx];
    __nv_bfloat16 hi = __float2bfloat16(x);
    __nv_bfloat16 lo = __float2bfloat16(x - __bfloat162float(hi));
    size_t base = (size_t)r * K3;
    dst[base + c] = hi;
    dst[base + c + DM] = lo;
    dst[base + c + 2*DM] = hi;
}

// B't row n: cols [0,768)=hi(W[k][n]), [768,1536)=hi, [1536,2304)=lo
__global__ void split_wqkv_kernel(const float* __restrict__ wq, const float* __restrict__ wk,
                                  const float* __restrict__ wv, __nv_bfloat16* __restrict__ dst) {
    int idx = blockIdx.x * blockDim.x + threadIdx.x;       // over 1280*768
    if (idx >= 1280 * DM) return;
    int n = idx / DM, k = idx % DM;
    float x;
    if (n < 768)       x = wq[(size_t)k * 768 + n];
    else if (n < 1024) x = wk[(size_t)k * 256 + (n - 768)];
    else               x = wv[(size_t)k * 256 + (n - 1024)];
    __nv_bfloat16 hi = __float2bfloat16(x);
    __nv_bfloat16 lo = __float2bfloat16(x - __bfloat162float(hi));
    size_t base = (size_t)n * K3;
    dst[base + k] = hi;
    dst[base + k + DM] = hi;
    dst[base + k + 2*DM] = lo;
}

__global__ void split_wo_kernel(const float* __restrict__ wo, __nv_bfloat16* __restrict__ dst) {
    int idx = blockIdx.x * blockDim.x + threadIdx.x;       // over 768*768
    if (idx >= DM * DM) return;
    int n = idx / DM, k = idx % DM;
    float x = wo[(size_t)k * DM + n];
    __nv_bfloat16 hi = __float2bfloat16(x);
    __nv_bfloat16 lo = __float2bfloat16(x - __bfloat162float(hi));
    size_t base = (size_t)n * K3;
    dst[base + k] = hi;
    dst[base + k + DM] = hi;
    dst[base + k + 2*DM] = lo;
}

// ---------------- bf16 tensor-core GEMM ----------------
// C[M,N] = A'[M,K3] (row-major) @ B't[N,K3]^T, all bf16 in, f32 out.
// Block tile 128x128, 8 warps (warp tile 64x32), K-step 32, cp.async double buffer.
#define BM 128
#define BN 128
#define BK 32
#define SAP 40    // padded smem stride in halves (conflict-free for ldmatrix: 5r mod 8 is a perm)

__global__ void __launch_bounds__(256, 2)
gemm_bf16_kernel(const __nv_bfloat16* __restrict__ A, const __nv_bfloat16* __restrict__ Bt,
                 float* __restrict__ C, int N, int K) {
    __shared__ __align__(16) __nv_bfloat16 As[2][BM * SAP];
    __shared__ __align__(16) __nv_bfloat16 Bs[2][BN * SAP];

    int tid = threadIdx.x;
    int warp = tid >> 5, lane = tid & 31;
    int wm = warp & 1;            // 2 warps along M (64 rows each)
    int wn = warp >> 1;           // 4 warps along N (32 cols each)
    int bm = blockIdx.y * BM, bn = blockIdx.x * BN;

    int g = lane >> 2;            // group 0..7
    int t2 = (lane & 3) * 2;      // pair col 0,2,4,6

    float acc[4][4][4];
    #pragma unroll
    for (int i = 0; i < 4; i++)
        #pragma unroll
        for (int j = 0; j < 4; j++)
            #pragma unroll
            for (int r = 0; r < 4; r++) acc[i][j][r] = 0.f;

    const int KT = K / BK;        // 72

    // prefetch stage 0
    {
        #pragma unroll
        for (int i = 0; i < 2; i++) {
            int chunk = tid + i * 256;                   // 512 chunks of 16B for A
            int row = chunk >> 2, c4 = chunk & 3;
            cp16(&As[0][row * SAP + c4 * 8], A + (size_t)(bm + row) * K + c4 * 8);
        }
        #pragma unroll
        for (int i = 0; i < 2; i++) {
            int chunk = tid + i * 256;
            int row = chunk >> 2, c4 = chunk & 3;
            cp16(&Bs[0][row * SAP + c4 * 8], Bt + (size_t)(bn + row) * K + c4 * 8);
        }
        cp_commit();
    }

    for (int kt = 0; kt < KT; kt++) {
        int s = kt & 1;
        if (kt + 1 < KT) {
            int koff = (kt + 1) * BK;
            #pragma unroll
            for (int i = 0; i < 2; i++) {
                int chunk = tid + i * 256;
                int row = chunk >> 2, c4 = chunk & 3;
                cp16(&As[s ^ 1][row * SAP + c4 * 8], A + (size_t)(bm + row) * K + koff + c4 * 8);
            }
            #pragma unroll
            for (int i = 0; i < 2; i++) {
                int chunk = tid + i * 256;
                int row = chunk >> 2, c4 = chunk & 3;
                cp16(&Bs[s ^ 1][row * SAP + c4 * 8], Bt + (size_t)(bn + row) * K + koff + c4 * 8);
            }
            cp_commit();
            asm volatile("cp.async.wait_group 1;\n");
        } else {
            asm volatile("cp.async.wait_group 0;\n");
        }
        __syncthreads();

        #pragma unroll
        for (int ks = 0; ks < BK; ks += 16) {
            uint32_t a[4][4], b[4][2];
            // A fragments: 4 m-frags of 16 rows
            #pragma unroll
            for (int mf = 0; mf < 4; mf++) {
                int tile = lane >> 3, rr = lane & 7;
                int mrow = wm * 64 + mf * 16 + (tile & 1) * 8 + rr;
                int kcol = ks + (tile >> 1) * 8;
                uint32_t addr = (uint32_t)__cvta_generic_to_shared(&As[s][mrow * SAP + kcol]);
                asm volatile("ldmatrix.sync.aligned.m8n8.x4.shared.b16 {%0,%1,%2,%3}, [%4];"
                             : "=r"(a[mf][0]), "=r"(a[mf][1]), "=r"(a[mf][2]), "=r"(a[mf][3])
                             : "r"(addr));
            }
            // B fragments: 4 n-frags of 8 cols
            #pragma unroll
            for (int nf = 0; nf < 4; nf++) {
                int tile = (lane >> 3) & 1, rr = lane & 7;
                int nrow = wn * 32 + nf * 8 + rr;
                int kcol = ks + tile * 8;
                uint32_t addr = (uint32_t)__cvta_generic_to_shared(&Bs[s][nrow * SAP + kcol]);
                asm volatile("ldmatrix.sync.aligned.m8n8.x2.shared.b16 {%0,%1}, [%2];"
                             : "=r"(b[nf][0]), "=r"(b[nf][1]) : "r"(addr));
            }
            #pragma unroll
            for (int mf = 0; mf < 4; mf++)
                #pragma unroll
                for (int nf = 0; nf < 4; nf++) {
                    asm volatile(
                        "mma.sync.aligned.m16n8k16.row.col.f32.bf16.bf16.f32 "
                        "{%0,%1,%2,%3}, {%4,%5,%6,%7}, {%8,%9}, {%0,%1,%2,%3};"
                        : "+f"(acc[mf][nf][0]), "+f"(acc[mf][nf][1]),
                          "+f"(acc[mf][nf][2]), "+f"(acc[mf][nf][3])
                        : "r"(a[mf][0]), "r"(a[mf][1]), "r"(a[mf][2]), "r"(a[mf][3]),
                          "r"(b[nf][0]), "r"(b[nf][1]));
                }
        }
        __syncthreads();
    }

    // epilogue
    #pragma unroll
    for (int mf = 0; mf < 4; mf++) {
        int r0 = bm + wm * 64 + mf * 16 + g;
        #pragma unroll
        for (int nf = 0; nf < 4; nf++) {
            int c0 = bn + wn * 32 + nf * 8 + t2;
            *reinterpret_cast<float2*>(&C[(size_t)r0 * N + c0]) =
                make_float2(acc[mf][nf][0], acc[mf][nf][1]);
            *reinterpret_cast<float2*>(&C[(size_t)(r0 + 8) * N + c0]) =
                make_float2(acc[mf][nf][2], acc[mf][nf][3]);
        }
    }
}

// ---------------- RoPE + transpose (reads fused qkv [4096][1280]) ----------------
__global__ void rope_kernel(const float* __restrict__ qkv,
                            float* __restrict__ qr, float* __restrict__ kout,
                            float* __restrict__ vout) {
    int bt = blockIdx.x;
    int b = bt >> 11, t = bt & (T_ - 1);
    int tid = threadIdx.x;
    const float* row = qkv + (size_t)bt * 1280;
    {   // q: 12 heads x 32 pairs = 384 threads
        int h = tid >> 5, m = tid & 31;
        float inv = powf(10000.0f, -(float)m / 32.0f);
        float ang = (float)t * inv;
        float s, c; sincosf(ang, &s, &c);
        float x0 = row[h * DH + m];
        float x1 = row[h * DH + m + 32];
        size_t base = ((size_t)(b * NH + h) * T_ + t) * DH;
        qr[base + m]      = (x0 * c - x1 * s) * 0.125f;
        qr[base + m + 32] = (x1 * c + x0 * s) * 0.125f;
    }
    if (tid < NKV * 32) {   // k rope
        int h = tid >> 5, m = tid & 31;
        float inv = powf(10000.0f, -(float)m / 32.0f);
        float ang = (float)t * inv;
        float s, c; sincosf(ang, &s, &c);
        float x0 = row[768 + h * DH + m];
        float x1 = row[768 + h * DH + m + 32];
        size_t base = ((size_t)(b * NKV + h) * T_ + t) * DH;
        kout[base + m]      = x0 * c - x1 * s;
        kout[base + m + 32] = x1 * c + x0 * s;
    }
    if (tid < NKV * DH) {   // v transpose copy
        int h = tid >> 6, d = tid & 63;
        size_t base = ((size_t)(b * NKV + h) * T_ + t) * DH;
        vout[base + d] = row[1024 + tid];
    }
}

// ---------------- windowed flash attention, GQA-shared K/V ----------------
// block = (b, kvh, 8-query tile); warp w owns query qbase+w for ALL 3 q-heads of kvh.
__global__ void attn_kernel(const float* __restrict__ qr, const float* __restrict__ kc,
                            const float* __restrict__ vc, float* __restrict__ ao) {
    int blk = blockIdx.x;
    int qt  = blk & 255;                  // T/8 tiles
    int kvh = (blk >> 8) & 3;
    int b   = blk >> 10;
    int qbase = qt * 8;
    int tid = threadIdx.x, w = tid >> 5, lane = tid & 31;
    int i = qbase + w;

    __shared__ float Ksm[32][65];
    __shared__ float Vsm[32][65];
    __shared__ float qsm[8][3][64];

    #pragma unroll
    for (int hh = 0; hh < 3; hh++) {
        int h = kvh * 3 + hh;
        const float* qrow = qr + ((size_t)(b * NH + h) * T_ + i) * DH;
        qsm[w][hh][lane]      = qrow[lane];
        qsm[w][hh][lane + 32] = qrow[lane + 32];
    }
    __syncwarp();

    const float* Kb = kc + (size_t)(b * NKV + kvh) * T_ * DH;
    const float* Vb = vc + (size_t)(b * NKV + kvh) * T_ * DH;

    float m[3]  = {-1e30f, -1e30f, -1e30f};
    float l[3]  = {0.f, 0.f, 0.f};
    float a0[3] = {0.f, 0.f, 0.f};
    float a1[3] = {0.f, 0.f, 0.f};

    int wlo = qbase - WIN + 1; if (wlo < GLB) wlo = GLB;
    wlo &= ~31;
    int wend = qbase + 8;

    for (int phase = 0; phase < 2; phase++) {
        int c0s = phase ? wlo : 0;
        int c0e = phase ? wend : GLB;
        for (int c0 = c0s; c0 < c0e; c0 += 32) {
            __syncthreads();
            #pragma unroll
            for (int r = 0; r < 8; r++) {           // stage 32 keys + values
                int e = tid + r * 256;
                int j = e >> 6, d = e & 63;
                Ksm[j][d] = Kb[(size_t)(c0 + j) * DH + d];
                Vsm[j][d] = Vb[(size_t)(c0 + j) * DH + d];
            }
            __syncthreads();

            int kj = c0 + lane;
            bool allowed = (kj <= i) && (phase == 0 || kj > i - WIN);

            float s0 = 0.f, s1 = 0.f, s2 = 0.f;
            #pragma unroll
            for (int d = 0; d < 64; d++) {
                float kv = Ksm[lane][d];
                s0 += qsm[w][0][d] * kv;
                s1 += qsm[w][1][d] * kv;
                s2 += qsm[w][2][d] * kv;
            }
            float sv[3] = {s0, s1, s2};
            float p[3];
            #pragma unroll
            for (int hh = 0; hh < 3; hh++) {
                float sm_ = allowed ? sv[hh] : -1e30f;
                float cm = sm_;
                #pragma unroll
                for (int o = 16; o > 0; o >>= 1) cm = fmaxf(cm, __shfl_xor_sync(0xffffffffu, cm, o));
                float mn = fmaxf(m[hh], cm);
                float pp = allowed ? __expf(sm_ - mn) : 0.f;
                float cs = pp;
                #pragma unroll
                for (int o = 16; o > 0; o >>= 1) cs += __shfl_xor_sync(0xffffffffu, cs, o);
                float scale = __expf(m[hh] - mn);
                l[hh] = l[hh] * scale + cs;
                a0[hh] *= scale; a1[hh] *= scale;
                m[hh] = mn;
                p[hh] = pp;
            }
            #pragma unroll
            for (int j = 0; j < 32; j++) {
                float v0 = Vsm[j][lane];
                float v1 = Vsm[j][lane + 32];
                #pragma unroll
                for (int hh = 0; hh < 3; hh++) {
                    float pj = __shfl_sync(0xffffffffu, p[hh], j);
                    a0[hh] += pj * v0;
                    a1[hh] += pj * v1;
                }
            }
        }
    }
    #pragma unroll
    for (int hh = 0; hh < 3; hh++) {
        int h = kvh * 3 + hh;
        float invl = 1.0f / l[hh];
        size_t o = ((size_t)b * T_ + i) * DM + h * DH + lane;
        ao[o]      = a0[hh] * invl;
        ao[o + 32] = a1[hh] * invl;
    }
}

extern "C" void kernel_launch(void* const* d_in, const int* in_sizes, int n_in,
                              void* d_out, int out_size) {
    const float* x  = (const float*)d_in[0];
    const float* wq = (const float*)d_in[1];
    const float* wk = (const float*)d_in[2];
    const float* wv = (const float*)d_in[3];
    const float* wo = (const float*)d_in[4];
    float* out = (float*)d_out;

    __nv_bfloat16 *ax, *wt1, *wt2;
    float *qkv, *qr, *ao, *kr, *vr;
    cudaGetSymbolAddress((void**)&ax,  g_ax);
    cudaGetSymbolAddress((void**)&wt1, g_wt1);
    cudaGetSymbolAddress((void**)&wt2, g_wt2);
    cudaGetSymbolAddress((void**)&qkv, g_qkv);
    cudaGetSymbolAddress((void**)&qr,  g_qr);
    cudaGetSymbolAddress((void**)&ao,  g_ao);
    cudaGetSymbolAddress((void**)&kr,  g_kr);
    cudaGetSymbolAddress((void**)&vr,  g_vr);

    const int out_elems = B_ * T_ * DM;            // 3145728
    const int kv_elems  = B_ * NKV * T_ * DH;      // 1048576
    float* kout = kr; float* vout = vr;
    if (out_size >= out_elems + 2 * kv_elems) {    // tuple-flattened output
        kout = out + out_elems;
        vout = out + out_elems + kv_elems;
    }

    split_act_kernel <<<(MROWS*DM + 255)/256, 256>>>(x, ax);
    split_wqkv_kernel<<<(1280*DM  + 255)/256, 256>>>(wq, wk, wv, wt1);
    split_wo_kernel  <<<(DM*DM    + 255)/256, 256>>>(wo, wt2);

    gemm_bf16_kernel<<<dim3(1280/BN, MROWS/BM), 256>>>(ax, wt1, qkv, 1280, K3);
    rope_kernel<<<MROWS, 384>>>(qkv, qr, kout, vout);
    attn_kernel<<<B_ * NKV * (T_/8), 256>>>(qr, kout, vout, ao);
    split_act_kernel<<<(MROWS*DM + 255)/256, 256>>>(ao, ax);
    gemm_bf16_kernel<<<dim3(DM/BN, MROWS/BM), 256>>>(ax, wt2, out, DM, K3);
}

// round 6
// speedup vs baseline: 3.0979x; 1.7391x over previous
#include <cuda_runtime.h>
#include <cuda_bf16.h>
#include <stdint.h>
#include <cstdint>
#include <math.h>

#define B_ 2
#define T_ 2048
#define DM 768
#define NH 12
#define NKV 4
#define DH 64
#define WIN 512
#define GLB 64
#define MROWS (B_*T_)          // 4096
#define K3 (3*DM)              // 2304 stacked-K for bf16x3 trick

// ---------------- scratch ----------------
__device__ __nv_bfloat16 g_ax[(size_t)MROWS*K3];       // split activations [4096][2304]
__device__ __nv_bfloat16 g_wt1[(size_t)1280*K3];       // split+transposed [wq|wk|wv]
__device__ __nv_bfloat16 g_wt2[(size_t)DM*K3];         // split+transposed wo
__device__ float g_qkv[(size_t)MROWS*1280];            // fused qkv proj out
__device__ float g_ao[(size_t)MROWS*DM];               // attention out [B*T, H*D]
__device__ float g_kr[(size_t)B_*NKV*T_*DH];           // fallback k out
__device__ float g_vr[(size_t)B_*NKV*T_*DH];           // fallback v out
// attention operands (split precision)
__device__ __nv_bfloat16 g_qsp[(size_t)B_*NH*T_*192];  // Q' [b,h,t][hi64|lo64|hi64]
__device__ __nv_bfloat16 g_ksp[(size_t)B_*NKV*T_*192]; // K' [b,kvh,t][hi64|hi64|lo64]
__device__ __nv_bfloat16 g_vthi[(size_t)B_*NKV*DH*T_]; // V^T hi [b,kvh,d][t]
__device__ __nv_bfloat16 g_vtlo[(size_t)B_*NKV*DH*T_]; // V^T lo [b,kvh,d][t]

// ---------------- helpers ----------------
__device__ __forceinline__ void cp16(void* smem, const void* gmem) {
    uint32_t s = (uint32_t)__cvta_generic_to_shared(smem);
    asm volatile("cp.async.cg.shared.global [%0], [%1], 16;\n" :: "r"(s), "l"(gmem));
}
__device__ __forceinline__ void cp_commit() { asm volatile("cp.async.commit_group;\n"); }

__device__ __forceinline__ void ldmx4(uint32_t* r, const void* p) {
    uint32_t a = (uint32_t)__cvta_generic_to_shared(p);
    asm volatile("ldmatrix.sync.aligned.m8n8.x4.shared.b16 {%0,%1,%2,%3}, [%4];"
                 : "=r"(r[0]), "=r"(r[1]), "=r"(r[2]), "=r"(r[3]) : "r"(a));
}
__device__ __forceinline__ void mma16816(float* d, const uint32_t* a, uint32_t b0, uint32_t b1) {
    asm volatile("mma.sync.aligned.m16n8k16.row.col.f32.bf16.bf16.f32 "
                 "{%0,%1,%2,%3}, {%4,%5,%6,%7}, {%8,%9}, {%0,%1,%2,%3};"
                 : "+f"(d[0]), "+f"(d[1]), "+f"(d[2]), "+f"(d[3])
                 : "r"(a[0]), "r"(a[1]), "r"(a[2]), "r"(a[3]), "r"(b0), "r"(b1));
}
__device__ __forceinline__ uint32_t packbf2(float lo, float hi) {
    __nv_bfloat162 h = __floats2bfloat162_rn(lo, hi);
    return *reinterpret_cast<uint32_t*>(&h);
}

// ---------------- split kernels (bf16 hi/lo, stacked-K layout) ----------------
__global__ void split_act_kernel(const float* __restrict__ src, __nv_bfloat16* __restrict__ dst) {
    int idx = blockIdx.x * blockDim.x + threadIdx.x;
    if (idx >= MROWS * DM) return;
    int r = idx / DM, c = idx % DM;
    float x = src[idx];
    __nv_bfloat16 hi = __float2bfloat16(x);
    __nv_bfloat16 lo = __float2bfloat16(x - __bfloat162float(hi));
    size_t base = (size_t)r * K3;
    dst[base + c] = hi;
    dst[base + c + DM] = lo;
    dst[base + c + 2*DM] = hi;
}

__global__ void split_wqkv_kernel(const float* __restrict__ wq, const float* __restrict__ wk,
                                  const float* __restrict__ wv, __nv_bfloat16* __restrict__ dst) {
    int idx = blockIdx.x * blockDim.x + threadIdx.x;
    if (idx >= 1280 * DM) return;
    int n = idx / DM, k = idx % DM;
    float x;
    if (n < 768)       x = wq[(size_t)k * 768 + n];
    else if (n < 1024) x = wk[(size_t)k * 256 + (n - 768)];
    else               x = wv[(size_t)k * 256 + (n - 1024)];
    __nv_bfloat16 hi = __float2bfloat16(x);
    __nv_bfloat16 lo = __float2bfloat16(x - __bfloat162float(hi));
    size_t base = (size_t)n * K3;
    dst[base + k] = hi;
    dst[base + k + DM] = hi;
    dst[base + k + 2*DM] = lo;
}

__global__ void split_wo_kernel(const float* __restrict__ wo, __nv_bfloat16* __restrict__ dst) {
    int idx = blockIdx.x * blockDim.x + threadIdx.x;
    if (idx >= DM * DM) return;
    int n = idx / DM, k = idx % DM;
    float x = wo[(size_t)k * DM + n];
    __nv_bfloat16 hi = __float2bfloat16(x);
    __nv_bfloat16 lo = __float2bfloat16(x - __bfloat162float(hi));
    size_t base = (size_t)n * K3;
    dst[base + k] = hi;
    dst[base + k + DM] = hi;
    dst[base + k + 2*DM] = lo;
}

// ---------------- bf16 tensor-core GEMM (unchanged from R5-pass) ----------------
#define BM 128
#define BN 128
#define BK 32
#define SAP 40

__global__ void __launch_bounds__(256, 2)
gemm_bf16_kernel(const __nv_bfloat16* __restrict__ A, const __nv_bfloat16* __restrict__ Bt,
                 float* __restrict__ C, int N, int K) {
    __shared__ __align__(16) __nv_bfloat16 As[2][BM * SAP];
    __shared__ __align__(16) __nv_bfloat16 Bs[2][BN * SAP];

    int tid = threadIdx.x;
    int warp = tid >> 5, lane = tid & 31;
    int wm = warp & 1;
    int wn = warp >> 1;
    int bm = blockIdx.y * BM, bn = blockIdx.x * BN;
    int g = lane >> 2;
    int t2 = (lane & 3) * 2;

    float acc[4][4][4];
    #pragma unroll
    for (int i = 0; i < 4; i++)
        #pragma unroll
        for (int j = 0; j < 4; j++)
            #pragma unroll
            for (int r = 0; r < 4; r++) acc[i][j][r] = 0.f;

    const int KT = K / BK;

    {
        #pragma unroll
        for (int i = 0; i < 2; i++) {
            int chunk = tid + i * 256;
            int row = chunk >> 2, c4 = chunk & 3;
            cp16(&As[0][row * SAP + c4 * 8], A + (size_t)(bm + row) * K + c4 * 8);
        }
        #pragma unroll
        for (int i = 0; i < 2; i++) {
            int chunk = tid + i * 256;
            int row = chunk >> 2, c4 = chunk & 3;
            cp16(&Bs[0][row * SAP + c4 * 8], Bt + (size_t)(bn + row) * K + c4 * 8);
        }
        cp_commit();
    }

    for (int kt = 0; kt < KT; kt++) {
        int s = kt & 1;
        if (kt + 1 < KT) {
            int koff = (kt + 1) * BK;
            #pragma unroll
            for (int i = 0; i < 2; i++) {
                int chunk = tid + i * 256;
                int row = chunk >> 2, c4 = chunk & 3;
                cp16(&As[s ^ 1][row * SAP + c4 * 8], A + (size_t)(bm + row) * K + koff + c4 * 8);
            }
            #pragma unroll
            for (int i = 0; i < 2; i++) {
                int chunk = tid + i * 256;
                int row = chunk >> 2, c4 = chunk & 3;
                cp16(&Bs[s ^ 1][row * SAP + c4 * 8], Bt + (size_t)(bn + row) * K + koff + c4 * 8);
            }
            cp_commit();
            asm volatile("cp.async.wait_group 1;\n");
        } else {
            asm volatile("cp.async.wait_group 0;\n");
        }
        __syncthreads();

        #pragma unroll
        for (int ks = 0; ks < BK; ks += 16) {
            uint32_t a[4][4], b[4][2];
            #pragma unroll
            for (int mf = 0; mf < 4; mf++) {
                int tile = lane >> 3, rr = lane & 7;
                int mrow = wm * 64 + mf * 16 + (tile & 1) * 8 + rr;
                int kcol = ks + (tile >> 1) * 8;
                ldmx4(a[mf], &As[s][mrow * SAP + kcol]);
            }
            #pragma unroll
            for (int nf = 0; nf < 4; nf++) {
                int tile = (lane >> 3) & 1, rr = lane & 7;
                int nrow = wn * 32 + nf * 8 + rr;
                int kcol = ks + tile * 8;
                uint32_t addr = (uint32_t)__cvta_generic_to_shared(&Bs[s][nrow * SAP + kcol]);
                asm volatile("ldmatrix.sync.aligned.m8n8.x2.shared.b16 {%0,%1}, [%2];"
                             : "=r"(b[nf][0]), "=r"(b[nf][1]) : "r"(addr));
            }
            #pragma unroll
            for (int mf = 0; mf < 4; mf++)
                #pragma unroll
                for (int nf = 0; nf < 4; nf++)
                    mma16816(acc[mf][nf], a[mf], b[nf][0], b[nf][1]);
        }
        __syncthreads();
    }

    #pragma unroll
    for (int mf = 0; mf < 4; mf++) {
        int r0 = bm + wm * 64 + mf * 16 + g;
        #pragma unroll
        for (int nf = 0; nf < 4; nf++) {
            int c0 = bn + wn * 32 + nf * 8 + t2;
            *reinterpret_cast<float2*>(&C[(size_t)r0 * N + c0]) =
                make_float2(acc[mf][nf][0], acc[mf][nf][1]);
            *reinterpret_cast<float2*>(&C[(size_t)(r0 + 8) * N + c0]) =
                make_float2(acc[mf][nf][2], acc[mf][nf][3]);
        }
    }
}

// ---------------- RoPE + transpose + split for attention ----------------
__global__ void rope_kernel(const float* __restrict__ qkv,
                            float* __restrict__ kout, float* __restrict__ vout,
                            __nv_bfloat16* __restrict__ qsp, __nv_bfloat16* __restrict__ ksp,
                            __nv_bfloat16* __restrict__ vthi, __nv_bfloat16* __restrict__ vtlo) {
    int bt = blockIdx.x;
    int b = bt >> 11, t = bt & (T_ - 1);
    int tid = threadIdx.x;
    const float* row = qkv + (size_t)bt * 1280;
    {   // q: 12 heads x 32 pairs; pre-scale by 1/8, split hi/lo
        int h = tid >> 5, m = tid & 31;
        float inv = powf(10000.0f, -(float)m / 32.0f);
        float ang = (float)t * inv;
        float s, c; sincosf(ang, &s, &c);
        float x0 = row[h * DH + m];
        float x1 = row[h * DH + m + 32];
        float r0 = (x0 * c - x1 * s) * 0.125f;
        float r1 = (x1 * c + x0 * s) * 0.125f;
        size_t base = ((size_t)(b * NH + h) * T_ + t) * 192;
        __nv_bfloat16 h0 = __float2bfloat16(r0);
        __nv_bfloat16 h1 = __float2bfloat16(r1);
        __nv_bfloat16 l0 = __float2bfloat16(r0 - __bfloat162float(h0));
        __nv_bfloat16 l1 = __float2bfloat16(r1 - __bfloat162float(h1));
        qsp[base + m] = h0;        qsp[base + m + 32] = h1;       // hi
        qsp[base + 64 + m] = l0;   qsp[base + 96 + m] = l1;       // lo
        qsp[base + 128 + m] = h0;  qsp[base + 160 + m] = h1;      // hi
    }
    if (tid < NKV * 32) {   // k rope: fp32 out + split [hi|hi|lo]
        int h = tid >> 5, m = tid & 31;
        float inv = powf(10000.0f, -(float)m / 32.0f);
        float ang = (float)t * inv;
        float s, c; sincosf(ang, &s, &c);
        float x0 = row[768 + h * DH + m];
        float x1 = row[768 + h * DH + m + 32];
        float r0 = x0 * c - x1 * s;
        float r1 = x1 * c + x0 * s;
        size_t fbase = ((size_t)(b * NKV + h) * T_ + t) * DH;
        kout[fbase + m]      = r0;
        kout[fbase + m + 32] = r1;
        size_t base = ((size_t)(b * NKV + h) * T_ + t) * 192;
        __nv_bfloat16 h0 = __float2bfloat16(r0);
        __nv_bfloat16 h1 = __float2bfloat16(r1);
        __nv_bfloat16 l0 = __float2bfloat16(r0 - __bfloat162float(h0));
        __nv_bfloat16 l1 = __float2bfloat16(r1 - __bfloat162float(h1));
        ksp[base + m] = h0;        ksp[base + m + 32] = h1;
        ksp[base + 64 + m] = h0;   ksp[base + 96 + m] = h1;
        ksp[base + 128 + m] = l0;  ksp[base + 160 + m] = l1;
    }
    if (tid < NKV * DH) {   // v: fp32 transpose copy + bf16 hi/lo transposed [d][t]
        int h = tid >> 6, d = tid & 63;
        float v = row[1024 + tid];
        size_t fbase = ((size_t)(b * NKV + h) * T_ + t) * DH;
        vout[fbase + d] = v;
        __nv_bfloat16 hi = __float2bfloat16(v);
        __nv_bfloat16 lo = __float2bfloat16(v - __bfloat162float(hi));
        size_t tbase = ((size_t)(b * NKV + h) * DH + d) * T_ + t;
        vthi[tbase] = hi;
        vtlo[tbase] = lo;
    }
}

// ---------------- tensor-core windowed flash attention ----------------
// block = (b, h, 64-query tile); 4 warps, warp w owns q rows [w*16, w*16+16).
// S = Q'[64x192] @ K'chunk[32x192]^T (bf16x3), online softmax on frags,
// O += P'[64x96] @ V'chunk[96x64] (P hi/lo in-register, V hi/lo from smem).
#define QSTR 200   // Q/K smem row stride (bf16), 400B: 16B-aligned, conflict-free
#define VSTR 72    // V smem row stride (bf16), 144B

__global__ void attn_mma_kernel(const __nv_bfloat16* __restrict__ qsp,
                                const __nv_bfloat16* __restrict__ ksp,
                                const __nv_bfloat16* __restrict__ vthi,
                                const __nv_bfloat16* __restrict__ vtlo,
                                float* __restrict__ ao) {
    extern __shared__ __align__(16) __nv_bfloat16 sm[];
    __nv_bfloat16* Qs = sm;                       // [64][QSTR]
    __nv_bfloat16* Ks = Qs + 64 * QSTR;           // [2][32][QSTR]
    __nv_bfloat16* Vs = Ks + 2 * 32 * QSTR;       // [2][64][VSTR]  (cols: hi 0-31 | lo 32-63)

    int blk = blockIdx.x;
    int qt = 31 - blk / (B_ * NH);                // big tiles first
    int rest = blk % (B_ * NH);
    int h = rest % NH, b = rest / NH;
    int kvh = h / (NH / NKV);
    int qbase = qt * 64;

    int tid = threadIdx.x, w = tid >> 5, lane = tid & 31;
    int g = lane >> 2, t2 = (lane & 3) * 2;

    const __nv_bfloat16* Qg = qsp + ((size_t)(b * NH + h) * T_ + qbase) * 192;
    const __nv_bfloat16* Kg = ksp + (size_t)(b * NKV + kvh) * T_ * 192;
    const __nv_bfloat16* Vhg = vthi + (size_t)(b * NKV + kvh) * DH * T_;
    const __nv_bfloat16* Vlg = vtlo + (size_t)(b * NKV + kvh) * DH * T_;

    // chunk schedule: global chunks 0,1 then window chunks [cw0, cend)
    int cw0 = (qbase - (WIN - 1)) >> 5; if (cw0 < 2) cw0 = 2;
    int cend = (qbase + 64) >> 5;
    int nch = 2 + (cend > cw0 ? cend - cw0 : 0);

    // load Q tile (64 x 192): 1536 16B units, 12 per thread
    #pragma unroll
    for (int i = 0; i < 12; i++) {
        int u = tid + i * 128;
        int r = u / 24, c = u % 24;
        cp16(&Qs[r * QSTR + c * 8], Qg + (size_t)r * 192 + c * 8);
    }

    // chunk loader
    auto load_chunk = [&](int buf, int cid) {
        int c0 = cid * 32;
        __nv_bfloat16* Kb = Ks + buf * 32 * QSTR;
        __nv_bfloat16* Vb = Vs + buf * 64 * VSTR;
        #pragma unroll
        for (int i = 0; i < 6; i++) {            // K: 32 rows x 24 units
            int u = tid + i * 128;
            int r = u / 24, c = u % 24;
            cp16(&Kb[r * QSTR + c * 8], Kg + (size_t)(c0 + r) * 192 + c * 8);
        }
        #pragma unroll
        for (int i = 0; i < 4; i++) {            // V: 64 rows x (4 hi + 4 lo) units
            int u = tid + i * 128;
            int r = u >> 3, seg = u & 7;
            const __nv_bfloat16* src = (seg < 4) ? Vhg : Vlg;
            cp16(&Vb[r * VSTR + seg * 8], src + (size_t)r * T_ + c0 + (seg & 3) * 8);
        }
    };

    load_chunk(0, 0);
    cp_commit();

    float O[8][4];
    #pragma unroll
    for (int nf = 0; nf < 8; nf++)
        #pragma unroll
        for (int r = 0; r < 4; r++) O[nf][r] = 0.f;
    float mrow[2] = {-1e30f, -1e30f};
    float lrow[2] = {0.f, 0.f};
    int irow0 = qbase + w * 16 + g;

    for (int idx = 0; idx < nch; idx++) {
        int buf = idx & 1;
        int cid = (idx < 2) ? idx : cw0 + (idx - 2);
        int c0 = cid * 32;
        if (idx + 1 < nch) {
            int cid2 = (idx + 1 < 2) ? idx + 1 : cw0 + (idx - 1);
            load_chunk(buf ^ 1, cid2);
            cp_commit();
            asm volatile("cp.async.wait_group 1;\n");
        } else {
            asm volatile("cp.async.wait_group 0;\n");
        }
        __syncthreads();

        const __nv_bfloat16* Kb = Ks + buf * 32 * QSTR;
        const __nv_bfloat16* Vb = Vs + buf * 64 * VSTR;

        // ---- S = Q K^T : [16 x 32] per warp over k=192 ----
        float sc[4][4];
        #pragma unroll
        for (int nf = 0; nf < 4; nf++)
            #pragma unroll
            for (int r = 0; r < 4; r++) sc[nf][r] = 0.f;

        #pragma unroll
        for (int kb = 0; kb < 6; kb++) {
            uint32_t aA[4], aB[4];
            {
                int tile = lane >> 3, rr = lane & 7;
                int mrw = w * 16 + (tile & 1) * 8 + rr;
                ldmx4(aA, &Qs[mrw * QSTR + kb * 32 + (tile >> 1) * 8]);
                ldmx4(aB, &Qs[mrw * QSTR + kb * 32 + 16 + (tile >> 1) * 8]);
            }
            #pragma unroll
            for (int nf = 0; nf < 4; nf++) {
                uint32_t bb[4];
                ldmx4(bb, &Kb[(nf * 8 + (lane & 7)) * QSTR + kb * 32 + (lane >> 3) * 8]);
                mma16816(sc[nf], aA, bb[0], bb[1]);
                mma16816(sc[nf], aB, bb[2], bb[3]);
            }
        }

        // ---- mask + online softmax on fragments ----
        float cmax[2] = {-1e30f, -1e30f};
        #pragma unroll
        for (int nf = 0; nf < 4; nf++)
            #pragma unroll
            for (int r = 0; r < 4; r++) {
                int j = c0 + nf * 8 + t2 + (r & 1);
                int i = irow0 + (r >> 1) * 8;
                bool a = (j <= i) && ((j > i - WIN) || (j < GLB) || (i < GLB));
                float s = a ? sc[nf][r] : -1e30f;
                sc[nf][r] = s;
                cmax[r >> 1] = fmaxf(cmax[r >> 1], s);
            }
        #pragma unroll
        for (int r2 = 0; r2 < 2; r2++) {
            cmax[r2] = fmaxf(cmax[r2], __shfl_xor_sync(0xffffffffu, cmax[r2], 1));
            cmax[r2] = fmaxf(cmax[r2], __shfl_xor_sync(0xffffffffu, cmax[r2], 2));
        }
        float scl[2], rsum[2] = {0.f, 0.f};
        #pragma unroll
        for (int r2 = 0; r2 < 2; r2++) {
            float mn = fmaxf(mrow[r2], cmax[r2]);
            scl[r2] = __expf(mrow[r2] - mn);
            mrow[r2] = mn;
        }
        #pragma unroll
        for (int nf = 0; nf < 4; nf++)
            #pragma unroll
            for (int r = 0; r < 4; r++) {
                float s = sc[nf][r];
                float p = (s > -5e29f) ? __expf(s - mrow[r >> 1]) : 0.f;
                sc[nf][r] = p;
                rsum[r >> 1] += p;
            }
        #pragma unroll
        for (int r2 = 0; r2 < 2; r2++) {
            rsum[r2] += __shfl_xor_sync(0xffffffffu, rsum[r2], 1);
            rsum[r2] += __shfl_xor_sync(0xffffffffu, rsum[r2], 2);
            lrow[r2] = lrow[r2] * scl[r2] + rsum[r2];
        }
        #pragma unroll
        for (int nf = 0; nf < 8; nf++) {
            O[nf][0] *= scl[0]; O[nf][1] *= scl[0];
            O[nf][2] *= scl[1]; O[nf][3] *= scl[1];
        }

        // ---- P fragments (A-layout): Phi keys 0-15 / 16-31, Plo same ----
        uint32_t Phi0[4], Phi1[4], Plo0[4], Plo1[4];
        {
            float pl[4][4];
            #pragma unroll
            for (int nf = 0; nf < 4; nf++)
                #pragma unroll
                for (int r = 0; r < 4; r++) {
                    float p = sc[nf][r];
                    float ph = __bfloat162float(__float2bfloat16(p));
                    pl[nf][r] = p - ph;
                }
            Phi0[0] = packbf2(sc[0][0], sc[0][1]); Phi0[1] = packbf2(sc[0][2], sc[0][3]);
            Phi0[2] = packbf2(sc[1][0], sc[1][1]); Phi0[3] = packbf2(sc[1][2], sc[1][3]);
            Phi1[0] = packbf2(sc[2][0], sc[2][1]); Phi1[1] = packbf2(sc[2][2], sc[2][3]);
            Phi1[2] = packbf2(sc[3][0], sc[3][1]); Phi1[3] = packbf2(sc[3][2], sc[3][3]);
            Plo0[0] = packbf2(pl[0][0], pl[0][1]); Plo0[1] = packbf2(pl[0][2], pl[0][3]);
            Plo0[2] = packbf2(pl[1][0], pl[1][1]); Plo0[3] = packbf2(pl[1][2], pl[1][3]);
            Plo1[0] = packbf2(pl[2][0], pl[2][1]); Plo1[1] = packbf2(pl[2][2], pl[2][3]);
            Plo1[2] = packbf2(pl[3][0], pl[3][1]); Plo1[3] = packbf2(pl[3][2], pl[3][3]);
        }

        // ---- O += P V : terms Phi*Vhi + Phi*Vlo + Plo*Vhi ----
        #pragma unroll
        for (int nf = 0; nf < 8; nf++) {
            uint32_t vh[4], vl[4];
            int nrow = nf * 8 + (lane & 7);
            ldmx4(vh, &Vb[nrow * VSTR + (lane >> 3) * 8]);        // hi cols 0-31
            ldmx4(vl, &Vb[nrow * VSTR + 32 + (lane >> 3) * 8]);   // lo cols 0-31
            mma16816(O[nf], Phi0, vh[0], vh[1]);
            mma16816(O[nf], Phi1, vh[2], vh[3]);
            mma16816(O[nf], Phi0, vl[0], vl[1]);
            mma16816(O[nf], Phi1, vl[2], vl[3]);
            mma16816(O[nf], Plo0, vh[0], vh[1]);
            mma16816(O[nf], Plo1, vh[2], vh[3]);
        }
        __syncthreads();
    }

    // ---- epilogue ----
    float inv0 = 1.0f / lrow[0], inv1 = 1.0f / lrow[1];
    int i0 = irow0, i1 = irow0 + 8;
    #pragma unroll
    for (int nf = 0; nf < 8; nf++) {
        int col = h * DH + nf * 8 + t2;
        *reinterpret_cast<float2*>(&ao[((size_t)b * T_ + i0) * DM + col]) =
            make_float2(O[nf][0] * inv0, O[nf][1] * inv0);
        *reinterpret_cast<float2*>(&ao[((size_t)b * T_ + i1) * DM + col]) =
            make_float2(O[nf][2] * inv1, O[nf][3] * inv1);
    }
}

extern "C" void kernel_launch(void* const* d_in, const int* in_sizes, int n_in,
                              void* d_out, int out_size) {
    const float* x  = (const float*)d_in[0];
    const float* wq = (const float*)d_in[1];
    const float* wk = (const float*)d_in[2];
    const float* wv = (const float*)d_in[3];
    const float* wo = (const float*)d_in[4];
    float* out = (float*)d_out;

    __nv_bfloat16 *ax, *wt1, *wt2, *qsp, *ksp, *vthi, *vtlo;
    float *qkv, *ao, *kr, *vr;
    cudaGetSymbolAddress((void**)&ax,   g_ax);
    cudaGetSymbolAddress((void**)&wt1,  g_wt1);
    cudaGetSymbolAddress((void**)&wt2,  g_wt2);
    cudaGetSymbolAddress((void**)&qkv,  g_qkv);
    cudaGetSymbolAddress((void**)&ao,   g_ao);
    cudaGetSymbolAddress((void**)&kr,   g_kr);
    cudaGetSymbolAddress((void**)&vr,   g_vr);
    cudaGetSymbolAddress((void**)&qsp,  g_qsp);
    cudaGetSymbolAddress((void**)&ksp,  g_ksp);
    cudaGetSymbolAddress((void**)&vthi, g_vthi);
    cudaGetSymbolAddress((void**)&vtlo, g_vtlo);

    const int out_elems = B_ * T_ * DM;
    const int kv_elems  = B_ * NKV * T_ * DH;
    float* kout = kr; float* vout = vr;
    if (out_size >= out_elems + 2 * kv_elems) {
        kout = out + out_elems;
        vout = out + out_elems + kv_elems;
    }

    const int attn_smem = (64 * QSTR + 2 * 32 * QSTR + 2 * 64 * VSTR) * 2; // 69632 B
    cudaFuncSetAttribute(attn_mma_kernel, cudaFuncAttributeMaxDynamicSharedMemorySize, attn_smem);

    split_act_kernel <<<(MROWS*DM + 255)/256, 256>>>(x, ax);
    split_wqkv_kernel<<<(1280*DM  + 255)/256, 256>>>(wq, wk, wv, wt1);
    split_wo_kernel  <<<(DM*DM    + 255)/256, 256>>>(wo, wt2);

    gemm_bf16_kernel<<<dim3(1280/BN, MROWS/BM), 256>>>(ax, wt1, qkv, 1280, K3);
    rope_kernel<<<MROWS, 384>>>(qkv, kout, vout, qsp, ksp, vthi, vtlo);
    attn_mma_kernel<<<B_ * NH * (T_/64), 128, attn_smem>>>(qsp, ksp, vthi, vtlo, ao);
    split_act_kernel<<<(MROWS*DM + 255)/256, 256>>>(ao, ax);
    gemm_bf16_kernel<<<dim3(DM/BN, MROWS/BM), 256>>>(ax, wt2, out, DM, K3);
}

// round 8
// speedup vs baseline: 4.8014x; 1.5499x over previous
#include <cuda_runtime.h>
#include <cuda_fp16.h>
#include <stdint.h>
#include <cstdint>
#include <math.h>

#define B_ 2
#define T_ 2048
#define DM 768
#define NH 12
#define NKV 4
#define DH 64
#define WIN 512
#define GLB 64
#define MROWS (B_*T_)          // 4096
#define K2 1536                // stacked-K (2x) for fp16 hi/lo trick
#define KW 768                 // weight K (single copy; loader wraps)

// ---------------- scratch ----------------
__device__ __half g_ax[(size_t)MROWS*K2];        // split activations [4096][hi768|lo768]
__device__ __half g_wt1[(size_t)1280*KW];        // fp16 transposed [wq|wk|wv] : [1280][768]
__device__ __half g_wt2[(size_t)DM*KW];          // fp16 transposed wo : [768][768]
__device__ float  g_qkv[(size_t)MROWS*1280];     // fused qkv proj out (fp32)
__device__ float  g_kr[(size_t)B_*NKV*T_*DH];    // fallback k out
__device__ float  g_vr[(size_t)B_*NKV*T_*DH];    // fallback v out
__device__ __half g_qsp[(size_t)B_*NH*T_*128];   // Q' [b,h,t][hi64|lo64], pre-scaled 1/8
__device__ __half g_ksp[(size_t)B_*NKV*T_*DH];   // K fp16 [b,kvh,t][64]
__device__ __half g_vt[(size_t)B_*NKV*DH*T_];    // V^T fp16 [b,kvh,d][t]

// ---------------- helpers ----------------
__device__ __forceinline__ void cp16(void* smem, const void* gmem) {
    uint32_t s = (uint32_t)__cvta_generic_to_shared(smem);
    asm volatile("cp.async.cg.shared.global [%0], [%1], 16;\n" :: "r"(s), "l"(gmem));
}
__device__ __forceinline__ void cp_commit() { asm volatile("cp.async.commit_group;\n"); }

__device__ __forceinline__ void ldmx4(uint32_t* r, const void* p) {
    uint32_t a = (uint32_t)__cvta_generic_to_shared(p);
    asm volatile("ldmatrix.sync.aligned.m8n8.x4.shared.b16 {%0,%1,%2,%3}, [%4];"
                 : "=r"(r[0]), "=r"(r[1]), "=r"(r[2]), "=r"(r[3]) : "r"(a));
}
__device__ __forceinline__ void mma16816(float* d, const uint32_t* a, uint32_t b0, uint32_t b1) {
    asm volatile("mma.sync.aligned.m16n8k16.row.col.f32.f16.f16.f32 "
                 "{%0,%1,%2,%3}, {%4,%5,%6,%7}, {%8,%9}, {%0,%1,%2,%3};"
                 : "+f"(d[0]), "+f"(d[1]), "+f"(d[2]), "+f"(d[3])
                 : "r"(a[0]), "r"(a[1]), "r"(a[2]), "r"(a[3]), "r"(b0), "r"(b1));
}
__device__ __forceinline__ uint32_t packh2(float a, float b) {
    __half2 h = __floats2half2_rn(a, b);
    return *reinterpret_cast<uint32_t*>(&h);
}

// ---------------- split kernels ----------------
// A': row r = [hi(x row) | lo(x row)] fp16
__global__ void split_act_kernel(const float* __restrict__ src, __half* __restrict__ dst) {
    int idx = blockIdx.x * blockDim.x + threadIdx.x;
    if (idx >= MROWS * DM) return;
    int r = idx / DM, c = idx % DM;
    float x = src[idx];
    __half hi = __float2half_rn(x);
    __half lo = __float2half_rn(x - __half2float(hi));
    size_t base = (size_t)r * K2;
    dst[base + c] = hi;
    dst[base + c + KW] = lo;
}

__global__ void split_wqkv_kernel(const float* __restrict__ wq, const float* __restrict__ wk,
                                  const float* __restrict__ wv, __half* __restrict__ dst) {
    int idx = blockIdx.x * blockDim.x + threadIdx.x;
    if (idx >= 1280 * DM) return;
    int n = idx / DM, k = idx % DM;
    float x;
    if (n < 768)       x = wq[(size_t)k * 768 + n];
    else if (n < 1024) x = wk[(size_t)k * 256 + (n - 768)];
    else               x = wv[(size_t)k * 256 + (n - 1024)];
    dst[(size_t)n * KW + k] = __float2half_rn(x);
}

__global__ void split_wo_kernel(const float* __restrict__ wo, __half* __restrict__ dst) {
    int idx = blockIdx.x * blockDim.x + threadIdx.x;
    if (idx >= DM * DM) return;
    int n = idx / DM, k = idx % DM;
    dst[(size_t)n * KW + k] = __float2half_rn(wo[(size_t)k * DM + n]);
}

// ---------------- fp16 tensor-core GEMM ----------------
// C[M,N] = A'[M,1536] @ ([W|W])^T. B loader wraps k at 768. 3-stage cp.async ring.
#define BM 128
#define BN 128
#define BK 32
#define SAP 40
#define KT2 (K2/BK)   // 48

__global__ void __launch_bounds__(256, 2)
gemm_fp16_kernel(const __half* __restrict__ A, const __half* __restrict__ Bt,
                 float* __restrict__ C, int N) {
    __shared__ __align__(16) __half As[3][BM * SAP];
    __shared__ __align__(16) __half Bs[3][BN * SAP];

    int tid = threadIdx.x;
    int warp = tid >> 5, lane = tid & 31;
    int wm = warp & 1;
    int wn = warp >> 1;
    int bm = blockIdx.y * BM, bn = blockIdx.x * BN;
    int g = lane >> 2;
    int t2 = (lane & 3) * 2;

    float acc[4][4][4];
    #pragma unroll
    for (int i = 0; i < 4; i++)
        #pragma unroll
        for (int j = 0; j < 4; j++)
            #pragma unroll
            for (int r = 0; r < 4; r++) acc[i][j][r] = 0.f;

    auto load_stage = [&](int st, int kt) {
        int koff = kt * BK;
        int bko = koff < KW ? koff : koff - KW;
        #pragma unroll
        for (int i = 0; i < 2; i++) {
            int chunk = tid + i * 256;
            int row = chunk >> 2, c4 = chunk & 3;
            cp16(&As[st][row * SAP + c4 * 8], A + (size_t)(bm + row) * K2 + koff + c4 * 8);
        }
        #pragma unroll
        for (int i = 0; i < 2; i++) {
            int chunk = tid + i * 256;
            int row = chunk >> 2, c4 = chunk & 3;
            cp16(&Bs[st][row * SAP + c4 * 8], Bt + (size_t)(bn + row) * KW + bko + c4 * 8);
        }
        cp_commit();
    };

    load_stage(0, 0);
    load_stage(1, 1);

    for (int kt = 0; kt < KT2; kt++) {
        int s = kt % 3;
        if (kt == KT2 - 1) asm volatile("cp.async.wait_group 0;\n");
        else               asm volatile("cp.async.wait_group 1;\n");
        __syncthreads();
        if (kt + 2 < KT2) load_stage((kt + 2) % 3, kt + 2);

        #pragma unroll
        for (int ks = 0; ks < BK; ks += 16) {
            uint32_t a[4][4], b[4][2];
            #pragma unroll
            for (int mf = 0; mf < 4; mf++) {
                int tile = lane >> 3, rr = lane & 7;
                int mrow = wm * 64 + mf * 16 + (tile & 1) * 8 + rr;
                int kcol = ks + (tile >> 1) * 8;
                ldmx4(a[mf], &As[s][mrow * SAP + kcol]);
            }
            #pragma unroll
            for (int nf = 0; nf < 4; nf++) {
                int tile = (lane >> 3) & 1, rr = lane & 7;
                int nrow = wn * 32 + nf * 8 + rr;
                int kcol = ks + tile * 8;
                uint32_t addr = (uint32_t)__cvta_generic_to_shared(&Bs[s][nrow * SAP + kcol]);
                asm volatile("ldmatrix.sync.aligned.m8n8.x2.shared.b16 {%0,%1}, [%2];"
                             : "=r"(b[nf][0]), "=r"(b[nf][1]) : "r"(addr));
            }
            #pragma unroll
            for (int mf = 0; mf < 4; mf++)
                #pragma unroll
                for (int nf = 0; nf < 4; nf++)
                    mma16816(acc[mf][nf], a[mf], b[nf][0], b[nf][1]);
        }
    }

    #pragma unroll
    for (int mf = 0; mf < 4; mf++) {
        int r0 = bm + wm * 64 + mf * 16 + g;
        #pragma unroll
        for (int nf = 0; nf < 4; nf++) {
            int c0 = bn + wn * 32 + nf * 8 + t2;
            *reinterpret_cast<float2*>(&C[(size_t)r0 * N + c0]) =
                make_float2(acc[mf][nf][0], acc[mf][nf][1]);
            *reinterpret_cast<float2*>(&C[(size_t)(r0 + 8) * N + c0]) =
                make_float2(acc[mf][nf][2], acc[mf][nf][3]);
        }
    }
}

// ---------------- RoPE + transpose + fp16 split ----------------
__global__ void rope_kernel(const float* __restrict__ qkv,
                            float* __restrict__ kout, float* __restrict__ vout,
                            __half* __restrict__ qsp, __half* __restrict__ ksp,
                            __half* __restrict__ vt) {
    int bt = blockIdx.x;
    int b = bt >> 11, t = bt & (T_ - 1);
    int tid = threadIdx.x;
    const float* row = qkv + (size_t)bt * 1280;
    {   // q: 12 heads x 32 pairs; pre-scale by 1/8, split hi/lo fp16
        int h = tid >> 5, m = tid & 31;
        float inv = powf(10000.0f, -(float)m / 32.0f);
        float ang = (float)t * inv;
        float s, c; sincosf(ang, &s, &c);
        float x0 = row[h * DH + m];
        float x1 = row[h * DH + m + 32];
        float r0 = (x0 * c - x1 * s) * 0.125f;
        float r1 = (x1 * c + x0 * s) * 0.125f;
        size_t base = ((size_t)(b * NH + h) * T_ + t) * 128;
        __half h0 = __float2half_rn(r0);
        __half h1 = __float2half_rn(r1);
        qsp[base + m]       = h0;
        qsp[base + m + 32]  = h1;
        qsp[base + 64 + m]  = __float2half_rn(r0 - __half2float(h0));
        qsp[base + 96 + m]  = __float2half_rn(r1 - __half2float(h1));
    }
    if (tid < NKV * 32) {   // k rope: fp32 out + single fp16
        int h = tid >> 5, m = tid & 31;
        float inv = powf(10000.0f, -(float)m / 32.0f);
        float ang = (float)t * inv;
        float s, c; sincosf(ang, &s, &c);
        float x0 = row[768 + h * DH + m];
        float x1 = row[768 + h * DH + m + 32];
        float r0 = x0 * c - x1 * s;
        float r1 = x1 * c + x0 * s;
        size_t fbase = ((size_t)(b * NKV + h) * T_ + t) * DH;
        kout[fbase + m]      = r0;
        kout[fbase + m + 32] = r1;
        ksp[fbase + m]       = __float2half_rn(r0);
        ksp[fbase + m + 32]  = __float2half_rn(r1);
    }
    if (tid < NKV * DH) {   // v: fp32 copy + fp16 transposed [d][t]
        int h = tid >> 6, d = tid & 63;
        float v = row[1024 + tid];
        vout[((size_t)(b * NKV + h) * T_ + t) * DH + d] = v;
        vt[((size_t)(b * NKV + h) * DH + d) * T_ + t] = __float2half_rn(v);
    }
}

// ---------------- fp16 tensor-core windowed flash attention ----------------
// block = (b, h, 64-query tile); 4 warps x 16 q-rows.
// S = [q_hi|q_lo][64x128] @ [k;k]^T (k indexed twice), online softmax,
// O += [P_hi|P_lo] @ [V;V] (V indexed twice). Epilogue writes fp16 hi/lo into g_ax.
#define QSTR 136
#define KSTR 72
#define VSTR 40

__global__ void attn_mma_kernel(const __half* __restrict__ qsp,
                                const __half* __restrict__ ksp,
                                const __half* __restrict__ vt,
                                __half* __restrict__ ax) {
    extern __shared__ __align__(16) __half sm[];
    __half* Qs = sm;                       // [64][QSTR]
    __half* Ks = Qs + 64 * QSTR;           // [2][32][KSTR]
    __half* Vs = Ks + 2 * 32 * KSTR;       // [2][64][VSTR]

    int blk = blockIdx.x;
    int qt = 31 - blk / (B_ * NH);         // big tiles first
    int rest = blk % (B_ * NH);
    int h = rest % NH, b = rest / NH;
    int kvh = h / (NH / NKV);
    int qbase = qt * 64;

    int tid = threadIdx.x, w = tid >> 5, lane = tid & 31;
    int g = lane >> 2, t2 = (lane & 3) * 2;

    const __half* Qg = qsp + ((size_t)(b * NH + h) * T_ + qbase) * 128;
    const __half* Kg = ksp + (size_t)(b * NKV + kvh) * T_ * DH;
    const __half* Vg = vt + (size_t)(b * NKV + kvh) * DH * T_;

    int cw0 = (qbase - (WIN - 1)) >> 5; if (cw0 < 2) cw0 = 2;
    int cend = (qbase + 64) >> 5;
    int nch = 2 + (cend > cw0 ? cend - cw0 : 0);

    // Q tile 64 x 128: 1024 16B units
    #pragma unroll
    for (int i = 0; i < 8; i++) {
        int u = tid + i * 128;
        int r = u >> 4, c = u & 15;
        cp16(&Qs[r * QSTR + c * 8], Qg + (size_t)r * 128 + c * 8);
    }

    auto load_chunk = [&](int buf, int cid) {
        int c0 = cid * 32;
        __half* Kb = Ks + buf * 32 * KSTR;
        __half* Vb = Vs + buf * 64 * VSTR;
        #pragma unroll
        for (int i = 0; i < 2; i++) {            // K: 32 rows x 8 units (64 cols)
            int u = tid + i * 128;
            int r = u >> 3, c = u & 7;
            cp16(&Kb[r * KSTR + c * 8], Kg + (size_t)(c0 + r) * DH + c * 8);
        }
        #pragma unroll
        for (int i = 0; i < 2; i++) {            // V: 64 rows x 4 units (32 cols)
            int u = tid + i * 128;
            int r = u >> 2, seg = u & 3;
            cp16(&Vb[r * VSTR + seg * 8], Vg + (size_t)r * T_ + c0 + seg * 8);
        }
    };

    load_chunk(0, 0);
    cp_commit();

    float O[8][4];
    #pragma unroll
    for (int nf = 0; nf < 8; nf++)
        #pragma unroll
        for (int r = 0; r < 4; r++) O[nf][r] = 0.f;
    float mrow[2] = {-1e30f, -1e30f};
    float lrow[2] = {0.f, 0.f};
    int irow0 = qbase + w * 16 + g;

    for (int idx = 0; idx < nch; idx++) {
        int buf = idx & 1;
        int cid = (idx < 2) ? idx : cw0 + (idx - 2);
        int c0 = cid * 32;
        if (idx + 1 < nch) {
            int cid2 = (idx + 1 < 2) ? idx + 1 : cw0 + (idx - 1);
            load_chunk(buf ^ 1, cid2);
            cp_commit();
            asm volatile("cp.async.wait_group 1;\n");
        } else {
            asm volatile("cp.async.wait_group 0;\n");
        }
        __syncthreads();

        const __half* Kb = Ks + buf * 32 * KSTR;
        const __half* Vb = Vs + buf * 64 * VSTR;

        // ---- S = Q'K^T : [16 x 32] per warp, k' = 128 (k indexed mod 64) ----
        float sc[4][4];
        #pragma unroll
        for (int nf = 0; nf < 4; nf++)
            #pragma unroll
            for (int r = 0; r < 4; r++) sc[nf][r] = 0.f;

        #pragma unroll
        for (int kb = 0; kb < 4; kb++) {
            uint32_t aA[4], aB[4];
            {
                int tile = lane >> 3, rr = lane & 7;
                int mrw = w * 16 + (tile & 1) * 8 + rr;
                ldmx4(aA, &Qs[mrw * QSTR + kb * 32 + (tile >> 1) * 8]);
                ldmx4(aB, &Qs[mrw * QSTR + kb * 32 + 16 + (tile >> 1) * 8]);
            }
            int kk = (kb & 1) * 32;
            #pragma unroll
            for (int nf = 0; nf < 4; nf++) {
                uint32_t bb[4];
                ldmx4(bb, &Kb[(nf * 8 + (lane & 7)) * KSTR + kk + (lane >> 3) * 8]);
                mma16816(sc[nf], aA, bb[0], bb[1]);
                mma16816(sc[nf], aB, bb[2], bb[3]);
            }
        }

        // ---- mask + online softmax ----
        float cmax[2] = {-1e30f, -1e30f};
        #pragma unroll
        for (int nf = 0; nf < 4; nf++)
            #pragma unroll
            for (int r = 0; r < 4; r++) {
                int j = c0 + nf * 8 + t2 + (r & 1);
                int i = irow0 + (r >> 1) * 8;
                bool a = (j <= i) && ((j > i - WIN) || (j < GLB) || (i < GLB));
                float s = a ? sc[nf][r] : -1e30f;
                sc[nf][r] = s;
                cmax[r >> 1] = fmaxf(cmax[r >> 1], s);
            }
        #pragma unroll
        for (int r2 = 0; r2 < 2; r2++) {
            cmax[r2] = fmaxf(cmax[r2], __shfl_xor_sync(0xffffffffu, cmax[r2], 1));
            cmax[r2] = fmaxf(cmax[r2], __shfl_xor_sync(0xffffffffu, cmax[r2], 2));
        }
        float scl[2], rsum[2] = {0.f, 0.f};
        #pragma unroll
        for (int r2 = 0; r2 < 2; r2++) {
            float mn = fmaxf(mrow[r2], cmax[r2]);
            scl[r2] = __expf(mrow[r2] - mn);
            mrow[r2] = mn;
        }
        #pragma unroll
        for (int nf = 0; nf < 4; nf++)
            #pragma unroll
            for (int r = 0; r < 4; r++) {
                float s = sc[nf][r];
                float p = (s > -5e29f) ? __expf(s - mrow[r >> 1]) : 0.f;
                sc[nf][r] = p;
                rsum[r >> 1] += p;
            }
        #pragma unroll
        for (int r2 = 0; r2 < 2; r2++) {
            rsum[r2] += __shfl_xor_sync(0xffffffffu, rsum[r2], 1);
            rsum[r2] += __shfl_xor_sync(0xffffffffu, rsum[r2], 2);
            lrow[r2] = lrow[r2] * scl[r2] + rsum[r2];
        }
        #pragma unroll
        for (int nf = 0; nf < 8; nf++) {
            O[nf][0] *= scl[0]; O[nf][1] *= scl[0];
            O[nf][2] *= scl[1]; O[nf][3] *= scl[1];
        }

        // ---- P fragments (fp16 hi/lo, exact split) ----
        uint32_t Phi0[4], Phi1[4], Plo0[4], Plo1[4];
        {
            float pl[4][4];
            #pragma unroll
            for (int nf = 0; nf < 4; nf++)
                #pragma unroll
                for (int r = 0; r < 4; r++) {
                    float p = sc[nf][r];
                    float ph = __half2float(__float2half_rn(p));
                    pl[nf][r] = p - ph;
                }
            Phi0[0] = packh2(sc[0][0], sc[0][1]); Phi0[1] = packh2(sc[0][2], sc[0][3]);
            Phi0[2] = packh2(sc[1][0], sc[1][1]); Phi0[3] = packh2(sc[1][2], sc[1][3]);
            Phi1[0] = packh2(sc[2][0], sc[2][1]); Phi1[1] = packh2(sc[2][2], sc[2][3]);
            Phi1[2] = packh2(sc[3][0], sc[3][1]); Phi1[3] = packh2(sc[3][2], sc[3][3]);
            Plo0[0] = packh2(pl[0][0], pl[0][1]); Plo0[1] = packh2(pl[0][2], pl[0][3]);
            Plo0[2] = packh2(pl[1][0], pl[1][1]); Plo0[3] = packh2(pl[1][2], pl[1][3]);
            Plo1[0] = packh2(pl[2][0], pl[2][1]); Plo1[1] = packh2(pl[2][2], pl[2][3]);
            Plo1[2] = packh2(pl[3][0], pl[3][1]); Plo1[3] = packh2(pl[3][2], pl[3][3]);
        }

        // ---- O += P V (V indexed twice) ----
        #pragma unroll
        for (int nf = 0; nf < 8; nf++) {
            uint32_t vv[4];
            ldmx4(vv, &Vb[(nf * 8 + (lane & 7)) * VSTR + (lane >> 3) * 8]);
            mma16816(O[nf], Phi0, vv[0], vv[1]);
            mma16816(O[nf], Phi1, vv[2], vv[3]);
            mma16816(O[nf], Plo0, vv[0], vv[1]);
            mma16816(O[nf], Plo1, vv[2], vv[3]);
        }
        __syncthreads();
    }

    // ---- epilogue: normalize + fp16 hi/lo split directly into gemm2's A ----
    float inv0 = 1.0f / lrow[0], inv1 = 1.0f / lrow[1];
    size_t r0g = (size_t)b * T_ + irow0;
    size_t r1g = r0g + 8;
    #pragma unroll
    for (int nf = 0; nf < 8; nf++) {
        int col = h * DH + nf * 8 + t2;
        float v00 = O[nf][0] * inv0, v01 = O[nf][1] * inv0;
        float v10 = O[nf][2] * inv1, v11 = O[nf][3] * inv1;
        __half h00 = __float2half_rn(v00), h01 = __float2half_rn(v01);
        __half h10 = __float2half_rn(v10), h11 = __float2half_rn(v11);
        *reinterpret_cast<uint32_t*>(&ax[r0g * K2 + col]) = packh2(v00, v01);
        *reinterpret_cast<uint32_t*>(&ax[r1g * K2 + col]) = packh2(v10, v11);
        *reinterpret_cast<uint32_t*>(&ax[r0g * K2 + KW + col]) =
            packh2(v00 - __half2float(h00), v01 - __half2float(h01));
        *reinterpret_cast<uint32_t*>(&ax[r1g * K2 + KW + col]) =
            packh2(v10 - __half2float(h10), v11 - __half2float(h11));
    }
}

extern "C" void kernel_launch(void* const* d_in, const int* in_sizes, int n_in,
                              void* d_out, int out_size) {
    const float* x  = (const float*)d_in[0];
    const float* wq = (const float*)d_in[1];
    const float* wk = (const float*)d_in[2];
    const float* wv = (const float*)d_in[3];
    const float* wo = (const float*)d_in[4];
    float* out = (float*)d_out;

    __half *ax, *wt1, *wt2, *qsp, *ksp, *vt;
    float *qkv, *kr, *vr;
    cudaGetSymbolAddress((void**)&ax,  g_ax);
    cudaGetSymbolAddress((void**)&wt1, g_wt1);
    cudaGetSymbolAddress((void**)&wt2, g_wt2);
    cudaGetSymbolAddress((void**)&qkv, g_qkv);
    cudaGetSymbolAddress((void**)&kr,  g_kr);
    cudaGetSymbolAddress((void**)&vr,  g_vr);
    cudaGetSymbolAddress((void**)&qsp, g_qsp);
    cudaGetSymbolAddress((void**)&ksp, g_ksp);
    cudaGetSymbolAddress((void**)&vt,  g_vt);

    const int out_elems = B_ * T_ * DM;
    const int kv_elems  = B_ * NKV * T_ * DH;
    float* kout = kr; float* vout = vr;
    if (out_size >= out_elems + 2 * kv_elems) {
        kout = out + out_elems;
        vout = out + out_elems + kv_elems;
    }

    const int attn_smem = (64 * QSTR + 2 * 32 * KSTR + 2 * 64 * VSTR) * 2; // 36864 B
    cudaFuncSetAttribute(attn_mma_kernel, cudaFuncAttributeMaxDynamicSharedMemorySize, attn_smem);

    split_act_kernel <<<(MROWS*DM + 255)/256, 256>>>(x, ax);
    split_wqkv_kernel<<<(1280*DM  + 255)/256, 256>>>(wq, wk, wv, wt1);
    split_wo_kernel  <<<(DM*DM    + 255)/256, 256>>>(wo, wt2);

    gemm_fp16_kernel<<<dim3(1280/BN, MROWS/BM), 256>>>(ax, wt1, qkv, 1280);
    rope_kernel<<<MROWS, 384>>>(qkv, kout, vout, qsp, ksp, vt);
    attn_mma_kernel<<<B_ * NH * (T_/64), 128, attn_smem>>>(qsp, ksp, vt, ax);
    gemm_fp16_kernel<<<dim3(DM/BN, MROWS/BM), 256>>>(ax, wt2, out, DM);
}

// round 11
// speedup vs baseline: 5.2154x; 1.0862x over previous
#include <cuda_runtime.h>
#include <cuda_fp16.h>
#include <stdint.h>
#include <cstdint>
#include <math.h>

#define B_ 2
#define T_ 2048
#define DM 768
#define NH 12
#define NKV 4
#define DH 64
#define WIN 512
#define GLB 64
#define MROWS (B_*T_)          // 4096
#define K2 1536                // stacked-K (2x) for fp16 hi/lo trick
#define KW 768                 // weight K (single copy; loader wraps)

// ---------------- scratch ----------------
__device__ __half g_ax[(size_t)MROWS*K2];        // split activations [4096][hi768|lo768]
__device__ __half g_wt1[(size_t)1280*KW];        // fp16 transposed [wq|wk|wv] : [1280][768]
__device__ __half g_wt2[(size_t)DM*KW];          // fp16 transposed wo : [768][768]
__device__ float  g_qkv[(size_t)MROWS*1280];     // fused qkv proj out (fp32)
__device__ float  g_kr[(size_t)B_*NKV*T_*DH];    // fallback k out
__device__ float  g_vr[(size_t)B_*NKV*T_*DH];    // fallback v out
__device__ __half g_qsp[(size_t)B_*NH*T_*128];   // Q' [b,h,t][hi64|lo64], pre-scaled 1/8
__device__ __half g_ksp[(size_t)B_*NKV*T_*DH];   // K fp16 [b,kvh,t][64]
__device__ __half g_vt[(size_t)B_*NKV*DH*T_];    // V^T fp16 [b,kvh,d][t]

// ---------------- helpers ----------------
__device__ __forceinline__ void cp16(void* smem, const void* gmem) {
    uint32_t s = (uint32_t)__cvta_generic_to_shared(smem);
    asm volatile("cp.async.cg.shared.global [%0], [%1], 16;\n" :: "r"(s), "l"(gmem));
}
__device__ __forceinline__ void cp_commit() { asm volatile("cp.async.commit_group;\n"); }

__device__ __forceinline__ void ldmx4(uint32_t* r, const void* p) {
    uint32_t a = (uint32_t)__cvta_generic_to_shared(p);
    asm volatile("ldmatrix.sync.aligned.m8n8.x4.shared.b16 {%0,%1,%2,%3}, [%4];"
                 : "=r"(r[0]), "=r"(r[1]), "=r"(r[2]), "=r"(r[3]) : "r"(a));
}
__device__ __forceinline__ void mma16816(float* d, const uint32_t* a, uint32_t b0, uint32_t b1) {
    asm volatile("mma.sync.aligned.m16n8k16.row.col.f32.f16.f16.f32 "
                 "{%0,%1,%2,%3}, {%4,%5,%6,%7}, {%8,%9}, {%0,%1,%2,%3};"
                 : "+f"(d[0]), "+f"(d[1]), "+f"(d[2]), "+f"(d[3])
                 : "r"(a[0]), "r"(a[1]), "r"(a[2]), "r"(a[3]), "r"(b0), "r"(b1));
}
__device__ __forceinline__ uint32_t packh2(float a, float b) {
    __half2 h = __floats2half2_rn(a, b);
    return *reinterpret_cast<uint32_t*>(&h);
}

// ---------------- fused prep: activation split + weight transposes ----------------
#define N_ACT (MROWS*DM)          // 3145728
#define N_W1  (1280*DM)           // 983040
#define N_W2  (DM*DM)             // 589824
__global__ void prep_kernel(const float* __restrict__ x,
                            const float* __restrict__ wq, const float* __restrict__ wk,
                            const float* __restrict__ wv, const float* __restrict__ wo,
                            __half* __restrict__ ax, __half* __restrict__ wt1,
                            __half* __restrict__ wt2) {
    int idx = blockIdx.x * blockDim.x + threadIdx.x;
    if (idx < N_ACT) {
        int r = idx / DM, c = idx % DM;
        float v = x[idx];
        __half hi = __float2half_rn(v);
        __half lo = __float2half_rn(v - __half2float(hi));
        size_t base = (size_t)r * K2;
        ax[base + c] = hi;
        ax[base + c + KW] = lo;
    } else if (idx < N_ACT + N_W1) {
        int e = idx - N_ACT;
        int n = e / DM, k = e % DM;
        float v;
        if (n < 768)       v = wq[(size_t)k * 768 + n];
        else if (n < 1024) v = wk[(size_t)k * 256 + (n - 768)];
        else               v = wv[(size_t)k * 256 + (n - 1024)];
        wt1[(size_t)n * KW + k] = __float2half_rn(v);
    } else if (idx < N_ACT + N_W1 + N_W2) {
        int e = idx - N_ACT - N_W1;
        int n = e / DM, k = e % DM;
        wt2[(size_t)n * KW + k] = __float2half_rn(wo[(size_t)k * DM + n]);
    }
}

// ---------------- fp16 tensor-core GEMM ----------------
// C[M,N] = A'[M,1536] @ ([W|W])^T. B loader wraps k at 768.
// BK=64 (half the syncs of BK=32), 3-stage cp.async ring, dynamic smem.
#define BM 128
#define BN 128
#define BK 64
#define SAP 72                 // padded row stride (halves); 144B rows, conflict-free ldmatrix
#define ASTG (BM*SAP)          // halves per stage per operand (18432 B)
#define KT2 (K2/BK)            // 24

__global__ void __launch_bounds__(256, 2)
gemm_fp16_kernel(const __half* __restrict__ A, const __half* __restrict__ Bt,
                 float* __restrict__ C, int N) {
    extern __shared__ __align__(16) __half smem_g[];
    __half* As = smem_g;               // [3][ASTG]
    __half* Bs = smem_g + 3 * ASTG;    // [3][ASTG]

    int tid = threadIdx.x;
    int warp = tid >> 5, lane = tid & 31;
    int wm = warp & 1;
    int wn = warp >> 1;
    int bm = blockIdx.y * BM, bn = blockIdx.x * BN;
    int g = lane >> 2;
    int t2 = (lane & 3) * 2;

    float acc[4][4][4];
    #pragma unroll
    for (int i = 0; i < 4; i++)
        #pragma unroll
        for (int j = 0; j < 4; j++)
            #pragma unroll
            for (int r = 0; r < 4; r++) acc[i][j][r] = 0.f;

    auto load_stage = [&](int st, int kt) {
        int koff = kt * BK;
        int bko = koff < KW ? koff : koff - KW;
        #pragma unroll
        for (int i = 0; i < 4; i++) {              // A: 128 rows x 8 units
            int chunk = tid + i * 256;
            int row = chunk >> 3, c8 = chunk & 7;
            cp16(&As[st * ASTG + row * SAP + c8 * 8],
                 A + (size_t)(bm + row) * K2 + koff + c8 * 8);
        }
        #pragma unroll
        for (int i = 0; i < 4; i++) {              // B: 128 rows x 8 units
            int chunk = tid + i * 256;
            int row = chunk >> 3, c8 = chunk & 7;
            cp16(&Bs[st * ASTG + row * SAP + c8 * 8],
                 Bt + (size_t)(bn + row) * KW + bko + c8 * 8);
        }
        cp_commit();
    };

    load_stage(0, 0);
    load_stage(1, 1);

    for (int kt = 0; kt < KT2; kt++) {
        int s = kt % 3;
        if (kt == KT2 - 1) asm volatile("cp.async.wait_group 0;\n");
        else               asm volatile("cp.async.wait_group 1;\n");
        __syncthreads();
        if (kt + 2 < KT2) load_stage((kt + 2) % 3, kt + 2);

        #pragma unroll
        for (int ks = 0; ks < BK; ks += 16) {
            uint32_t a[4][4], b[4][2];
            #pragma unroll
            for (int mf = 0; mf < 4; mf++) {
                int tile = lane >> 3, rr = lane & 7;
                int mrow = wm * 64 + mf * 16 + (tile & 1) * 8 + rr;
                int kcol = ks + (tile >> 1) * 8;
                ldmx4(a[mf], &As[s * ASTG + mrow * SAP + kcol]);
            }
            #pragma unroll
            for (int nf = 0; nf < 4; nf++) {
                int tile = (lane >> 3) & 1, rr = lane & 7;
                int nrow = wn * 32 + nf * 8 + rr;
                int kcol = ks + tile * 8;
                uint32_t addr = (uint32_t)__cvta_generic_to_shared(&Bs[s * ASTG + nrow * SAP + kcol]);
                asm volatile("ldmatrix.sync.aligned.m8n8.x2.shared.b16 {%0,%1}, [%2];"
                             : "=r"(b[nf][0]), "=r"(b[nf][1]) : "r"(addr));
            }
            #pragma unroll
            for (int mf = 0; mf < 4; mf++)
                #pragma unroll
                for (int nf = 0; nf < 4; nf++)
                    mma16816(acc[mf][nf], a[mf], b[nf][0], b[nf][1]);
        }
    }

    #pragma unroll
    for (int mf = 0; mf < 4; mf++) {
        int r0 = bm + wm * 64 + mf * 16 + g;
        #pragma unroll
        for (int nf = 0; nf < 4; nf++) {
            int c0 = bn + wn * 32 + nf * 8 + t2;
            *reinterpret_cast<float2*>(&C[(size_t)r0 * N + c0]) =
                make_float2(acc[mf][nf][0], acc[mf][nf][1]);
            *reinterpret_cast<float2*>(&C[(size_t)(r0 + 8) * N + c0]) =
                make_float2(acc[mf][nf][2], acc[mf][nf][3]);
        }
    }
}

// ---------------- RoPE + transpose + fp16 split ----------------
__global__ void rope_kernel(const float* __restrict__ qkv,
                            float* __restrict__ kout, float* __restrict__ vout,
                            __half* __restrict__ qsp, __half* __restrict__ ksp,
                            __half* __restrict__ vt) {
    int bt = blockIdx.x;
    int b = bt >> 11, t = bt & (T_ - 1);
    int tid = threadIdx.x;
    const float* row = qkv + (size_t)bt * 1280;
    {   // q: 12 heads x 32 pairs; pre-scale by 1/8, split hi/lo fp16
        int h = tid >> 5, m = tid & 31;
        float inv = powf(10000.0f, -(float)m / 32.0f);
        float ang = (float)t * inv;
        float s, c; sincosf(ang, &s, &c);
        float x0 = row[h * DH + m];
        float x1 = row[h * DH + m + 32];
        float r0 = (x0 * c - x1 * s) * 0.125f;
        float r1 = (x1 * c + x0 * s) * 0.125f;
        size_t base = ((size_t)(b * NH + h) * T_ + t) * 128;
        __half h0 = __float2half_rn(r0);
        __half h1 = __float2half_rn(r1);
        qsp[base + m]       = h0;
        qsp[base + m + 32]  = h1;
        qsp[base + 64 + m]  = __float2half_rn(r0 - __half2float(h0));
        qsp[base + 96 + m]  = __float2half_rn(r1 - __half2float(h1));
    }
    if (tid < NKV * 32) {   // k rope: fp32 out + single fp16
        int h = tid >> 5, m = tid & 31;
        float inv = powf(10000.0f, -(float)m / 32.0f);
        float ang = (float)t * inv;
        float s, c; sincosf(ang, &s, &c);
        float x0 = row[768 + h * DH + m];
        float x1 = row[768 + h * DH + m + 32];
        float r0 = x0 * c - x1 * s;
        float r1 = x1 * c + x0 * s;
        size_t fbase = ((size_t)(b * NKV + h) * T_ + t) * DH;
        kout[fbase + m]      = r0;
        kout[fbase + m + 32] = r1;
        ksp[fbase + m]       = __float2half_rn(r0);
        ksp[fbase + m + 32]  = __float2half_rn(r1);
    }
    if (tid < NKV * DH) {   // v: fp32 copy + fp16 transposed [d][t]
        int h = tid >> 6, d = tid & 63;
        float v = row[1024 + tid];
        vout[((size_t)(b * NKV + h) * T_ + t) * DH + d] = v;
        vt[((size_t)(b * NKV + h) * DH + d) * T_ + t] = __float2half_rn(v);
    }
}

// ---------------- fp16 tensor-core windowed flash attention ----------------
#define QSTR 136
#define KSTR 72
#define VSTR 40

__global__ void attn_mma_kernel(const __half* __restrict__ qsp,
                                const __half* __restrict__ ksp,
                                const __half* __restrict__ vt,
                                __half* __restrict__ ax) {
    extern __shared__ __align__(16) __half sm[];
    __half* Qs = sm;                       // [64][QSTR]
    __half* Ks = Qs + 64 * QSTR;           // [2][32][KSTR]
    __half* Vs = Ks + 2 * 32 * KSTR;       // [2][64][VSTR]

    int blk = blockIdx.x;
    int qt = 31 - blk / (B_ * NH);         // big tiles first
    int rest = blk % (B_ * NH);
    int h = rest % NH, b = rest / NH;
    int kvh = h / (NH / NKV);
    int qbase = qt * 64;

    int tid = threadIdx.x, w = tid >> 5, lane = tid & 31;
    int g = lane >> 2, t2 = (lane & 3) * 2;

    const __half* Qg = qsp + ((size_t)(b * NH + h) * T_ + qbase) * 128;
    const __half* Kg = ksp + (size_t)(b * NKV + kvh) * T_ * DH;
    const __half* Vg = vt + (size_t)(b * NKV + kvh) * DH * T_;

    int cw0 = (qbase - (WIN - 1)) >> 5; if (cw0 < 2) cw0 = 2;
    int cend = (qbase + 64) >> 5;
    int nch = 2 + (cend > cw0 ? cend - cw0 : 0);

    #pragma unroll
    for (int i = 0; i < 8; i++) {
        int u = tid + i * 128;
        int r = u >> 4, c = u & 15;
        cp16(&Qs[r * QSTR + c * 8], Qg + (size_t)r * 128 + c * 8);
    }

    auto load_chunk = [&](int buf, int cid) {
        int c0 = cid * 32;
        __half* Kb = Ks + buf * 32 * KSTR;
        __half* Vb = Vs + buf * 64 * VSTR;
        #pragma unroll
        for (int i = 0; i < 2; i++) {            // K: 32 rows x 8 units (64 cols)
            int u = tid + i * 128;
            int r = u >> 3, c = u & 7;
            cp16(&Kb[r * KSTR + c * 8], Kg + (size_t)(c0 + r) * DH + c * 8);
        }
        #pragma unroll
        for (int i = 0; i < 2; i++) {            // V: 64 rows x 4 units (32 cols)
            int u = tid + i * 128;
            int r = u >> 2, seg = u & 3;
            cp16(&Vb[r * VSTR + seg * 8], Vg + (size_t)r * T_ + c0 + seg * 8);
        }
    };

    load_chunk(0, 0);
    cp_commit();

    float O[8][4];
    #pragma unroll
    for (int nf = 0; nf < 8; nf++)
        #pragma unroll
        for (int r = 0; r < 4; r++) O[nf][r] = 0.f;
    float mrow[2] = {-1e30f, -1e30f};
    float lrow[2] = {0.f, 0.f};
    int irow0 = qbase + w * 16 + g;

    for (int idx = 0; idx < nch; idx++) {
        int buf = idx & 1;
        int cid = (idx < 2) ? idx : cw0 + (idx - 2);
        int c0 = cid * 32;
        if (idx + 1 < nch) {
            int cid2 = (idx + 1 < 2) ? idx + 1 : cw0 + (idx - 1);
            load_chunk(buf ^ 1, cid2);
            cp_commit();
            asm volatile("cp.async.wait_group 1;\n");
        } else {
            asm volatile("cp.async.wait_group 0;\n");
        }
        __syncthreads();

        const __half* Kb = Ks + buf * 32 * KSTR;
        const __half* Vb = Vs + buf * 64 * VSTR;

        float sc[4][4];
        #pragma unroll
        for (int nf = 0; nf < 4; nf++)
            #pragma unroll
            for (int r = 0; r < 4; r++) sc[nf][r] = 0.f;

        #pragma unroll
        for (int kb = 0; kb < 4; kb++) {
            uint32_t aA[4], aB[4];
            {
                int tile = lane >> 3, rr = lane & 7;
                int mrw = w * 16 + (tile & 1) * 8 + rr;
                ldmx4(aA, &Qs[mrw * QSTR + kb * 32 + (tile >> 1) * 8]);
                ldmx4(aB, &Qs[mrw * QSTR + kb * 32 + 16 + (tile >> 1) * 8]);
            }
            int kk = (kb & 1) * 32;
            #pragma unroll
            for (int nf = 0; nf < 4; nf++) {
                uint32_t bb[4];
                ldmx4(bb, &Kb[(nf * 8 + (lane & 7)) * KSTR + kk + (lane >> 3) * 8]);
                mma16816(sc[nf], aA, bb[0], bb[1]);
                mma16816(sc[nf], aB, bb[2], bb[3]);
            }
        }

        float cmax[2] = {-1e30f, -1e30f};
        #pragma unroll
        for (int nf = 0; nf < 4; nf++)
            #pragma unroll
            for (int r = 0; r < 4; r++) {
                int j = c0 + nf * 8 + t2 + (r & 1);
                int i = irow0 + (r >> 1) * 8;
                bool a = (j <= i) && ((j > i - WIN) || (j < GLB) || (i < GLB));
                float s = a ? sc[nf][r] : -1e30f;
                sc[nf][r] = s;
                cmax[r >> 1] = fmaxf(cmax[r >> 1], s);
            }
        #pragma unroll
        for (int r2 = 0; r2 < 2; r2++) {
            cmax[r2] = fmaxf(cmax[r2], __shfl_xor_sync(0xffffffffu, cmax[r2], 1));
            cmax[r2] = fmaxf(cmax[r2], __shfl_xor_sync(0xffffffffu, cmax[r2], 2));
        }
        float scl[2], rsum[2] = {0.f, 0.f};
        #pragma unroll
        for (int r2 = 0; r2 < 2; r2++) {
            float mn = fmaxf(mrow[r2], cmax[r2]);
            scl[r2] = __expf(mrow[r2] - mn);
            mrow[r2] = mn;
        }
        #pragma unroll
        for (int nf = 0; nf < 4; nf++)
            #pragma unroll
            for (int r = 0; r < 4; r++) {
                float s = sc[nf][r];
                float p = (s > -5e29f) ? __expf(s - mrow[r >> 1]) : 0.f;
                sc[nf][r] = p;
                rsum[r >> 1] += p;
            }
        #pragma unroll
        for (int r2 = 0; r2 < 2; r2++) {
            rsum[r2] += __shfl_xor_sync(0xffffffffu, rsum[r2], 1);
            rsum[r2] += __shfl_xor_sync(0xffffffffu, rsum[r2], 2);
            lrow[r2] = lrow[r2] * scl[r2] + rsum[r2];
        }
        #pragma unroll
        for (int nf = 0; nf < 8; nf++) {
            O[nf][0] *= scl[0]; O[nf][1] *= scl[0];
            O[nf][2] *= scl[1]; O[nf][3] *= scl[1];
        }

        uint32_t Phi0[4], Phi1[4], Plo0[4], Plo1[4];
        {
            float pl[4][4];
            #pragma unroll
            for (int nf = 0; nf < 4; nf++)
                #pragma unroll
                for (int r = 0; r < 4; r++) {
                    float p = sc[nf][r];
                    float ph = __half2float(__float2half_rn(p));
                    pl[nf][r] = p - ph;
                }
            Phi0[0] = packh2(sc[0][0], sc[0][1]); Phi0[1] = packh2(sc[0][2], sc[0][3]);
            Phi0[2] = packh2(sc[1][0], sc[1][1]); Phi0[3] = packh2(sc[1][2], sc[1][3]);
            Phi1[0] = packh2(sc[2][0], sc[2][1]); Phi1[1] = packh2(sc[2][2], sc[2][3]);
            Phi1[2] = packh2(sc[3][0], sc[3][1]); Phi1[3] = packh2(sc[3][2], sc[3][3]);
            Plo0[0] = packh2(pl[0][0], pl[0][1]); Plo0[1] = packh2(pl[0][2], pl[0][3]);
            Plo0[2] = packh2(pl[1][0], pl[1][1]); Plo0[3] = packh2(pl[1][2], pl[1][3]);
            Plo1[0] = packh2(pl[2][0], pl[2][1]); Plo1[1] = packh2(pl[2][2], pl[2][3]);
            Plo1[2] = packh2(pl[3][0], pl[3][1]); Plo1[3] = packh2(pl[3][2], pl[3][3]);
        }

        #pragma unroll
        for (int nf = 0; nf < 8; nf++) {
            uint32_t vv[4];
            ldmx4(vv, &Vb[(nf * 8 + (lane & 7)) * VSTR + (lane >> 3) * 8]);
            mma16816(O[nf], Phi0, vv[0], vv[1]);
            mma16816(O[nf], Phi1, vv[2], vv[3]);
            mma16816(O[nf], Plo0, vv[0], vv[1]);
            mma16816(O[nf], Plo1, vv[2], vv[3]);
        }
        __syncthreads();
    }

    float inv0 = 1.0f / lrow[0], inv1 = 1.0f / lrow[1];
    size_t r0g = (size_t)b * T_ + irow0;
    size_t r1g = r0g + 8;
    #pragma unroll
    for (int nf = 0; nf < 8; nf++) {
        int col = h * DH + nf * 8 + t2;
        float v00 = O[nf][0] * inv0, v01 = O[nf][1] * inv0;
        float v10 = O[nf][2] * inv1, v11 = O[nf][3] * inv1;
        __half h00 = __float2half_rn(v00), h01 = __float2half_rn(v01);
        __half h10 = __float2half_rn(v10), h11 = __float2half_rn(v11);
        *reinterpret_cast<uint32_t*>(&ax[r0g * K2 + col]) = packh2(v00, v01);
        *reinterpret_cast<uint32_t*>(&ax[r1g * K2 + col]) = packh2(v10, v11);
        *reinterpret_cast<uint32_t*>(&ax[r0g * K2 + KW + col]) =
            packh2(v00 - __half2float(h00), v01 - __half2float(h01));
        *reinterpret_cast<uint32_t*>(&ax[r1g * K2 + KW + col]) =
            packh2(v10 - __half2float(h10), v11 - __half2float(h11));
    }
}

extern "C" void kernel_launch(void* const* d_in, const int* in_sizes, int n_in,
                              void* d_out, int out_size) {
    const float* x  = (const float*)d_in[0];
    const float* wq = (const float*)d_in[1];
    const float* wk = (const float*)d_in[2];
    const float* wv = (const float*)d_in[3];
    const float* wo = (const float*)d_in[4];
    float* out = (float*)d_out;

    __half *ax, *wt1, *wt2, *qsp, *ksp, *vt;
    float *qkv, *kr, *vr;
    cudaGetSymbolAddress((void**)&ax,  g_ax);
    cudaGetSymbolAddress((void**)&wt1, g_wt1);
    cudaGetSymbolAddress((void**)&wt2, g_wt2);
    cudaGetSymbolAddress((void**)&qkv, g_qkv);
    cudaGetSymbolAddress((void**)&kr,  g_kr);
    cudaGetSymbolAddress((void**)&vr,  g_vr);
    cudaGetSymbolAddress((void**)&qsp, g_qsp);
    cudaGetSymbolAddress((void**)&ksp, g_ksp);
    cudaGetSymbolAddress((void**)&vt,  g_vt);

    const int out_elems = B_ * T_ * DM;
    const int kv_elems  = B_ * NKV * T_ * DH;
    float* kout = kr; float* vout = vr;
    if (out_size >= out_elems + 2 * kv_elems) {
        kout = out + out_elems;
        vout = out + out_elems + kv_elems;
    }

    const int gemm_smem = 6 * ASTG * 2;                                    // 110592 B
    cudaFuncSetAttribute(gemm_fp16_kernel, cudaFuncAttributeMaxDynamicSharedMemorySize, gemm_smem);
    const int attn_smem = (64 * QSTR + 2 * 32 * KSTR + 2 * 64 * VSTR) * 2; // 36864 B
    cudaFuncSetAttribute(attn_mma_kernel, cudaFuncAttributeMaxDynamicSharedMemorySize, attn_smem);

    const int prep_total = N_ACT + N_W1 + N_W2;
    prep_kernel<<<(prep_total + 255)/256, 256>>>(x, wq, wk, wv, wo, ax, wt1, wt2);

    gemm_fp16_kernel<<<dim3(1280/BN, MROWS/BM), 256, gemm_smem>>>(ax, wt1, qkv, 1280);
    rope_kernel<<<MROWS, 384>>>(qkv, kout, vout, qsp, ksp, vt);
    attn_mma_kernel<<<B_ * NH * (T_/64), 128, attn_smem>>>(qsp, ksp, vt, ax);
    gemm_fp16_kernel<<<dim3(DM/BN, MROWS/BM), 256, gemm_smem>>>(ax, wt2, out, DM);
}

// round 12
// speedup vs baseline: 5.3320x; 1.0224x over previous
#include <cuda_runtime.h>
#include <cuda_fp16.h>
#include <stdint.h>
#include <cstdint>
#include <math.h>

#define B_ 2
#define T_ 2048
#define DM 768
#define NH 12
#define NKV 4
#define DH 64
#define WIN 512
#define GLB 64
#define MROWS (B_*T_)          // 4096
#define K2 1536                // stacked-K (2x) for fp16 hi/lo trick
#define KW 768                 // weight K (single copy; loader wraps)

// ---------------- scratch ----------------
__device__ __half g_ax[(size_t)MROWS*K2];        // split activations [4096][hi768|lo768]
__device__ __half g_wt1[(size_t)1280*KW];        // fp16 transposed [wq|wk|wv] : [1280][768]
__device__ __half g_wt2[(size_t)DM*KW];          // fp16 transposed wo : [768][768]
__device__ float  g_qkv[(size_t)MROWS*1280];     // fused qkv proj out (fp32)
__device__ float  g_kr[(size_t)B_*NKV*T_*DH];    // fallback k out
__device__ float  g_vr[(size_t)B_*NKV*T_*DH];    // fallback v out
__device__ __half g_qsp[(size_t)B_*NH*T_*128];   // Q' [b,h,t][hi64|lo64], pre-scaled 1/8
__device__ __half g_ksp[(size_t)B_*NKV*T_*DH];   // K fp16 [b,kvh,t][64]
__device__ __half g_vt[(size_t)B_*NKV*DH*T_];    // V^T fp16 [b,kvh,d][t]

// ---------------- helpers ----------------
__device__ __forceinline__ void cp16(void* smem, const void* gmem) {
    uint32_t s = (uint32_t)__cvta_generic_to_shared(smem);
    asm volatile("cp.async.cg.shared.global [%0], [%1], 16;\n" :: "r"(s), "l"(gmem));
}
__device__ __forceinline__ void cp_commit() { asm volatile("cp.async.commit_group;\n"); }

__device__ __forceinline__ void ldmx4(uint32_t* r, const void* p) {
    uint32_t a = (uint32_t)__cvta_generic_to_shared(p);
    asm volatile("ldmatrix.sync.aligned.m8n8.x4.shared.b16 {%0,%1,%2,%3}, [%4];"
                 : "=r"(r[0]), "=r"(r[1]), "=r"(r[2]), "=r"(r[3]) : "r"(a));
}
__device__ __forceinline__ void mma16816(float* d, const uint32_t* a, uint32_t b0, uint32_t b1) {
    asm volatile("mma.sync.aligned.m16n8k16.row.col.f32.f16.f16.f32 "
                 "{%0,%1,%2,%3}, {%4,%5,%6,%7}, {%8,%9}, {%0,%1,%2,%3};"
                 : "+f"(d[0]), "+f"(d[1]), "+f"(d[2]), "+f"(d[3])
                 : "r"(a[0]), "r"(a[1]), "r"(a[2]), "r"(a[3]), "r"(b0), "r"(b1));
}
__device__ __forceinline__ uint32_t packh2(float a, float b) {
    __half2 h = __floats2half2_rn(a, b);
    return *reinterpret_cast<uint32_t*>(&h);
}

// ---------------- fused prep: activation split + weight transposes ----------------
#define N_ACT (MROWS*DM)          // 3145728
#define N_W1  (1280*DM)           // 983040
#define N_W2  (DM*DM)             // 589824
__global__ void prep_kernel(const float* __restrict__ x,
                            const float* __restrict__ wq, const float* __restrict__ wk,
                            const float* __restrict__ wv, const float* __restrict__ wo,
                            __half* __restrict__ ax, __half* __restrict__ wt1,
                            __half* __restrict__ wt2) {
    int idx = blockIdx.x * blockDim.x + threadIdx.x;
    if (idx < N_ACT) {
        int r = idx / DM, c = idx % DM;
        float v = x[idx];
        __half hi = __float2half_rn(v);
        __half lo = __float2half_rn(v - __half2float(hi));
        size_t base = (size_t)r * K2;
        ax[base + c] = hi;
        ax[base + c + KW] = lo;
    } else if (idx < N_ACT + N_W1) {
        int e = idx - N_ACT;
        int n = e / DM, k = e % DM;
        float v;
        if (n < 768)       v = wq[(size_t)k * 768 + n];
        else if (n < 1024) v = wk[(size_t)k * 256 + (n - 768)];
        else               v = wv[(size_t)k * 256 + (n - 1024)];
        wt1[(size_t)n * KW + k] = __float2half_rn(v);
    } else if (idx < N_ACT + N_W1 + N_W2) {
        int e = idx - N_ACT - N_W1;
        int n = e / DM, k = e % DM;
        wt2[(size_t)n * KW + k] = __float2half_rn(wo[(size_t)k * DM + n]);
    }
}

// ---------------- fp16 tensor-core GEMM (frozen from R11-pass) ----------------
#define BM 128
#define BN 128
#define BK 64
#define SAP 72
#define ASTG (BM*SAP)
#define KT2 (K2/BK)   // 24

__global__ void __launch_bounds__(256, 2)
gemm_fp16_kernel(const __half* __restrict__ A, const __half* __restrict__ Bt,
                 float* __restrict__ C, int N) {
    extern __shared__ __align__(16) __half smem_g[];
    __half* As = smem_g;               // [3][ASTG]
    __half* Bs = smem_g + 3 * ASTG;    // [3][ASTG]

    int tid = threadIdx.x;
    int warp = tid >> 5, lane = tid & 31;
    int wm = warp & 1;
    int wn = warp >> 1;
    int bm = blockIdx.y * BM, bn = blockIdx.x * BN;
    int g = lane >> 2;
    int t2 = (lane & 3) * 2;

    float acc[4][4][4];
    #pragma unroll
    for (int i = 0; i < 4; i++)
        #pragma unroll
        for (int j = 0; j < 4; j++)
            #pragma unroll
            for (int r = 0; r < 4; r++) acc[i][j][r] = 0.f;

    auto load_stage = [&](int st, int kt) {
        int koff = kt * BK;
        int bko = koff < KW ? koff : koff - KW;
        #pragma unroll
        for (int i = 0; i < 4; i++) {
            int chunk = tid + i * 256;
            int row = chunk >> 3, c8 = chunk & 7;
            cp16(&As[st * ASTG + row * SAP + c8 * 8],
                 A + (size_t)(bm + row) * K2 + koff + c8 * 8);
        }
        #pragma unroll
        for (int i = 0; i < 4; i++) {
            int chunk = tid + i * 256;
            int row = chunk >> 3, c8 = chunk & 7;
            cp16(&Bs[st * ASTG + row * SAP + c8 * 8],
                 Bt + (size_t)(bn + row) * KW + bko + c8 * 8);
        }
        cp_commit();
    };

    load_stage(0, 0);
    load_stage(1, 1);

    for (int kt = 0; kt < KT2; kt++) {
        int s = kt % 3;
        if (kt == KT2 - 1) asm volatile("cp.async.wait_group 0;\n");
        else               asm volatile("cp.async.wait_group 1;\n");
        __syncthreads();
        if (kt + 2 < KT2) load_stage((kt + 2) % 3, kt + 2);

        #pragma unroll
        for (int ks = 0; ks < BK; ks += 16) {
            uint32_t a[4][4], b[4][2];
            #pragma unroll
            for (int mf = 0; mf < 4; mf++) {
                int tile = lane >> 3, rr = lane & 7;
                int mrow = wm * 64 + mf * 16 + (tile & 1) * 8 + rr;
                int kcol = ks + (tile >> 1) * 8;
                ldmx4(a[mf], &As[s * ASTG + mrow * SAP + kcol]);
            }
            #pragma unroll
            for (int nf = 0; nf < 4; nf++) {
                int tile = (lane >> 3) & 1, rr = lane & 7;
                int nrow = wn * 32 + nf * 8 + rr;
                int kcol = ks + tile * 8;
                uint32_t addr = (uint32_t)__cvta_generic_to_shared(&Bs[s * ASTG + nrow * SAP + kcol]);
                asm volatile("ldmatrix.sync.aligned.m8n8.x2.shared.b16 {%0,%1}, [%2];"
                             : "=r"(b[nf][0]), "=r"(b[nf][1]) : "r"(addr));
            }
            #pragma unroll
            for (int mf = 0; mf < 4; mf++)
                #pragma unroll
                for (int nf = 0; nf < 4; nf++)
                    mma16816(acc[mf][nf], a[mf], b[nf][0], b[nf][1]);
        }
    }

    #pragma unroll
    for (int mf = 0; mf < 4; mf++) {
        int r0 = bm + wm * 64 + mf * 16 + g;
        #pragma unroll
        for (int nf = 0; nf < 4; nf++) {
            int c0 = bn + wn * 32 + nf * 8 + t2;
            *reinterpret_cast<float2*>(&C[(size_t)r0 * N + c0]) =
                make_float2(acc[mf][nf][0], acc[mf][nf][1]);
            *reinterpret_cast<float2*>(&C[(size_t)(r0 + 8) * N + c0]) =
                make_float2(acc[mf][nf][2], acc[mf][nf][3]);
        }
    }
}

// ---------------- RoPE + transpose + fp16 split (frozen) ----------------
__global__ void rope_kernel(const float* __restrict__ qkv,
                            float* __restrict__ kout, float* __restrict__ vout,
                            __half* __restrict__ qsp, __half* __restrict__ ksp,
                            __half* __restrict__ vt) {
    int bt = blockIdx.x;
    int b = bt >> 11, t = bt & (T_ - 1);
    int tid = threadIdx.x;
    const float* row = qkv + (size_t)bt * 1280;
    {
        int h = tid >> 5, m = tid & 31;
        float inv = powf(10000.0f, -(float)m / 32.0f);
        float ang = (float)t * inv;
        float s, c; sincosf(ang, &s, &c);
        float x0 = row[h * DH + m];
        float x1 = row[h * DH + m + 32];
        float r0 = (x0 * c - x1 * s) * 0.125f;
        float r1 = (x1 * c + x0 * s) * 0.125f;
        size_t base = ((size_t)(b * NH + h) * T_ + t) * 128;
        __half h0 = __float2half_rn(r0);
        __half h1 = __float2half_rn(r1);
        qsp[base + m]       = h0;
        qsp[base + m + 32]  = h1;
        qsp[base + 64 + m]  = __float2half_rn(r0 - __half2float(h0));
        qsp[base + 96 + m]  = __float2half_rn(r1 - __half2float(h1));
    }
    if (tid < NKV * 32) {
        int h = tid >> 5, m = tid & 31;
        float inv = powf(10000.0f, -(float)m / 32.0f);
        float ang = (float)t * inv;
        float s, c; sincosf(ang, &s, &c);
        float x0 = row[768 + h * DH + m];
        float x1 = row[768 + h * DH + m + 32];
        float r0 = x0 * c - x1 * s;
        float r1 = x1 * c + x0 * s;
        size_t fbase = ((size_t)(b * NKV + h) * T_ + t) * DH;
        kout[fbase + m]      = r0;
        kout[fbase + m + 32] = r1;
        ksp[fbase + m]       = __float2half_rn(r0);
        ksp[fbase + m + 32]  = __float2half_rn(r1);
    }
    if (tid < NKV * DH) {
        int h = tid >> 6, d = tid & 63;
        float v = row[1024 + tid];
        vout[((size_t)(b * NKV + h) * T_ + t) * DH + d] = v;
        vt[((size_t)(b * NKV + h) * DH + d) * T_ + t] = __float2half_rn(v);
    }
}

// ---------------- fp16 tensor-core windowed flash attention, 64-key chunks ----------------
// block = (b, h, 64-query tile); 4 warps x 16 q-rows; 64-key chunks double-buffered.
// Full-chunk fast path skips mask ALU when the chunk is warp-uniformly allowed.
#define QSTR 136
#define KSTR 72
#define VSTR 72
#define CH 64

__global__ void attn_mma_kernel(const __half* __restrict__ qsp,
                                const __half* __restrict__ ksp,
                                const __half* __restrict__ vt,
                                __half* __restrict__ ax) {
    extern __shared__ __align__(16) __half sm[];
    __half* Qs = sm;                       // [64][QSTR]
    __half* Ks = Qs + 64 * QSTR;           // [2][64][KSTR]
    __half* Vs = Ks + 2 * 64 * KSTR;       // [2][64][VSTR]   V^T: d rows x t cols

    int blk = blockIdx.x;
    int qt = 31 - blk / (B_ * NH);         // big tiles first
    int rest = blk % (B_ * NH);
    int h = rest % NH, b = rest / NH;
    int kvh = h / (NH / NKV);
    int qbase = qt * 64;

    int tid = threadIdx.x, w = tid >> 5, lane = tid & 31;
    int g = lane >> 2, t2 = (lane & 3) * 2;

    const __half* Qg = qsp + ((size_t)(b * NH + h) * T_ + qbase) * 128;
    const __half* Kg = ksp + (size_t)(b * NKV + kvh) * T_ * DH;
    const __half* Vg = vt + (size_t)(b * NKV + kvh) * DH * T_;

    // chunk schedule: chunk 0 = keys [0,64) (global); then window chunks of 64
    int wlo_key = qbase - (WIN - 1);
    if (wlo_key < GLB) wlo_key = GLB;
    wlo_key &= ~(CH - 1);
    int nch = 1 + ((qbase + 64 - wlo_key) >> 6 > 0 ? (qbase + 64 - wlo_key) >> 6 : 0);

    // Q tile 64 x 128
    #pragma unroll
    for (int i = 0; i < 8; i++) {
        int u = tid + i * 128;
        int r = u >> 4, c = u & 15;
        cp16(&Qs[r * QSTR + c * 8], Qg + (size_t)r * 128 + c * 8);
    }

    auto load_chunk = [&](int buf, int c0) {
        __half* Kb = Ks + buf * 64 * KSTR;
        __half* Vb = Vs + buf * 64 * VSTR;
        #pragma unroll
        for (int i = 0; i < 4; i++) {            // K: 64 rows x 8 units
            int u = tid + i * 128;
            int r = u >> 3, c = u & 7;
            cp16(&Kb[r * KSTR + c * 8], Kg + (size_t)(c0 + r) * DH + c * 8);
        }
        #pragma unroll
        for (int i = 0; i < 4; i++) {            // V^T: 64 d-rows x 8 units (64 t-cols)
            int u = tid + i * 128;
            int r = u >> 3, c = u & 7;
            cp16(&Vb[r * VSTR + c * 8], Vg + (size_t)r * T_ + c0 + c * 8);
        }
    };

    load_chunk(0, 0);
    cp_commit();

    float O[8][4];
    #pragma unroll
    for (int nf = 0; nf < 8; nf++)
        #pragma unroll
        for (int r = 0; r < 4; r++) O[nf][r] = 0.f;
    float mrow[2] = {-1e30f, -1e30f};
    float lrow[2] = {0.f, 0.f};
    int irow0 = qbase + w * 16 + g;
    int wminr = qbase + w * 16;              // warp's min query row
    int wmaxr = wminr + 15;

    for (int idx = 0; idx < nch; idx++) {
        int buf = idx & 1;
        int c0 = (idx == 0) ? 0 : wlo_key + (idx - 1) * CH;
        if (idx + 1 < nch) {
            int c0n = (idx == 0) ? wlo_key : c0 + CH;
            load_chunk(buf ^ 1, c0n);
            cp_commit();
            asm volatile("cp.async.wait_group 1;\n");
        } else {
            asm volatile("cp.async.wait_group 0;\n");
        }
        __syncthreads();

        const __half* Kb = Ks + buf * 64 * KSTR;
        const __half* Vb = Vs + buf * 64 * VSTR;

        // ---- S = Q'K^T : [16 x 64] per warp ----
        float sc[8][4];
        #pragma unroll
        for (int nf = 0; nf < 8; nf++)
            #pragma unroll
            for (int r = 0; r < 4; r++) sc[nf][r] = 0.f;

        #pragma unroll
        for (int kb = 0; kb < 4; kb++) {
            uint32_t aA[4], aB[4];
            {
                int tile = lane >> 3, rr = lane & 7;
                int mrw = w * 16 + (tile & 1) * 8 + rr;
                ldmx4(aA, &Qs[mrw * QSTR + kb * 32 + (tile >> 1) * 8]);
                ldmx4(aB, &Qs[mrw * QSTR + kb * 32 + 16 + (tile >> 1) * 8]);
            }
            int kk = (kb & 1) * 32;
            #pragma unroll
            for (int nf = 0; nf < 8; nf++) {
                uint32_t bb[4];
                ldmx4(bb, &Kb[(nf * 8 + (lane & 7)) * KSTR + kk + (lane >> 3) * 8]);
                mma16816(sc[nf], aA, bb[0], bb[1]);
                mma16816(sc[nf], aB, bb[2], bb[3]);
            }
        }

        // ---- mask (skipped on fully-allowed chunks) + online softmax ----
        bool full = (c0 + CH - 1 <= wminr) &&
                    ((c0 >= wmaxr - WIN + 1) || (c0 + CH - 1 < GLB));
        float cmax[2] = {-1e30f, -1e30f};
        if (full) {
            #pragma unroll
            for (int nf = 0; nf < 8; nf++)
                #pragma unroll
                for (int r = 0; r < 4; r++)
                    cmax[r >> 1] = fmaxf(cmax[r >> 1], sc[nf][r]);
        } else {
            #pragma unroll
            for (int nf = 0; nf < 8; nf++)
                #pragma unroll
                for (int r = 0; r < 4; r++) {
                    int j = c0 + nf * 8 + t2 + (r & 1);
                    int i = irow0 + (r >> 1) * 8;
                    bool a = (j <= i) && ((j > i - WIN) || (j < GLB) || (i < GLB));
                    float s = a ? sc[nf][r] : -1e30f;
                    sc[nf][r] = s;
                    cmax[r >> 1] = fmaxf(cmax[r >> 1], s);
                }
        }
        #pragma unroll
        for (int r2 = 0; r2 < 2; r2++) {
            cmax[r2] = fmaxf(cmax[r2], __shfl_xor_sync(0xffffffffu, cmax[r2], 1));
            cmax[r2] = fmaxf(cmax[r2], __shfl_xor_sync(0xffffffffu, cmax[r2], 2));
        }
        float scl[2], rsum[2] = {0.f, 0.f};
        #pragma unroll
        for (int r2 = 0; r2 < 2; r2++) {
            float mn = fmaxf(mrow[r2], cmax[r2]);
            scl[r2] = __expf(mrow[r2] - mn);
            mrow[r2] = mn;
        }
        #pragma unroll
        for (int nf = 0; nf < 8; nf++)
            #pragma unroll
            for (int r = 0; r < 4; r++) {
                float s = sc[nf][r];
                float p = (s > -5e29f) ? __expf(s - mrow[r >> 1]) : 0.f;
                sc[nf][r] = p;
                rsum[r >> 1] += p;
            }
        #pragma unroll
        for (int r2 = 0; r2 < 2; r2++) {
            rsum[r2] += __shfl_xor_sync(0xffffffffu, rsum[r2], 1);
            rsum[r2] += __shfl_xor_sync(0xffffffffu, rsum[r2], 2);
            lrow[r2] = lrow[r2] * scl[r2] + rsum[r2];
        }
        #pragma unroll
        for (int nf = 0; nf < 8; nf++) {
            O[nf][0] *= scl[0]; O[nf][1] *= scl[0];
            O[nf][2] *= scl[1]; O[nf][3] *= scl[1];
        }

        // ---- P fragments (fp16 hi/lo, exact split); frag f covers keys f*16..f*16+16 ----
        uint32_t Ph[4][4], Pl[4][4];
        #pragma unroll
        for (int f = 0; f < 4; f++) {
            float p0 = sc[2*f][0],   p1 = sc[2*f][1],   p2 = sc[2*f][2],   p3 = sc[2*f][3];
            float q0 = sc[2*f+1][0], q1 = sc[2*f+1][1], q2 = sc[2*f+1][2], q3 = sc[2*f+1][3];
            Ph[f][0] = packh2(p0, p1); Ph[f][1] = packh2(p2, p3);
            Ph[f][2] = packh2(q0, q1); Ph[f][3] = packh2(q2, q3);
            Pl[f][0] = packh2(p0 - __half2float(__float2half_rn(p0)),
                              p1 - __half2float(__float2half_rn(p1)));
            Pl[f][1] = packh2(p2 - __half2float(__float2half_rn(p2)),
                              p3 - __half2float(__float2half_rn(p3)));
            Pl[f][2] = packh2(q0 - __half2float(__float2half_rn(q0)),
                              q1 - __half2float(__float2half_rn(q1)));
            Pl[f][3] = packh2(q2 - __half2float(__float2half_rn(q2)),
                              q3 - __half2float(__float2half_rn(q3)));
        }

        // ---- O += P V ----
        #pragma unroll
        for (int nf = 0; nf < 8; nf++) {
            uint32_t va[4], vb[4];
            const __half* vrow = &Vb[(nf * 8 + (lane & 7)) * VSTR + (lane >> 3) * 8];
            ldmx4(va, vrow);
            ldmx4(vb, vrow + 32);
            mma16816(O[nf], Ph[0], va[0], va[1]);
            mma16816(O[nf], Ph[1], va[2], va[3]);
            mma16816(O[nf], Ph[2], vb[0], vb[1]);
            mma16816(O[nf], Ph[3], vb[2], vb[3]);
            mma16816(O[nf], Pl[0], va[0], va[1]);
            mma16816(O[nf], Pl[1], va[2], va[3]);
            mma16816(O[nf], Pl[2], vb[0], vb[1]);
            mma16816(O[nf], Pl[3], vb[2], vb[3]);
        }
        __syncthreads();
    }

    // ---- epilogue: normalize + fp16 hi/lo split directly into gemm2's A ----
    float inv0 = 1.0f / lrow[0], inv1 = 1.0f / lrow[1];
    size_t r0g = (size_t)b * T_ + irow0;
    size_t r1g = r0g + 8;
    #pragma unroll
    for (int nf = 0; nf < 8; nf++) {
        int col = h * DH + nf * 8 + t2;
        float v00 = O[nf][0] * inv0, v01 = O[nf][1] * inv0;
        float v10 = O[nf][2] * inv1, v11 = O[nf][3] * inv1;
        __half h00 = __float2half_rn(v00), h01 = __float2half_rn(v01);
        __half h10 = __float2half_rn(v10), h11 = __float2half_rn(v11);
        *reinterpret_cast<uint32_t*>(&ax[r0g * K2 + col]) = packh2(v00, v01);
        *reinterpret_cast<uint32_t*>(&ax[r1g * K2 + col]) = packh2(v10, v11);
        *reinterpret_cast<uint32_t*>(&ax[r0g * K2 + KW + col]) =
            packh2(v00 - __half2float(h00), v01 - __half2float(h01));
        *reinterpret_cast<uint32_t*>(&ax[r1g * K2 + KW + col]) =
            packh2(v10 - __half2float(h10), v11 - __half2float(h11));
    }
}

extern "C" void kernel_launch(void* const* d_in, const int* in_sizes, int n_in,
                              void* d_out, int out_size) {
    const float* x  = (const float*)d_in[0];
    const float* wq = (const float*)d_in[1];
    const float* wk = (const float*)d_in[2];
    const float* wv = (const float*)d_in[3];
    const float* wo = (const float*)d_in[4];
    float* out = (float*)d_out;

    __half *ax, *wt1, *wt2, *qsp, *ksp, *vt;
    float *qkv, *kr, *vr;
    cudaGetSymbolAddress((void**)&ax,  g_ax);
    cudaGetSymbolAddress((void**)&wt1, g_wt1);
    cudaGetSymbolAddress((void**)&wt2, g_wt2);
    cudaGetSymbolAddress((void**)&qkv, g_qkv);
    cudaGetSymbolAddress((void**)&kr,  g_kr);
    cudaGetSymbolAddress((void**)&vr,  g_vr);
    cudaGetSymbolAddress((void**)&qsp, g_qsp);
    cudaGetSymbolAddress((void**)&ksp, g_ksp);
    cudaGetSymbolAddress((void**)&vt,  g_vt);

    const int out_elems = B_ * T_ * DM;
    const int kv_elems  = B_ * NKV * T_ * DH;
    float* kout = kr; float* vout = vr;
    if (out_size >= out_elems + 2 * kv_elems) {
        kout = out + out_elems;
        vout = out + out_elems + kv_elems;
    }

    const int gemm_smem = 6 * ASTG * 2;                                    // 110592 B
    cudaFuncSetAttribute(gemm_fp16_kernel, cudaFuncAttributeMaxDynamicSharedMemorySize, gemm_smem);
    const int attn_smem = (64 * QSTR + 2 * 64 * KSTR + 2 * 64 * VSTR) * 2; // 54272 B
    cudaFuncSetAttribute(attn_mma_kernel, cudaFuncAttributeMaxDynamicSharedMemorySize, attn_smem);

    const int prep_total = N_ACT + N_W1 + N_W2;
    prep_kernel<<<(prep_total + 255)/256, 256>>>(x, wq, wk, wv, wo, ax, wt1, wt2);

    gemm_fp16_kernel<<<dim3(1280/BN, MROWS/BM), 256, gemm_smem>>>(ax, wt1, qkv, 1280);
    rope_kernel<<<MROWS, 384>>>(qkv, kout, vout, qsp, ksp, vt);
    attn_mma_kernel<<<B_ * NH * (T_/64), 128, attn_smem>>>(qsp, ksp, vt, ax);
    gemm_fp16_kernel<<<dim3(DM/BN, MROWS/BM), 256, gemm_smem>>>(ax, wt2, out, DM);
}

// round 13
// speedup vs baseline: 5.4943x; 1.0304x over previous
#include <cuda_runtime.h>
#include <cuda_fp16.h>
#include <stdint.h>
#include <cstdint>
#include <math.h>

#define B_ 2
#define T_ 2048
#define DM 768
#define NH 12
#define NKV 4
#define DH 64
#define WIN 512
#define GLB 64
#define MROWS (B_*T_)          // 4096
#define K2 1536                // stacked-K (2x) for fp16 hi/lo trick
#define KW 768                 // weight K (single copy; loader wraps)

// ---------------- scratch ----------------
__device__ __half g_ax[(size_t)MROWS*K2];        // split activations [4096][hi768|lo768]
__device__ __half g_wt1[(size_t)1280*KW];        // fp16 transposed [wq|wk|wv] : [1280][768]
__device__ __half g_wt2[(size_t)DM*KW];          // fp16 transposed wo : [768][768]
__device__ float  g_qkv[(size_t)MROWS*1280];     // fused qkv proj out (fp32)
__device__ float  g_kr[(size_t)B_*NKV*T_*DH];    // fallback k out
__device__ float  g_vr[(size_t)B_*NKV*T_*DH];    // fallback v out
__device__ __half g_qsp[(size_t)B_*NH*T_*128];   // Q' [b,h,t][hi64|lo64], pre-scaled 1/8
__device__ __half g_ksp[(size_t)B_*NKV*T_*DH];   // K fp16 [b,kvh,t][64]
__device__ __half g_vt[(size_t)B_*NKV*DH*T_];    // V^T fp16 [b,kvh,d][t]

// ---------------- helpers ----------------
__device__ __forceinline__ void cp16(void* smem, const void* gmem) {
    uint32_t s = (uint32_t)__cvta_generic_to_shared(smem);
    asm volatile("cp.async.cg.shared.global [%0], [%1], 16;\n" :: "r"(s), "l"(gmem));
}
__device__ __forceinline__ void cp_commit() { asm volatile("cp.async.commit_group;\n"); }

__device__ __forceinline__ void ldmx4(uint32_t* r, const void* p) {
    uint32_t a = (uint32_t)__cvta_generic_to_shared(p);
    asm volatile("ldmatrix.sync.aligned.m8n8.x4.shared.b16 {%0,%1,%2,%3}, [%4];"
                 : "=r"(r[0]), "=r"(r[1]), "=r"(r[2]), "=r"(r[3]) : "r"(a));
}
__device__ __forceinline__ void mma16816(float* d, const uint32_t* a, uint32_t b0, uint32_t b1) {
    asm volatile("mma.sync.aligned.m16n8k16.row.col.f32.f16.f16.f32 "
                 "{%0,%1,%2,%3}, {%4,%5,%6,%7}, {%8,%9}, {%0,%1,%2,%3};"
                 : "+f"(d[0]), "+f"(d[1]), "+f"(d[2]), "+f"(d[3])
                 : "r"(a[0]), "r"(a[1]), "r"(a[2]), "r"(a[3]), "r"(b0), "r"(b1));
}
__device__ __forceinline__ uint32_t packh2(float a, float b) {
    __half2 h = __floats2half2_rn(a, b);
    return *reinterpret_cast<uint32_t*>(&h);
}

// ---------------- fused prep: activation split + weight transposes ----------------
#define N_ACT (MROWS*DM)          // 3145728
#define N_W1  (1280*DM)           // 983040
#define N_W2  (DM*DM)             // 589824
__global__ void prep_kernel(const float* __restrict__ x,
                            const float* __restrict__ wq, const float* __restrict__ wk,
                            const float* __restrict__ wv, const float* __restrict__ wo,
                            __half* __restrict__ ax, __half* __restrict__ wt1,
                            __half* __restrict__ wt2) {
    int idx = blockIdx.x * blockDim.x + threadIdx.x;
    if (idx < N_ACT) {
        int r = idx / DM, c = idx % DM;
        float v = x[idx];
        __half hi = __float2half_rn(v);
        __half lo = __float2half_rn(v - __half2float(hi));
        size_t base = (size_t)r * K2;
        ax[base + c] = hi;
        ax[base + c + KW] = lo;
    } else if (idx < N_ACT + N_W1) {
        int e = idx - N_ACT;
        int n = e / DM, k = e % DM;
        float v;
        if (n < 768)       v = wq[(size_t)k * 768 + n];
        else if (n < 1024) v = wk[(size_t)k * 256 + (n - 768)];
        else               v = wv[(size_t)k * 256 + (n - 1024)];
        wt1[(size_t)n * KW + k] = __float2half_rn(v);
    } else if (idx < N_ACT + N_W1 + N_W2) {
        int e = idx - N_ACT - N_W1;
        int n = e / DM, k = e % DM;
        wt2[(size_t)n * KW + k] = __float2half_rn(wo[(size_t)k * DM + n]);
    }
}

// ---------------- fp16 tensor-core GEMM: 4 warps, 64x64 warp tiles ----------------
// C[M,N] = A'[M,1536] @ ([W|W])^T. B loader wraps k at 768.
// 128x128 CTA tile, BK=64, 2-stage cp.async ring (73.7KB smem -> 3 CTAs/SM, one wave).
#define BM 128
#define BN 128
#define BK 64
#define SAP 72
#define ASTG (BM*SAP)          // halves per stage per operand (18432 B)
#define KT2 (K2/BK)            // 24

__global__ void __launch_bounds__(128, 3)
gemm_fp16_kernel(const __half* __restrict__ A, const __half* __restrict__ Bt,
                 float* __restrict__ C, int N) {
    extern __shared__ __align__(16) __half smem_g[];
    __half* As = smem_g;               // [2][ASTG]
    __half* Bs = smem_g + 2 * ASTG;    // [2][ASTG]

    int tid = threadIdx.x;
    int warp = tid >> 5, lane = tid & 31;
    int wm = warp & 1;                 // 2 warps along M (64 rows)
    int wn = warp >> 1;                // 2 warps along N (64 cols)
    int bm = blockIdx.y * BM, bn = blockIdx.x * BN;
    int g = lane >> 2;
    int t2 = (lane & 3) * 2;

    float acc[4][8][4];
    #pragma unroll
    for (int i = 0; i < 4; i++)
        #pragma unroll
        for (int j = 0; j < 8; j++)
            #pragma unroll
            for (int r = 0; r < 4; r++) acc[i][j][r] = 0.f;

    auto load_stage = [&](int st, int kt) {
        int koff = kt * BK;
        int bko = koff < KW ? koff : koff - KW;
        #pragma unroll
        for (int i = 0; i < 8; i++) {              // A: 128 rows x 8 units
            int u = tid + i * 128;
            int row = u >> 3, c8 = u & 7;
            cp16(&As[st * ASTG + row * SAP + c8 * 8],
                 A + (size_t)(bm + row) * K2 + koff + c8 * 8);
        }
        #pragma unroll
        for (int i = 0; i < 8; i++) {              // B: 128 rows x 8 units
            int u = tid + i * 128;
            int row = u >> 3, c8 = u & 7;
            cp16(&Bs[st * ASTG + row * SAP + c8 * 8],
                 Bt + (size_t)(bn + row) * KW + bko + c8 * 8);
        }
        cp_commit();
    };

    load_stage(0, 0);
    load_stage(1, 1);

    for (int kt = 0; kt < KT2; kt++) {
        int s = kt & 1;
        if (kt == KT2 - 1) asm volatile("cp.async.wait_group 0;\n");
        else               asm volatile("cp.async.wait_group 1;\n");
        __syncthreads();

        #pragma unroll
        for (int ks = 0; ks < BK; ks += 16) {
            uint32_t a[4][4];
            #pragma unroll
            for (int mf = 0; mf < 4; mf++) {
                int tile = lane >> 3, rr = lane & 7;
                int mrow = wm * 64 + mf * 16 + (tile & 1) * 8 + rr;
                int kcol = ks + (tile >> 1) * 8;
                ldmx4(a[mf], &As[s * ASTG + mrow * SAP + kcol]);
            }
            #pragma unroll
            for (int nfp = 0; nfp < 4; nfp++) {    // B: paired x4 -> frags for nf=2*nfp, 2*nfp+1
                uint32_t bb[4];
                int tile = lane >> 3, rr = lane & 7;
                int nrow = wn * 64 + nfp * 16 + (tile >> 1) * 8 + rr;
                int kcol = ks + (tile & 1) * 8;
                ldmx4(bb, &Bs[s * ASTG + nrow * SAP + kcol]);
                #pragma unroll
                for (int mf = 0; mf < 4; mf++) {
                    mma16816(acc[mf][2*nfp],   a[mf], bb[0], bb[1]);
                    mma16816(acc[mf][2*nfp+1], a[mf], bb[2], bb[3]);
                }
            }
        }
        __syncthreads();                           // all reads of stage s done
        if (kt + 2 < KT2) load_stage(s, kt + 2);
    }

    #pragma unroll
    for (int mf = 0; mf < 4; mf++) {
        int r0 = bm + wm * 64 + mf * 16 + g;
        #pragma unroll
        for (int nf = 0; nf < 8; nf++) {
            int c0 = bn + wn * 64 + nf * 8 + t2;
            *reinterpret_cast<float2*>(&C[(size_t)r0 * N + c0]) =
                make_float2(acc[mf][nf][0], acc[mf][nf][1]);
            *reinterpret_cast<float2*>(&C[(size_t)(r0 + 8) * N + c0]) =
                make_float2(acc[mf][nf][2], acc[mf][nf][3]);
        }
    }
}

// ---------------- RoPE + transpose + fp16 split (frozen) ----------------
__global__ void rope_kernel(const float* __restrict__ qkv,
                            float* __restrict__ kout, float* __restrict__ vout,
                            __half* __restrict__ qsp, __half* __restrict__ ksp,
                            __half* __restrict__ vt) {
    int bt = blockIdx.x;
    int b = bt >> 11, t = bt & (T_ - 1);
    int tid = threadIdx.x;
    const float* row = qkv + (size_t)bt * 1280;
    {
        int h = tid >> 5, m = tid & 31;
        float inv = powf(10000.0f, -(float)m / 32.0f);
        float ang = (float)t * inv;
        float s, c; sincosf(ang, &s, &c);
        float x0 = row[h * DH + m];
        float x1 = row[h * DH + m + 32];
        float r0 = (x0 * c - x1 * s) * 0.125f;
        float r1 = (x1 * c + x0 * s) * 0.125f;
        size_t base = ((size_t)(b * NH + h) * T_ + t) * 128;
        __half h0 = __float2half_rn(r0);
        __half h1 = __float2half_rn(r1);
        qsp[base + m]       = h0;
        qsp[base + m + 32]  = h1;
        qsp[base + 64 + m]  = __float2half_rn(r0 - __half2float(h0));
        qsp[base + 96 + m]  = __float2half_rn(r1 - __half2float(h1));
    }
    if (tid < NKV * 32) {
        int h = tid >> 5, m = tid & 31;
        float inv = powf(10000.0f, -(float)m / 32.0f);
        float ang = (float)t * inv;
        float s, c; sincosf(ang, &s, &c);
        float x0 = row[768 + h * DH + m];
        float x1 = row[768 + h * DH + m + 32];
        float r0 = x0 * c - x1 * s;
        float r1 = x1 * c + x0 * s;
        size_t fbase = ((size_t)(b * NKV + h) * T_ + t) * DH;
        kout[fbase + m]      = r0;
        kout[fbase + m + 32] = r1;
        ksp[fbase + m]       = __float2half_rn(r0);
        ksp[fbase + m + 32]  = __float2half_rn(r1);
    }
    if (tid < NKV * DH) {
        int h = tid >> 6, d = tid & 63;
        float v = row[1024 + tid];
        vout[((size_t)(b * NKV + h) * T_ + t) * DH + d] = v;
        vt[((size_t)(b * NKV + h) * DH + d) * T_ + t] = __float2half_rn(v);
    }
}

// ---------------- fp16 tensor-core windowed flash attention, 64-key chunks ----------------
#define QSTR 136
#define KSTR 72
#define VSTR 72
#define CH 64

__global__ void __launch_bounds__(128, 4)
attn_mma_kernel(const __half* __restrict__ qsp,
                const __half* __restrict__ ksp,
                const __half* __restrict__ vt,
                __half* __restrict__ ax) {
    extern __shared__ __align__(16) __half sm[];
    __half* Qs = sm;                       // [64][QSTR]
    __half* Ks = Qs + 64 * QSTR;           // [2][64][KSTR]
    __half* Vs = Ks + 2 * 64 * KSTR;       // [2][64][VSTR]   V^T: d rows x t cols

    int blk = blockIdx.x;
    int qt = 31 - blk / (B_ * NH);         // big tiles first
    int rest = blk % (B_ * NH);
    int h = rest % NH, b = rest / NH;
    int kvh = h / (NH / NKV);
    int qbase = qt * 64;

    int tid = threadIdx.x, w = tid >> 5, lane = tid & 31;
    int g = lane >> 2, t2 = (lane & 3) * 2;

    const __half* Qg = qsp + ((size_t)(b * NH + h) * T_ + qbase) * 128;
    const __half* Kg = ksp + (size_t)(b * NKV + kvh) * T_ * DH;
    const __half* Vg = vt + (size_t)(b * NKV + kvh) * DH * T_;

    int wlo_key = qbase - (WIN - 1);
    if (wlo_key < GLB) wlo_key = GLB;
    wlo_key &= ~(CH - 1);
    int nch = 1 + ((qbase + 64 - wlo_key) >> 6 > 0 ? (qbase + 64 - wlo_key) >> 6 : 0);

    #pragma unroll
    for (int i = 0; i < 8; i++) {
        int u = tid + i * 128;
        int r = u >> 4, c = u & 15;
        cp16(&Qs[r * QSTR + c * 8], Qg + (size_t)r * 128 + c * 8);
    }

    auto load_chunk = [&](int buf, int c0) {
        __half* Kb = Ks + buf * 64 * KSTR;
        __half* Vb = Vs + buf * 64 * VSTR;
        #pragma unroll
        for (int i = 0; i < 4; i++) {
            int u = tid + i * 128;
            int r = u >> 3, c = u & 7;
            cp16(&Kb[r * KSTR + c * 8], Kg + (size_t)(c0 + r) * DH + c * 8);
        }
        #pragma unroll
        for (int i = 0; i < 4; i++) {
            int u = tid + i * 128;
            int r = u >> 3, c = u & 7;
            cp16(&Vb[r * VSTR + c * 8], Vg + (size_t)r * T_ + c0 + c * 8);
        }
    };

    load_chunk(0, 0);
    cp_commit();

    float O[8][4];
    #pragma unroll
    for (int nf = 0; nf < 8; nf++)
        #pragma unroll
        for (int r = 0; r < 4; r++) O[nf][r] = 0.f;
    float mrow[2] = {-1e30f, -1e30f};
    float lrow[2] = {0.f, 0.f};
    int irow0 = qbase + w * 16 + g;
    int wminr = qbase + w * 16;
    int wmaxr = wminr + 15;

    for (int idx = 0; idx < nch; idx++) {
        int buf = idx & 1;
        int c0 = (idx == 0) ? 0 : wlo_key + (idx - 1) * CH;
        if (idx + 1 < nch) {
            int c0n = (idx == 0) ? wlo_key : c0 + CH;
            load_chunk(buf ^ 1, c0n);
            cp_commit();
            asm volatile("cp.async.wait_group 1;\n");
        } else {
            asm volatile("cp.async.wait_group 0;\n");
        }
        __syncthreads();

        const __half* Kb = Ks + buf * 64 * KSTR;
        const __half* Vb = Vs + buf * 64 * VSTR;

        float sc[8][4];
        #pragma unroll
        for (int nf = 0; nf < 8; nf++)
            #pragma unroll
            for (int r = 0; r < 4; r++) sc[nf][r] = 0.f;

        #pragma unroll
        for (int kb = 0; kb < 4; kb++) {
            uint32_t aA[4], aB[4];
            {
                int tile = lane >> 3, rr = lane & 7;
                int mrw = w * 16 + (tile & 1) * 8 + rr;
                ldmx4(aA, &Qs[mrw * QSTR + kb * 32 + (tile >> 1) * 8]);
                ldmx4(aB, &Qs[mrw * QSTR + kb * 32 + 16 + (tile >> 1) * 8]);
            }
            int kk = (kb & 1) * 32;
            #pragma unroll
            for (int nf = 0; nf < 8; nf++) {
                uint32_t bb[4];
                ldmx4(bb, &Kb[(nf * 8 + (lane & 7)) * KSTR + kk + (lane >> 3) * 8]);
                mma16816(sc[nf], aA, bb[0], bb[1]);
                mma16816(sc[nf], aB, bb[2], bb[3]);
            }
        }

        bool full = (c0 + CH - 1 <= wminr) &&
                    ((c0 >= wmaxr - WIN + 1) || (c0 + CH - 1 < GLB));
        float cmax[2] = {-1e30f, -1e30f};
        if (full) {
            #pragma unroll
            for (int nf = 0; nf < 8; nf++)
                #pragma unroll
                for (int r = 0; r < 4; r++)
                    cmax[r >> 1] = fmaxf(cmax[r >> 1], sc[nf][r]);
        } else {
            #pragma unroll
            for (int nf = 0; nf < 8; nf++)
                #pragma unroll
                for (int r = 0; r < 4; r++) {
                    int j = c0 + nf * 8 + t2 + (r & 1);
                    int i = irow0 + (r >> 1) * 8;
                    bool a = (j <= i) && ((j > i - WIN) || (j < GLB) || (i < GLB));
                    float s = a ? sc[nf][r] : -1e30f;
                    sc[nf][r] = s;
                    cmax[r >> 1] = fmaxf(cmax[r >> 1], s);
                }
        }
        #pragma unroll
        for (int r2 = 0; r2 < 2; r2++) {
            cmax[r2] = fmaxf(cmax[r2], __shfl_xor_sync(0xffffffffu, cmax[r2], 1));
            cmax[r2] = fmaxf(cmax[r2], __shfl_xor_sync(0xffffffffu, cmax[r2], 2));
        }
        float scl[2], rsum[2] = {0.f, 0.f};
        #pragma unroll
        for (int r2 = 0; r2 < 2; r2++) {
            float mn = fmaxf(mrow[r2], cmax[r2]);
            scl[r2] = __expf(mrow[r2] - mn);
            mrow[r2] = mn;
        }
        #pragma unroll
        for (int nf = 0; nf < 8; nf++)
            #pragma unroll
            for (int r = 0; r < 4; r++) {
                float s = sc[nf][r];
                float p = (s > -5e29f) ? __expf(s - mrow[r >> 1]) : 0.f;
                sc[nf][r] = p;
                rsum[r >> 1] += p;
            }
        #pragma unroll
        for (int r2 = 0; r2 < 2; r2++) {
            rsum[r2] += __shfl_xor_sync(0xffffffffu, rsum[r2], 1);
            rsum[r2] += __shfl_xor_sync(0xffffffffu, rsum[r2], 2);
            lrow[r2] = lrow[r2] * scl[r2] + rsum[r2];
        }
        #pragma unroll
        for (int nf = 0; nf < 8; nf++) {
            O[nf][0] *= scl[0]; O[nf][1] *= scl[0];
            O[nf][2] *= scl[1]; O[nf][3] *= scl[1];
        }

        uint32_t Ph[4][4], Pl[4][4];
        #pragma unroll
        for (int f = 0; f < 4; f++) {
            float p0 = sc[2*f][0],   p1 = sc[2*f][1],   p2 = sc[2*f][2],   p3 = sc[2*f][3];
            float q0 = sc[2*f+1][0], q1 = sc[2*f+1][1], q2 = sc[2*f+1][2], q3 = sc[2*f+1][3];
            Ph[f][0] = packh2(p0, p1); Ph[f][1] = packh2(p2, p3);
            Ph[f][2] = packh2(q0, q1); Ph[f][3] = packh2(q2, q3);
            Pl[f][0] = packh2(p0 - __half2float(__float2half_rn(p0)),
                              p1 - __half2float(__float2half_rn(p1)));
            Pl[f][1] = packh2(p2 - __half2float(__float2half_rn(p2)),
                              p3 - __half2float(__float2half_rn(p3)));
            Pl[f][2] = packh2(q0 - __half2float(__float2half_rn(q0)),
                              q1 - __half2float(__float2half_rn(q1)));
            Pl[f][3] = packh2(q2 - __half2float(__float2half_rn(q2)),
                              q3 - __half2float(__float2half_rn(q3)));
        }

        #pragma unroll
        for (int nf = 0; nf < 8; nf++) {
            uint32_t va[4], vb[4];
            const __half* vrow = &Vb[(nf * 8 + (lane & 7)) * VSTR + (lane >> 3) * 8];
            ldmx4(va, vrow);
            ldmx4(vb, vrow + 32);
            mma16816(O[nf], Ph[0], va[0], va[1]);
            mma16816(O[nf], Ph[1], va[2], va[3]);
            mma16816(O[nf], Ph[2], vb[0], vb[1]);
            mma16816(O[nf], Ph[3], vb[2], vb[3]);
            mma16816(O[nf], Pl[0], va[0], va[1]);
            mma16816(O[nf], Pl[1], va[2], va[3]);
            mma16816(O[nf], Pl[2], vb[0], vb[1]);
            mma16816(O[nf], Pl[3], vb[2], vb[3]);
        }
        __syncthreads();
    }

    float inv0 = 1.0f / lrow[0], inv1 = 1.0f / lrow[1];
    size_t r0g = (size_t)b * T_ + irow0;
    size_t r1g = r0g + 8;
    #pragma unroll
    for (int nf = 0; nf < 8; nf++) {
        int col = h * DH + nf * 8 + t2;
        float v00 = O[nf][0] * inv0, v01 = O[nf][1] * inv0;
        float v10 = O[nf][2] * inv1, v11 = O[nf][3] * inv1;
        __half h00 = __float2half_rn(v00), h01 = __float2half_rn(v01);
        __half h10 = __float2half_rn(v10), h11 = __float2half_rn(v11);
        *reinterpret_cast<uint32_t*>(&ax[r0g * K2 + col]) = packh2(v00, v01);
        *reinterpret_cast<uint32_t*>(&ax[r1g * K2 + col]) = packh2(v10, v11);
        *reinterpret_cast<uint32_t*>(&ax[r0g * K2 + KW + col]) =
            packh2(v00 - __half2float(h00), v01 - __half2float(h01));
        *reinterpret_cast<uint32_t*>(&ax[r1g * K2 + KW + col]) =
            packh2(v10 - __half2float(h10), v11 - __half2float(h11));
    }
}

extern "C" void kernel_launch(void* const* d_in, const int* in_sizes, int n_in,
                              void* d_out, int out_size) {
    const float* x  = (const float*)d_in[0];
    const float* wq = (const float*)d_in[1];
    const float* wk = (const float*)d_in[2];
    const float* wv = (const float*)d_in[3];
    const float* wo = (const float*)d_in[4];
    float* out = (float*)d_out;

    __half *ax, *wt1, *wt2, *qsp, *ksp, *vt;
    float *qkv, *kr, *vr;
    cudaGetSymbolAddress((void**)&ax,  g_ax);
    cudaGetSymbolAddress((void**)&wt1, g_wt1);
    cudaGetSymbolAddress((void**)&wt2, g_wt2);
    cudaGetSymbolAddress((void**)&qkv, g_qkv);
    cudaGetSymbolAddress((void**)&kr,  g_kr);
    cudaGetSymbolAddress((void**)&vr,  g_vr);
    cudaGetSymbolAddress((void**)&qsp, g_qsp);
    cudaGetSymbolAddress((void**)&ksp, g_ksp);
    cudaGetSymbolAddress((void**)&vt,  g_vt);

    const int out_elems = B_ * T_ * DM;
    const int kv_elems  = B_ * NKV * T_ * DH;
    float* kout = kr; float* vout = vr;
    if (out_size >= out_elems + 2 * kv_elems) {
        kout = out + out_elems;
        vout = out + out_elems + kv_elems;
    }

    const int gemm_smem = 4 * ASTG * 2;                                    // 73728 B
    cudaFuncSetAttribute(gemm_fp16_kernel, cudaFuncAttributeMaxDynamicSharedMemorySize, gemm_smem);
    const int attn_smem = (64 * QSTR + 2 * 64 * KSTR + 2 * 64 * VSTR) * 2; // 54272 B
    cudaFuncSetAttribute(attn_mma_kernel, cudaFuncAttributeMaxDynamicSharedMemorySize, attn_smem);

    const int prep_total = N_ACT + N_W1 + N_W2;
    prep_kernel<<<(prep_total + 255)/256, 256>>>(x, wq, wk, wv, wo, ax, wt1, wt2);

    gemm_fp16_kernel<<<dim3(1280/BN, MROWS/BM), 128, gemm_smem>>>(ax, wt1, qkv, 1280);
    rope_kernel<<<MROWS, 384>>>(qkv, kout, vout, qsp, ksp, vt);
    attn_mma_kernel<<<B_ * NH * (T_/64), 128, attn_smem>>>(qsp, ksp, vt, ax);
    gemm_fp16_kernel<<<dim3(DM/BN, MROWS/BM), 128, gemm_smem>>>(ax, wt2, out, DM);
}

// round 14
// speedup vs baseline: 6.0400x; 1.0993x over previous
#include <cuda_runtime.h>
#include <cuda_fp16.h>
#include <stdint.h>
#include <cstdint>
#include <math.h>

#define B_ 2
#define T_ 2048
#define DM 768
#define NH 12
#define NKV 4
#define DH 64
#define WIN 512
#define GLB 64
#define MROWS (B_*T_)          // 4096
#define K2 1536                // stacked-K (2x) for fp16 hi/lo trick
#define KW 768                 // weight K (single copy; loader wraps)

// ---------------- scratch ----------------
__device__ __half g_ax[(size_t)MROWS*K2];        // split activations [4096][hi768|lo768]
__device__ __half g_wt1[(size_t)1280*KW];        // fp16 transposed [wq|wk|wv]
__device__ __half g_wt2[(size_t)DM*KW];          // fp16 transposed wo
__device__ float  g_kr[(size_t)B_*NKV*T_*DH];    // fallback k out
__device__ float  g_vr[(size_t)B_*NKV*T_*DH];    // fallback v out
__device__ __half g_qsp[(size_t)B_*NH*T_*128];   // Q' [b,h,t][hi64|lo64], pre-scaled 1/8
__device__ __half g_ksp[(size_t)B_*NKV*T_*DH];   // K fp16 [b,kvh,t][64]
__device__ __half g_vt[(size_t)B_*NKV*DH*T_];    // V^T fp16 [b,kvh,d][t]
__device__ float2 g_ropet[T_*32];                // cos/sin table [t][m]

// ---------------- helpers ----------------
__device__ __forceinline__ void cp16(void* smem, const void* gmem) {
    uint32_t s = (uint32_t)__cvta_generic_to_shared(smem);
    asm volatile("cp.async.cg.shared.global [%0], [%1], 16;\n" :: "r"(s), "l"(gmem));
}
__device__ __forceinline__ void cp_commit() { asm volatile("cp.async.commit_group;\n"); }

__device__ __forceinline__ void ldmx4(uint32_t* r, const void* p) {
    uint32_t a = (uint32_t)__cvta_generic_to_shared(p);
    asm volatile("ldmatrix.sync.aligned.m8n8.x4.shared.b16 {%0,%1,%2,%3}, [%4];"
                 : "=r"(r[0]), "=r"(r[1]), "=r"(r[2]), "=r"(r[3]) : "r"(a));
}
__device__ __forceinline__ void mma16816(float* d, const uint32_t* a, uint32_t b0, uint32_t b1) {
    asm volatile("mma.sync.aligned.m16n8k16.row.col.f32.f16.f16.f32 "
                 "{%0,%1,%2,%3}, {%4,%5,%6,%7}, {%8,%9}, {%0,%1,%2,%3};"
                 : "+f"(d[0]), "+f"(d[1]), "+f"(d[2]), "+f"(d[3])
                 : "r"(a[0]), "r"(a[1]), "r"(a[2]), "r"(a[3]), "r"(b0), "r"(b1));
}
__device__ __forceinline__ uint32_t packh2(float a, float b) {
    __half2 h = __floats2half2_rn(a, b);
    return *reinterpret_cast<uint32_t*>(&h);
}

// ---------------- prep: act split (vectorized) + weight transposes + rope table ----------------
#define N_ACT  (MROWS*DM)         // 3145728
#define N_ACT4 (N_ACT/4)          // 786432
#define N_W1   (1280*DM)          // 983040
#define N_W2   (DM*DM)            // 589824
#define N_TAB  (T_*32)            // 65536
__global__ void prep_kernel(const float* __restrict__ x,
                            const float* __restrict__ wq, const float* __restrict__ wk,
                            const float* __restrict__ wv, const float* __restrict__ wo,
                            __half* __restrict__ ax, __half* __restrict__ wt1,
                            __half* __restrict__ wt2, float2* __restrict__ ropet) {
    int idx = blockIdx.x * blockDim.x + threadIdx.x;
    if (idx < N_ACT4) {
        int e0 = idx * 4;
        int r = e0 / DM, c = e0 % DM;
        float4 v = *reinterpret_cast<const float4*>(&x[e0]);
        uint32_t h01 = packh2(v.x, v.y), h23 = packh2(v.z, v.w);
        float l0 = v.x - __half2float(__float2half_rn(v.x));
        float l1 = v.y - __half2float(__float2half_rn(v.y));
        float l2 = v.z - __half2float(__float2half_rn(v.z));
        float l3 = v.w - __half2float(__float2half_rn(v.w));
        size_t base = (size_t)r * K2;
        *reinterpret_cast<uint2*>(&ax[base + c])      = make_uint2(h01, h23);
        *reinterpret_cast<uint2*>(&ax[base + c + KW]) = make_uint2(packh2(l0, l1), packh2(l2, l3));
    } else if (idx < N_ACT4 + N_W1) {
        int e = idx - N_ACT4;
        int n = e / DM, k = e % DM;
        float v;
        if (n < 768)       v = wq[(size_t)k * 768 + n];
        else if (n < 1024) v = wk[(size_t)k * 256 + (n - 768)];
        else               v = wv[(size_t)k * 256 + (n - 1024)];
        wt1[(size_t)n * KW + k] = __float2half_rn(v);
    } else if (idx < N_ACT4 + N_W1 + N_W2) {
        int e = idx - N_ACT4 - N_W1;
        int n = e / DM, k = e % DM;
        wt2[(size_t)n * KW + k] = __float2half_rn(wo[(size_t)k * DM + n]);
    } else if (idx < N_ACT4 + N_W1 + N_W2 + N_TAB) {
        int e = idx - N_ACT4 - N_W1 - N_W2;
        int t = e >> 5, m = e & 31;
        float inv = powf(10000.0f, -(float)m / 32.0f);
        float s, c; sincosf((float)t * inv, &s, &c);
        ropet[e] = make_float2(c, s);
    }
}

// ---------------- GEMM mainloop shared config ----------------
#define BM 128
#define BN 128
#define BK 64
#define SAP 72
#define ASTG (BM*SAP)
#define KT2 (K2/BK)   // 24

#define GEMM_MAINLOOP(AS, BS, NSTRIDE)                                            \
    float acc[4][8][4];                                                           \
    _Pragma("unroll")                                                             \
    for (int i = 0; i < 4; i++)                                                   \
        _Pragma("unroll")                                                         \
        for (int j = 0; j < 8; j++)                                               \
            _Pragma("unroll")                                                     \
            for (int r = 0; r < 4; r++) acc[i][j][r] = 0.f;                       \
    auto load_stage = [&](int st, int kt) {                                       \
        int koff = kt * BK;                                                       \
        int bko = koff < KW ? koff : koff - KW;                                   \
        _Pragma("unroll")                                                         \
        for (int i = 0; i < 8; i++) {                                             \
            int u = tid + i * 128;                                                \
            int row = u >> 3, c8 = u & 7;                                         \
            cp16(&AS[st * ASTG + row * SAP + c8 * 8],                             \
                 A + (size_t)(bm + row) * K2 + koff + c8 * 8);                    \
        }                                                                         \
        _Pragma("unroll")                                                         \
        for (int i = 0; i < 8; i++) {                                             \
            int u = tid + i * 128;                                                \
            int row = u >> 3, c8 = u & 7;                                         \
            cp16(&BS[st * ASTG + row * SAP + c8 * 8],                             \
                 Bt + (size_t)(bn + row) * KW + bko + c8 * 8);                    \
        }                                                                         \
        cp_commit();                                                              \
    };                                                                            \
    load_stage(0, 0);                                                             \
    load_stage(1, 1);                                                             \
    for (int kt = 0; kt < KT2; kt++) {                                            \
        int s = kt & 1;                                                           \
        if (kt == KT2 - 1) asm volatile("cp.async.wait_group 0;\n");              \
        else               asm volatile("cp.async.wait_group 1;\n");              \
        __syncthreads();                                                          \
        _Pragma("unroll")                                                         \
        for (int ks = 0; ks < BK; ks += 16) {                                     \
            uint32_t a[4][4];                                                     \
            _Pragma("unroll")                                                     \
            for (int mf = 0; mf < 4; mf++) {                                      \
                int tile = lane >> 3, rr = lane & 7;                              \
                int mrow = wm * 64 + mf * 16 + (tile & 1) * 8 + rr;               \
                int kcol = ks + (tile >> 1) * 8;                                  \
                ldmx4(a[mf], &AS[s * ASTG + mrow * SAP + kcol]);                  \
            }                                                                     \
            _Pragma("unroll")                                                     \
            for (int nfp = 0; nfp < 4; nfp++) {                                   \
                uint32_t bb[4];                                                   \
                int tile = lane >> 3, rr = lane & 7;                              \
                int nrow = wn * 64 + nfp * 16 + (tile >> 1) * 8 + rr;             \
                int kcol = ks + (tile & 1) * 8;                                   \
                ldmx4(bb, &BS[s * ASTG + nrow * SAP + kcol]);                     \
                _Pragma("unroll")                                                 \
                for (int mf = 0; mf < 4; mf++) {                                  \
                    mma16816(acc[mf][2*nfp],   a[mf], bb[0], bb[1]);              \
                    mma16816(acc[mf][2*nfp+1], a[mf], bb[2], bb[3]);              \
                }                                                                 \
            }                                                                     \
        }                                                                         \
        __syncthreads();                                                          \
        if (kt + 2 < KT2) load_stage(s, kt + 2);                                  \
    }

// ---------------- gemm1: QKV projection with fused RoPE/split epilogue ----------------
// N = 1280. Warp's 64-col tile == one head-chunk hc = (bn + wn*64)/64.
__global__ void __launch_bounds__(128, 3)
gemm_qkv_kernel(const __half* __restrict__ A, const __half* __restrict__ Bt,
                __half* __restrict__ qsp, __half* __restrict__ ksp,
                __half* __restrict__ vt, float* __restrict__ kout,
                float* __restrict__ vout, const float2* __restrict__ ropet) {
    extern __shared__ __align__(16) __half smem_g[];
    __half* As = smem_g;
    __half* Bs = smem_g + 2 * ASTG;

    int tid = threadIdx.x;
    int warp = tid >> 5, lane = tid & 31;
    int wm = warp & 1, wn = warp >> 1;
    int bm = blockIdx.y * BM, bn = blockIdx.x * BN;
    int g = lane >> 2, t2 = (lane & 3) * 2;

    GEMM_MAINLOOP(As, Bs, 1280)

    int hc = (bn + wn * 64) >> 6;          // head chunk 0..19 (warp-uniform)
    if (hc < 12) {                          // ---- Q: rope + scale + hi/lo split ----
        int h = hc;
        #pragma unroll
        for (int mf = 0; mf < 4; mf++)
            #pragma unroll
            for (int r2 = 0; r2 < 2; r2++) {
                int trow = bm + wm * 64 + mf * 16 + g + r2 * 8;
                int b = trow >> 11, t = trow & (T_ - 1);
                size_t base = ((size_t)(b * NH + h) * T_ + t) * 128;
                #pragma unroll
                for (int nf = 0; nf < 4; nf++) {
                    int m0 = nf * 8 + t2;
                    float x0a = acc[mf][nf][r2*2],     x0b = acc[mf][nf][r2*2+1];
                    float x1a = acc[mf][nf+4][r2*2],   x1b = acc[mf][nf+4][r2*2+1];
                    float2 ca = ropet[t * 32 + m0];
                    float2 cb = ropet[t * 32 + m0 + 1];
                    float ra0 = (x0a*ca.x - x1a*ca.y) * 0.125f;
                    float ra1 = (x1a*ca.x + x0a*ca.y) * 0.125f;
                    float rb0 = (x0b*cb.x - x1b*cb.y) * 0.125f;
                    float rb1 = (x1b*cb.x + x0b*cb.y) * 0.125f;
                    *reinterpret_cast<uint32_t*>(&qsp[base + m0])      = packh2(ra0, rb0);
                    *reinterpret_cast<uint32_t*>(&qsp[base + m0 + 32]) = packh2(ra1, rb1);
                    float la0 = ra0 - __half2float(__float2half_rn(ra0));
                    float lb0 = rb0 - __half2float(__float2half_rn(rb0));
                    float la1 = ra1 - __half2float(__float2half_rn(ra1));
                    float lb1 = rb1 - __half2float(__float2half_rn(rb1));
                    *reinterpret_cast<uint32_t*>(&qsp[base + 64 + m0]) = packh2(la0, lb0);
                    *reinterpret_cast<uint32_t*>(&qsp[base + 96 + m0]) = packh2(la1, lb1);
                }
            }
    } else if (hc < 16) {                   // ---- K: rope, fp32 out + fp16 ----
        int kvh = hc - 12;
        #pragma unroll
        for (int mf = 0; mf < 4; mf++)
            #pragma unroll
            for (int r2 = 0; r2 < 2; r2++) {
                int trow = bm + wm * 64 + mf * 16 + g + r2 * 8;
                int b = trow >> 11, t = trow & (T_ - 1);
                size_t fb = ((size_t)(b * NKV + kvh) * T_ + t) * DH;
                #pragma unroll
                for (int nf = 0; nf < 4; nf++) {
                    int m0 = nf * 8 + t2;
                    float x0a = acc[mf][nf][r2*2],     x0b = acc[mf][nf][r2*2+1];
                    float x1a = acc[mf][nf+4][r2*2],   x1b = acc[mf][nf+4][r2*2+1];
                    float2 ca = ropet[t * 32 + m0];
                    float2 cb = ropet[t * 32 + m0 + 1];
                    float ra0 = x0a*ca.x - x1a*ca.y;
                    float ra1 = x1a*ca.x + x0a*ca.y;
                    float rb0 = x0b*cb.x - x1b*cb.y;
                    float rb1 = x1b*cb.x + x0b*cb.y;
                    *reinterpret_cast<float2*>(&kout[fb + m0])      = make_float2(ra0, rb0);
                    *reinterpret_cast<float2*>(&kout[fb + m0 + 32]) = make_float2(ra1, rb1);
                    *reinterpret_cast<uint32_t*>(&ksp[fb + m0])      = packh2(ra0, rb0);
                    *reinterpret_cast<uint32_t*>(&ksp[fb + m0 + 32]) = packh2(ra1, rb1);
                }
            }
    } else {                                // ---- V: fp32 out + fp16 transposed ----
        int kvh = hc - 16;
        #pragma unroll
        for (int mf = 0; mf < 4; mf++)
            #pragma unroll
            for (int r2 = 0; r2 < 2; r2++) {
                int trow = bm + wm * 64 + mf * 16 + g + r2 * 8;
                int b = trow >> 11, t = trow & (T_ - 1);
                size_t fb = ((size_t)(b * NKV + kvh) * T_ + t) * DH;
                size_t tb0 = (size_t)(b * NKV + kvh) * DH * T_ + t;
                #pragma unroll
                for (int nf = 0; nf < 8; nf++) {
                    int d0 = nf * 8 + t2;
                    float v0 = acc[mf][nf][r2*2], v1 = acc[mf][nf][r2*2+1];
                    *reinterpret_cast<float2*>(&vout[fb + d0]) = make_float2(v0, v1);
                    g_vt[tb0 + (size_t)d0 * T_]       = __float2half_rn(v0);
                    g_vt[tb0 + (size_t)(d0 + 1) * T_] = __float2half_rn(v1);
                }
            }
    }
    (void)vt;
}

// ---------------- gemm2: plain fp32-C output (frozen mainloop) ----------------
__global__ void __launch_bounds__(128, 3)
gemm_fp16_kernel(const __half* __restrict__ A, const __half* __restrict__ Bt,
                 float* __restrict__ C, int N) {
    extern __shared__ __align__(16) __half smem_g[];
    __half* As = smem_g;
    __half* Bs = smem_g + 2 * ASTG;

    int tid = threadIdx.x;
    int warp = tid >> 5, lane = tid & 31;
    int wm = warp & 1, wn = warp >> 1;
    int bm = blockIdx.y * BM, bn = blockIdx.x * BN;
    int g = lane >> 2, t2 = (lane & 3) * 2;

    GEMM_MAINLOOP(As, Bs, N)

    #pragma unroll
    for (int mf = 0; mf < 4; mf++) {
        int r0 = bm + wm * 64 + mf * 16 + g;
        #pragma unroll
        for (int nf = 0; nf < 8; nf++) {
            int c0 = bn + wn * 64 + nf * 8 + t2;
            *reinterpret_cast<float2*>(&C[(size_t)r0 * N + c0]) =
                make_float2(acc[mf][nf][0], acc[mf][nf][1]);
            *reinterpret_cast<float2*>(&C[(size_t)(r0 + 8) * N + c0]) =
                make_float2(acc[mf][nf][2], acc[mf][nf][3]);
        }
    }
}

// ---------------- fp16 tensor-core windowed flash attention (frozen from R13) ----------------
#define QSTR 136
#define KSTR 72
#define VSTR 72
#define CH 64

__global__ void __launch_bounds__(128, 4)
attn_mma_kernel(const __half* __restrict__ qsp,
                const __half* __restrict__ ksp,
                const __half* __restrict__ vt,
                __half* __restrict__ ax) {
    extern __shared__ __align__(16) __half sm[];
    __half* Qs = sm;
    __half* Ks = Qs + 64 * QSTR;
    __half* Vs = Ks + 2 * 64 * KSTR;

    int blk = blockIdx.x;
    int qt = 31 - blk / (B_ * NH);
    int rest = blk % (B_ * NH);
    int h = rest % NH, b = rest / NH;
    int kvh = h / (NH / NKV);
    int qbase = qt * 64;

    int tid = threadIdx.x, w = tid >> 5, lane = tid & 31;
    int g = lane >> 2, t2 = (lane & 3) * 2;

    const __half* Qg = qsp + ((size_t)(b * NH + h) * T_ + qbase) * 128;
    const __half* Kg = ksp + (size_t)(b * NKV + kvh) * T_ * DH;
    const __half* Vg = vt + (size_t)(b * NKV + kvh) * DH * T_;

    int wlo_key = qbase - (WIN - 1);
    if (wlo_key < GLB) wlo_key = GLB;
    wlo_key &= ~(CH - 1);
    int nch = 1 + ((qbase + 64 - wlo_key) >> 6 > 0 ? (qbase + 64 - wlo_key) >> 6 : 0);

    #pragma unroll
    for (int i = 0; i < 8; i++) {
        int u = tid + i * 128;
        int r = u >> 4, c = u & 15;
        cp16(&Qs[r * QSTR + c * 8], Qg + (size_t)r * 128 + c * 8);
    }

    auto load_chunk = [&](int buf, int c0) {
        __half* Kb = Ks + buf * 64 * KSTR;
        __half* Vb = Vs + buf * 64 * VSTR;
        #pragma unroll
        for (int i = 0; i < 4; i++) {
            int u = tid + i * 128;
            int r = u >> 3, c = u & 7;
            cp16(&Kb[r * KSTR + c * 8], Kg + (size_t)(c0 + r) * DH + c * 8);
        }
        #pragma unroll
        for (int i = 0; i < 4; i++) {
            int u = tid + i * 128;
            int r = u >> 3, c = u & 7;
            cp16(&Vb[r * VSTR + c * 8], Vg + (size_t)r * T_ + c0 + c * 8);
        }
    };

    load_chunk(0, 0);
    cp_commit();

    float O[8][4];
    #pragma unroll
    for (int nf = 0; nf < 8; nf++)
        #pragma unroll
        for (int r = 0; r < 4; r++) O[nf][r] = 0.f;
    float mrow[2] = {-1e30f, -1e30f};
    float lrow[2] = {0.f, 0.f};
    int irow0 = qbase + w * 16 + g;
    int wminr = qbase + w * 16;
    int wmaxr = wminr + 15;

    for (int idx = 0; idx < nch; idx++) {
        int buf = idx & 1;
        int c0 = (idx == 0) ? 0 : wlo_key + (idx - 1) * CH;
        if (idx + 1 < nch) {
            int c0n = (idx == 0) ? wlo_key : c0 + CH;
            load_chunk(buf ^ 1, c0n);
            cp_commit();
            asm volatile("cp.async.wait_group 1;\n");
        } else {
            asm volatile("cp.async.wait_group 0;\n");
        }
        __syncthreads();

        const __half* Kb = Ks + buf * 64 * KSTR;
        const __half* Vb = Vs + buf * 64 * VSTR;

        float sc[8][4];
        #pragma unroll
        for (int nf = 0; nf < 8; nf++)
            #pragma unroll
            for (int r = 0; r < 4; r++) sc[nf][r] = 0.f;

        #pragma unroll
        for (int kb = 0; kb < 4; kb++) {
            uint32_t aA[4], aB[4];
            {
                int tile = lane >> 3, rr = lane & 7;
                int mrw = w * 16 + (tile & 1) * 8 + rr;
                ldmx4(aA, &Qs[mrw * QSTR + kb * 32 + (tile >> 1) * 8]);
                ldmx4(aB, &Qs[mrw * QSTR + kb * 32 + 16 + (tile >> 1) * 8]);
            }
            int kk = (kb & 1) * 32;
            #pragma unroll
            for (int nf = 0; nf < 8; nf++) {
                uint32_t bb[4];
                ldmx4(bb, &Kb[(nf * 8 + (lane & 7)) * KSTR + kk + (lane >> 3) * 8]);
                mma16816(sc[nf], aA, bb[0], bb[1]);
                mma16816(sc[nf], aB, bb[2], bb[3]);
            }
        }

        bool full = (c0 + CH - 1 <= wminr) &&
                    ((c0 >= wmaxr - WIN + 1) || (c0 + CH - 1 < GLB));
        float cmax[2] = {-1e30f, -1e30f};
        if (full) {
            #pragma unroll
            for (int nf = 0; nf < 8; nf++)
                #pragma unroll
                for (int r = 0; r < 4; r++)
                    cmax[r >> 1] = fmaxf(cmax[r >> 1], sc[nf][r]);
        } else {
            #pragma unroll
            for (int nf = 0; nf < 8; nf++)
                #pragma unroll
                for (int r = 0; r < 4; r++) {
                    int j = c0 + nf * 8 + t2 + (r & 1);
                    int i = irow0 + (r >> 1) * 8;
                    bool a = (j <= i) && ((j > i - WIN) || (j < GLB) || (i < GLB));
                    float s = a ? sc[nf][r] : -1e30f;
                    sc[nf][r] = s;
                    cmax[r >> 1] = fmaxf(cmax[r >> 1], s);
                }
        }
        #pragma unroll
        for (int r2 = 0; r2 < 2; r2++) {
            cmax[r2] = fmaxf(cmax[r2], __shfl_xor_sync(0xffffffffu, cmax[r2], 1));
            cmax[r2] = fmaxf(cmax[r2], __shfl_xor_sync(0xffffffffu, cmax[r2], 2));
        }
        float scl[2], rsum[2] = {0.f, 0.f};
        #pragma unroll
        for (int r2 = 0; r2 < 2; r2++) {
            float mn = fmaxf(mrow[r2], cmax[r2]);
            scl[r2] = __expf(mrow[r2] - mn);
            mrow[r2] = mn;
        }
        #pragma unroll
        for (int nf = 0; nf < 8; nf++)
            #pragma unroll
            for (int r = 0; r < 4; r++) {
                float s = sc[nf][r];
                float p = (s > -5e29f) ? __expf(s - mrow[r >> 1]) : 0.f;
                sc[nf][r] = p;
                rsum[r >> 1] += p;
            }
        #pragma unroll
        for (int r2 = 0; r2 < 2; r2++) {
            rsum[r2] += __shfl_xor_sync(0xffffffffu, rsum[r2], 1);
            rsum[r2] += __shfl_xor_sync(0xffffffffu, rsum[r2], 2);
            lrow[r2] = lrow[r2] * scl[r2] + rsum[r2];
        }
        #pragma unroll
        for (int nf = 0; nf < 8; nf++) {
            O[nf][0] *= scl[0]; O[nf][1] *= scl[0];
            O[nf][2] *= scl[1]; O[nf][3] *= scl[1];
        }

        uint32_t Ph[4][4], Pl[4][4];
        #pragma unroll
        for (int f = 0; f < 4; f++) {
            float p0 = sc[2*f][0],   p1 = sc[2*f][1],   p2 = sc[2*f][2],   p3 = sc[2*f][3];
            float q0 = sc[2*f+1][0], q1 = sc[2*f+1][1], q2 = sc[2*f+1][2], q3 = sc[2*f+1][3];
            Ph[f][0] = packh2(p0, p1); Ph[f][1] = packh2(p2, p3);
            Ph[f][2] = packh2(q0, q1); Ph[f][3] = packh2(q2, q3);
            Pl[f][0] = packh2(p0 - __half2float(__float2half_rn(p0)),
                              p1 - __half2float(__float2half_rn(p1)));
            Pl[f][1] = packh2(p2 - __half2float(__float2half_rn(p2)),
                              p3 - __half2float(__float2half_rn(p3)));
            Pl[f][2] = packh2(q0 - __half2float(__float2half_rn(q0)),
                              q1 - __half2float(__float2half_rn(q1)));
            Pl[f][3] = packh2(q2 - __half2float(__float2half_rn(q2)),
                              q3 - __half2float(__float2half_rn(q3)));
        }

        #pragma unroll
        for (int nf = 0; nf < 8; nf++) {
            uint32_t va[4], vb[4];
            const __half* vrow = &Vb[(nf * 8 + (lane & 7)) * VSTR + (lane >> 3) * 8];
            ldmx4(va, vrow);
            ldmx4(vb, vrow + 32);
            mma16816(O[nf], Ph[0], va[0], va[1]);
            mma16816(O[nf], Ph[1], va[2], va[3]);
            mma16816(O[nf], Ph[2], vb[0], vb[1]);
            mma16816(O[nf], Ph[3], vb[2], vb[3]);
            mma16816(O[nf], Pl[0], va[0], va[1]);
            mma16816(O[nf], Pl[1], va[2], va[3]);
            mma16816(O[nf], Pl[2], vb[0], vb[1]);
            mma16816(O[nf], Pl[3], vb[2], vb[3]);
        }
        __syncthreads();
    }

    float inv0 = 1.0f / lrow[0], inv1 = 1.0f / lrow[1];
    size_t r0g = (size_t)b * T_ + irow0;
    size_t r1g = r0g + 8;
    #pragma unroll
    for (int nf = 0; nf < 8; nf++) {
        int col = h * DH + nf * 8 + t2;
        float v00 = O[nf][0] * inv0, v01 = O[nf][1] * inv0;
        float v10 = O[nf][2] * inv1, v11 = O[nf][3] * inv1;
        __half h00 = __float2half_rn(v00), h01 = __float2half_rn(v01);
        __half h10 = __float2half_rn(v10), h11 = __float2half_rn(v11);
        *reinterpret_cast<uint32_t*>(&ax[r0g * K2 + col]) = packh2(v00, v01);
        *reinterpret_cast<uint32_t*>(&ax[r1g * K2 + col]) = packh2(v10, v11);
        *reinterpret_cast<uint32_t*>(&ax[r0g * K2 + KW + col]) =
            packh2(v00 - __half2float(h00), v01 - __half2float(h01));
        *reinterpret_cast<uint32_t*>(&ax[r1g * K2 + KW + col]) =
            packh2(v10 - __half2float(h10), v11 - __half2float(h11));
    }
}

extern "C" void kernel_launch(void* const* d_in, const int* in_sizes, int n_in,
                              void* d_out, int out_size) {
    const float* x  = (const float*)d_in[0];
    const float* wq = (const float*)d_in[1];
    const float* wk = (const float*)d_in[2];
    const float* wv = (const float*)d_in[3];
    const float* wo = (const float*)d_in[4];
    float* out = (float*)d_out;

    __half *ax, *wt1, *wt2, *qsp, *ksp, *vt;
    float *kr, *vr;
    float2* ropet;
    cudaGetSymbolAddress((void**)&ax,    g_ax);
    cudaGetSymbolAddress((void**)&wt1,   g_wt1);
    cudaGetSymbolAddress((void**)&wt2,   g_wt2);
    cudaGetSymbolAddress((void**)&kr,    g_kr);
    cudaGetSymbolAddress((void**)&vr,    g_vr);
    cudaGetSymbolAddress((void**)&qsp,   g_qsp);
    cudaGetSymbolAddress((void**)&ksp,   g_ksp);
    cudaGetSymbolAddress((void**)&vt,    g_vt);
    cudaGetSymbolAddress((void**)&ropet, g_ropet);

    const int out_elems = B_ * T_ * DM;
    const int kv_elems  = B_ * NKV * T_ * DH;
    float* kout = kr; float* vout = vr;
    if (out_size >= out_elems + 2 * kv_elems) {
        kout = out + out_elems;
        vout = out + out_elems + kv_elems;
    }

    const int gemm_smem = 4 * ASTG * 2;                                    // 73728 B
    cudaFuncSetAttribute(gemm_qkv_kernel,  cudaFuncAttributeMaxDynamicSharedMemorySize, gemm_smem);
    cudaFuncSetAttribute(gemm_fp16_kernel, cudaFuncAttributeMaxDynamicSharedMemorySize, gemm_smem);
    const int attn_smem = (64 * QSTR + 2 * 64 * KSTR + 2 * 64 * VSTR) * 2; // 54272 B
    cudaFuncSetAttribute(attn_mma_kernel, cudaFuncAttributeMaxDynamicSharedMemorySize, attn_smem);

    const int prep_total = N_ACT4 + N_W1 + N_W2 + N_TAB;
    prep_kernel<<<(prep_total + 255)/256, 256>>>(x, wq, wk, wv, wo, ax, wt1, wt2, ropet);

    gemm_qkv_kernel<<<dim3(1280/BN, MROWS/BM), 128, gemm_smem>>>(ax, wt1, qsp, ksp, vt,
                                                                 kout, vout, ropet);
    attn_mma_kernel<<<B_ * NH * (T_/64), 128, attn_smem>>>(qsp, ksp, vt, ax);
    gemm_fp16_kernel<<<dim3(DM/BN, MROWS/BM), 128, gemm_smem>>>(ax, wt2, out, DM);
}

// round 15
// speedup vs baseline: 6.5781x; 1.0891x over previous
#include <cuda_runtime.h>
#include <cuda_fp16.h>
#include <stdint.h>
#include <cstdint>
#include <math.h>

#define B_ 2
#define T_ 2048
#define DM 768
#define NH 12
#define NKV 4
#define DH 64
#define WIN 512
#define GLB 64
#define MROWS (B_*T_)          // 4096
#define K2 1536                // stacked-K (2x) for fp16 hi/lo trick
#define KW 768                 // weight K (single copy; loader wraps)

// ---------------- scratch ----------------
__device__ __half g_ax[(size_t)MROWS*K2];        // split activations [4096][hi768|lo768]
__device__ __half g_wt1[(size_t)1280*KW];        // fp16 transposed [wq|wk|wv]
__device__ __half g_wt2[(size_t)DM*KW];          // fp16 transposed wo
__device__ float  g_kr[(size_t)B_*NKV*T_*DH];    // fallback k out
__device__ float  g_vr[(size_t)B_*NKV*T_*DH];    // fallback v out
__device__ __half g_qsp[(size_t)B_*NH*T_*128];   // Q' [b,h,t][hi64|lo64], pre-scaled 1/8
__device__ __half g_ksp[(size_t)B_*NKV*T_*DH];   // K fp16 [b,kvh,t][64]
__device__ __half g_vt[(size_t)B_*NKV*DH*T_];    // V^T fp16 [b,kvh,d][t]
__device__ float2 g_ropet[T_*32];                // cos/sin table [t][m]

// ---------------- helpers ----------------
__device__ __forceinline__ void cp16(void* smem, const void* gmem) {
    uint32_t s = (uint32_t)__cvta_generic_to_shared(smem);
    asm volatile("cp.async.cg.shared.global [%0], [%1], 16;\n" :: "r"(s), "l"(gmem));
}
__device__ __forceinline__ void cp_commit() { asm volatile("cp.async.commit_group;\n"); }

__device__ __forceinline__ void ldmx4(uint32_t* r, const void* p) {
    uint32_t a = (uint32_t)__cvta_generic_to_shared(p);
    asm volatile("ldmatrix.sync.aligned.m8n8.x4.shared.b16 {%0,%1,%2,%3}, [%4];"
                 : "=r"(r[0]), "=r"(r[1]), "=r"(r[2]), "=r"(r[3]) : "r"(a));
}
__device__ __forceinline__ void mma16816(float* d, const uint32_t* a, uint32_t b0, uint32_t b1) {
    asm volatile("mma.sync.aligned.m16n8k16.row.col.f32.f16.f16.f32 "
                 "{%0,%1,%2,%3}, {%4,%5,%6,%7}, {%8,%9}, {%0,%1,%2,%3};"
                 : "+f"(d[0]), "+f"(d[1]), "+f"(d[2]), "+f"(d[3])
                 : "r"(a[0]), "r"(a[1]), "r"(a[2]), "r"(a[3]), "r"(b0), "r"(b1));
}
__device__ __forceinline__ uint32_t packh2(float a, float b) {
    __half2 h = __floats2half2_rn(a, b);
    return *reinterpret_cast<uint32_t*>(&h);
}

// ---------------- prep: act split (vectorized) + weight transposes + rope table ----------------
#define N_ACT  (MROWS*DM)         // 3145728
#define N_ACT4 (N_ACT/4)          // 786432
#define N_W1   (1280*DM)          // 983040
#define N_W2   (DM*DM)            // 589824
#define N_TAB  (T_*32)            // 65536
__global__ void prep_kernel(const float* __restrict__ x,
                            const float* __restrict__ wq, const float* __restrict__ wk,
                            const float* __restrict__ wv, const float* __restrict__ wo,
                            __half* __restrict__ ax, __half* __restrict__ wt1,
                            __half* __restrict__ wt2, float2* __restrict__ ropet) {
    int idx = blockIdx.x * blockDim.x + threadIdx.x;
    if (idx < N_ACT4) {
        int e0 = idx * 4;
        int r = e0 / DM, c = e0 % DM;
        float4 v = *reinterpret_cast<const float4*>(&x[e0]);
        uint32_t h01 = packh2(v.x, v.y), h23 = packh2(v.z, v.w);
        float l0 = v.x - __half2float(__float2half_rn(v.x));
        float l1 = v.y - __half2float(__float2half_rn(v.y));
        float l2 = v.z - __half2float(__float2half_rn(v.z));
        float l3 = v.w - __half2float(__float2half_rn(v.w));
        size_t base = (size_t)r * K2;
        *reinterpret_cast<uint2*>(&ax[base + c])      = make_uint2(h01, h23);
        *reinterpret_cast<uint2*>(&ax[base + c + KW]) = make_uint2(packh2(l0, l1), packh2(l2, l3));
    } else if (idx < N_ACT4 + N_W1) {
        int e = idx - N_ACT4;
        int n = e / DM, k = e % DM;
        float v;
        if (n < 768)       v = wq[(size_t)k * 768 + n];
        else if (n < 1024) v = wk[(size_t)k * 256 + (n - 768)];
        else               v = wv[(size_t)k * 256 + (n - 1024)];
        wt1[(size_t)n * KW + k] = __float2half_rn(v);
    } else if (idx < N_ACT4 + N_W1 + N_W2) {
        int e = idx - N_ACT4 - N_W1;
        int n = e / DM, k = e % DM;
        wt2[(size_t)n * KW + k] = __float2half_rn(wo[(size_t)k * DM + n]);
    } else if (idx < N_ACT4 + N_W1 + N_W2 + N_TAB) {
        int e = idx - N_ACT4 - N_W1 - N_W2;
        int t = e >> 5, m = e & 31;
        float inv = powf(10000.0f, -(float)m / 32.0f);
        float s, c; sincosf((float)t * inv, &s, &c);
        ropet[e] = make_float2(c, s);
    }
}

// ---------------- GEMM shared config ----------------
#define BK 64
#define SAP 72
#define KT2 (K2/BK)   // 24

// ---------------- gemm1: QKV projection, 64x128 CTA tile, fused RoPE/split epilogue ----------------
// grid (1280/128=10, 4096/64=64) = 640 CTAs; 4 warps, warp tile 32x64.
#define A1STG (64*SAP)
#define B1STG (128*SAP)
__global__ void __launch_bounds__(128, 4)
gemm_qkv_kernel(const __half* __restrict__ A, const __half* __restrict__ Bt,
                __half* __restrict__ qsp, __half* __restrict__ ksp,
                float* __restrict__ kout, float* __restrict__ vout,
                const float2* __restrict__ ropet) {
    extern __shared__ __align__(16) __half smem_g[];
    __half* As = smem_g;                 // [2][A1STG]
    __half* Bs = smem_g + 2 * A1STG;     // [2][B1STG]

    int tid = threadIdx.x;
    int warp = tid >> 5, lane = tid & 31;
    int wm = warp & 1, wn = warp >> 1;   // wm: 32-row half, wn: 64-col half
    int bm = blockIdx.y * 64, bn = blockIdx.x * 128;
    int g = lane >> 2, t2 = (lane & 3) * 2;

    float acc[2][8][4];
    #pragma unroll
    for (int i = 0; i < 2; i++)
        #pragma unroll
        for (int j = 0; j < 8; j++)
            #pragma unroll
            for (int r = 0; r < 4; r++) acc[i][j][r] = 0.f;

    auto load_stage = [&](int st, int kt) {
        int koff = kt * BK;
        int bko = koff < KW ? koff : koff - KW;
        #pragma unroll
        for (int i = 0; i < 4; i++) {              // A: 64 rows x 8 units
            int u = tid + i * 128;
            int row = u >> 3, c8 = u & 7;
            cp16(&As[st * A1STG + row * SAP + c8 * 8],
                 A + (size_t)(bm + row) * K2 + koff + c8 * 8);
        }
        #pragma unroll
        for (int i = 0; i < 8; i++) {              // B: 128 rows x 8 units
            int u = tid + i * 128;
            int row = u >> 3, c8 = u & 7;
            cp16(&Bs[st * B1STG + row * SAP + c8 * 8],
                 Bt + (size_t)(bn + row) * KW + bko + c8 * 8);
        }
        cp_commit();
    };

    load_stage(0, 0);
    load_stage(1, 1);

    for (int kt = 0; kt < KT2; kt++) {
        int s = kt & 1;
        if (kt == KT2 - 1) asm volatile("cp.async.wait_group 0;\n");
        else               asm volatile("cp.async.wait_group 1;\n");
        __syncthreads();

        #pragma unroll
        for (int ks = 0; ks < BK; ks += 16) {
            uint32_t a[2][4];
            #pragma unroll
            for (int mf = 0; mf < 2; mf++) {
                int tile = lane >> 3, rr = lane & 7;
                int mrow = wm * 32 + mf * 16 + (tile & 1) * 8 + rr;
                int kcol = ks + (tile >> 1) * 8;
                ldmx4(a[mf], &As[s * A1STG + mrow * SAP + kcol]);
            }
            #pragma unroll
            for (int nfp = 0; nfp < 4; nfp++) {
                uint32_t bb[4];
                int tile = lane >> 3, rr = lane & 7;
                int nrow = wn * 64 + nfp * 16 + (tile >> 1) * 8 + rr;
                int kcol = ks + (tile & 1) * 8;
                ldmx4(bb, &Bs[s * B1STG + nrow * SAP + kcol]);
                #pragma unroll
                for (int mf = 0; mf < 2; mf++) {
                    mma16816(acc[mf][2*nfp],   a[mf], bb[0], bb[1]);
                    mma16816(acc[mf][2*nfp+1], a[mf], bb[2], bb[3]);
                }
            }
        }
        __syncthreads();
        if (kt + 2 < KT2) load_stage(s, kt + 2);
    }

    int hc = (bn + wn * 64) >> 6;          // head chunk 0..19 (warp-uniform)
    if (hc < 12) {                          // ---- Q: rope + scale + hi/lo split ----
        int h = hc;
        #pragma unroll
        for (int mf = 0; mf < 2; mf++)
            #pragma unroll
            for (int r2 = 0; r2 < 2; r2++) {
                int trow = bm + wm * 32 + mf * 16 + g + r2 * 8;
                int b = trow >> 11, t = trow & (T_ - 1);
                size_t base = ((size_t)(b * NH + h) * T_ + t) * 128;
                #pragma unroll
                for (int nf = 0; nf < 4; nf++) {
                    int m0 = nf * 8 + t2;
                    float x0a = acc[mf][nf][r2*2],     x0b = acc[mf][nf][r2*2+1];
                    float x1a = acc[mf][nf+4][r2*2],   x1b = acc[mf][nf+4][r2*2+1];
                    float2 ca = ropet[t * 32 + m0];
                    float2 cb = ropet[t * 32 + m0 + 1];
                    float ra0 = (x0a*ca.x - x1a*ca.y) * 0.125f;
                    float ra1 = (x1a*ca.x + x0a*ca.y) * 0.125f;
                    float rb0 = (x0b*cb.x - x1b*cb.y) * 0.125f;
                    float rb1 = (x1b*cb.x + x0b*cb.y) * 0.125f;
                    *reinterpret_cast<uint32_t*>(&qsp[base + m0])      = packh2(ra0, rb0);
                    *reinterpret_cast<uint32_t*>(&qsp[base + m0 + 32]) = packh2(ra1, rb1);
                    float la0 = ra0 - __half2float(__float2half_rn(ra0));
                    float lb0 = rb0 - __half2float(__float2half_rn(rb0));
                    float la1 = ra1 - __half2float(__float2half_rn(ra1));
                    float lb1 = rb1 - __half2float(__float2half_rn(rb1));
                    *reinterpret_cast<uint32_t*>(&qsp[base + 64 + m0]) = packh2(la0, lb0);
                    *reinterpret_cast<uint32_t*>(&qsp[base + 96 + m0]) = packh2(la1, lb1);
                }
            }
    } else if (hc < 16) {                   // ---- K: rope, fp32 out + fp16 ----
        int kvh = hc - 12;
        #pragma unroll
        for (int mf = 0; mf < 2; mf++)
            #pragma unroll
            for (int r2 = 0; r2 < 2; r2++) {
                int trow = bm + wm * 32 + mf * 16 + g + r2 * 8;
                int b = trow >> 11, t = trow & (T_ - 1);
                size_t fb = ((size_t)(b * NKV + kvh) * T_ + t) * DH;
                #pragma unroll
                for (int nf = 0; nf < 4; nf++) {
                    int m0 = nf * 8 + t2;
                    float x0a = acc[mf][nf][r2*2],     x0b = acc[mf][nf][r2*2+1];
                    float x1a = acc[mf][nf+4][r2*2],   x1b = acc[mf][nf+4][r2*2+1];
                    float2 ca = ropet[t * 32 + m0];
                    float2 cb = ropet[t * 32 + m0 + 1];
                    float ra0 = x0a*ca.x - x1a*ca.y;
                    float ra1 = x1a*ca.x + x0a*ca.y;
                    float rb0 = x0b*cb.x - x1b*cb.y;
                    float rb1 = x1b*cb.x + x0b*cb.y;
                    *reinterpret_cast<float2*>(&kout[fb + m0])      = make_float2(ra0, rb0);
                    *reinterpret_cast<float2*>(&kout[fb + m0 + 32]) = make_float2(ra1, rb1);
                    *reinterpret_cast<uint32_t*>(&ksp[fb + m0])      = packh2(ra0, rb0);
                    *reinterpret_cast<uint32_t*>(&ksp[fb + m0 + 32]) = packh2(ra1, rb1);
                }
            }
    } else {                                // ---- V: fp32 out + fp16 transposed ----
        int kvh = hc - 16;
        #pragma unroll
        for (int mf = 0; mf < 2; mf++)
            #pragma unroll
            for (int r2 = 0; r2 < 2; r2++) {
                int trow = bm + wm * 32 + mf * 16 + g + r2 * 8;
                int b = trow >> 11, t = trow & (T_ - 1);
                size_t fb = ((size_t)(b * NKV + kvh) * T_ + t) * DH;
                size_t tb0 = (size_t)(b * NKV + kvh) * DH * T_ + t;
                #pragma unroll
                for (int nf = 0; nf < 8; nf++) {
                    int d0 = nf * 8 + t2;
                    float v0 = acc[mf][nf][r2*2], v1 = acc[mf][nf][r2*2+1];
                    *reinterpret_cast<float2*>(&vout[fb + d0]) = make_float2(v0, v1);
                    g_vt[tb0 + (size_t)d0 * T_]       = __float2half_rn(v0);
                    g_vt[tb0 + (size_t)(d0 + 1) * T_] = __float2half_rn(v1);
                }
            }
    }
}

// ---------------- gemm2: 128x64 CTA tile, fp32-C output ----------------
// grid (768/64=12, 4096/128=32) = 384 CTAs; 4 warps, warp tile 64x32.
#define A2STG (128*SAP)
#define B2STG (64*SAP)
__global__ void __launch_bounds__(128, 4)
gemm_out_kernel(const __half* __restrict__ A, const __half* __restrict__ Bt,
                float* __restrict__ C, int N) {
    extern __shared__ __align__(16) __half smem_g[];
    __half* As = smem_g;                 // [2][A2STG]
    __half* Bs = smem_g + 2 * A2STG;     // [2][B2STG]

    int tid = threadIdx.x;
    int warp = tid >> 5, lane = tid & 31;
    int wm = warp & 1, wn = warp >> 1;   // wm: 64-row half, wn: 32-col half
    int bm = blockIdx.y * 128, bn = blockIdx.x * 64;
    int g = lane >> 2, t2 = (lane & 3) * 2;

    float acc[4][4][4];
    #pragma unroll
    for (int i = 0; i < 4; i++)
        #pragma unroll
        for (int j = 0; j < 4; j++)
            #pragma unroll
            for (int r = 0; r < 4; r++) acc[i][j][r] = 0.f;

    auto load_stage = [&](int st, int kt) {
        int koff = kt * BK;
        int bko = koff < KW ? koff : koff - KW;
        #pragma unroll
        for (int i = 0; i < 8; i++) {              // A: 128 rows x 8 units
            int u = tid + i * 128;
            int row = u >> 3, c8 = u & 7;
            cp16(&As[st * A2STG + row * SAP + c8 * 8],
                 A + (size_t)(bm + row) * K2 + koff + c8 * 8);
        }
        #pragma unroll
        for (int i = 0; i < 4; i++) {              // B: 64 rows x 8 units
            int u = tid + i * 128;
            int row = u >> 3, c8 = u & 7;
            cp16(&Bs[st * B2STG + row * SAP + c8 * 8],
                 Bt + (size_t)(bn + row) * KW + bko + c8 * 8);
        }
        cp_commit();
    };

    load_stage(0, 0);
    load_stage(1, 1);

    for (int kt = 0; kt < KT2; kt++) {
        int s = kt & 1;
        if (kt == KT2 - 1) asm volatile("cp.async.wait_group 0;\n");
        else               asm volatile("cp.async.wait_group 1;\n");
        __syncthreads();

        #pragma unroll
        for (int ks = 0; ks < BK; ks += 16) {
            uint32_t a[4][4];
            #pragma unroll
            for (int mf = 0; mf < 4; mf++) {
                int tile = lane >> 3, rr = lane & 7;
                int mrow = wm * 64 + mf * 16 + (tile & 1) * 8 + rr;
                int kcol = ks + (tile >> 1) * 8;
                ldmx4(a[mf], &As[s * A2STG + mrow * SAP + kcol]);
            }
            #pragma unroll
            for (int nfp = 0; nfp < 2; nfp++) {
                uint32_t bb[4];
                int tile = lane >> 3, rr = lane & 7;
                int nrow = wn * 32 + nfp * 16 + (tile >> 1) * 8 + rr;
                int kcol = ks + (tile & 1) * 8;
                ldmx4(bb, &Bs[s * B2STG + nrow * SAP + kcol]);
                #pragma unroll
                for (int mf = 0; mf < 4; mf++) {
                    mma16816(acc[mf][2*nfp],   a[mf], bb[0], bb[1]);
                    mma16816(acc[mf][2*nfp+1], a[mf], bb[2], bb[3]);
                }
            }
        }
        __syncthreads();
        if (kt + 2 < KT2) load_stage(s, kt + 2);
    }

    #pragma unroll
    for (int mf = 0; mf < 4; mf++) {
        int r0 = bm + wm * 64 + mf * 16 + g;
        #pragma unroll
        for (int nf = 0; nf < 4; nf++) {
            int c0 = bn + wn * 32 + nf * 8 + t2;
            *reinterpret_cast<float2*>(&C[(size_t)r0 * N + c0]) =
                make_float2(acc[mf][nf][0], acc[mf][nf][1]);
            *reinterpret_cast<float2*>(&C[(size_t)(r0 + 8) * N + c0]) =
                make_float2(acc[mf][nf][2], acc[mf][nf][3]);
        }
    }
}

// ---------------- fp16 tensor-core windowed flash attention (frozen from R13) ----------------
#define QSTR 136
#define KSTR 72
#define VSTR 72
#define CH 64

__global__ void __launch_bounds__(128, 4)
attn_mma_kernel(const __half* __restrict__ qsp,
                const __half* __restrict__ ksp,
                const __half* __restrict__ vt,
                __half* __restrict__ ax) {
    extern __shared__ __align__(16) __half sm[];
    __half* Qs = sm;
    __half* Ks = Qs + 64 * QSTR;
    __half* Vs = Ks + 2 * 64 * KSTR;

    int blk = blockIdx.x;
    int qt = 31 - blk / (B_ * NH);
    int rest = blk % (B_ * NH);
    int h = rest % NH, b = rest / NH;
    int kvh = h / (NH / NKV);
    int qbase = qt * 64;

    int tid = threadIdx.x, w = tid >> 5, lane = tid & 31;
    int g = lane >> 2, t2 = (lane & 3) * 2;

    const __half* Qg = qsp + ((size_t)(b * NH + h) * T_ + qbase) * 128;
    const __half* Kg = ksp + (size_t)(b * NKV + kvh) * T_ * DH;
    const __half* Vg = vt + (size_t)(b * NKV + kvh) * DH * T_;

    int wlo_key = qbase - (WIN - 1);
    if (wlo_key < GLB) wlo_key = GLB;
    wlo_key &= ~(CH - 1);
    int nch = 1 + ((qbase + 64 - wlo_key) >> 6 > 0 ? (qbase + 64 - wlo_key) >> 6 : 0);

    #pragma unroll
    for (int i = 0; i < 8; i++) {
        int u = tid + i * 128;
        int r = u >> 4, c = u & 15;
        cp16(&Qs[r * QSTR + c * 8], Qg + (size_t)r * 128 + c * 8);
    }

    auto load_chunk = [&](int buf, int c0) {
        __half* Kb = Ks + buf * 64 * KSTR;
        __half* Vb = Vs + buf * 64 * VSTR;
        #pragma unroll
        for (int i = 0; i < 4; i++) {
            int u = tid + i * 128;
            int r = u >> 3, c = u & 7;
            cp16(&Kb[r * KSTR + c * 8], Kg + (size_t)(c0 + r) * DH + c * 8);
        }
        #pragma unroll
        for (int i = 0; i < 4; i++) {
            int u = tid + i * 128;
            int r = u >> 3, c = u & 7;
            cp16(&Vb[r * VSTR + c * 8], Vg + (size_t)r * T_ + c0 + c * 8);
        }
    };

    load_chunk(0, 0);
    cp_commit();

    float O[8][4];
    #pragma unroll
    for (int nf = 0; nf < 8; nf++)
        #pragma unroll
        for (int r = 0; r < 4; r++) O[nf][r] = 0.f;
    float mrow[2] = {-1e30f, -1e30f};
    float lrow[2] = {0.f, 0.f};
    int irow0 = qbase + w * 16 + g;
    int wminr = qbase + w * 16;
    int wmaxr = wminr + 15;

    for (int idx = 0; idx < nch; idx++) {
        int buf = idx & 1;
        int c0 = (idx == 0) ? 0 : wlo_key + (idx - 1) * CH;
        if (idx + 1 < nch) {
            int c0n = (idx == 0) ? wlo_key : c0 + CH;
            load_chunk(buf ^ 1, c0n);
            cp_commit();
            asm volatile("cp.async.wait_group 1;\n");
        } else {
            asm volatile("cp.async.wait_group 0;\n");
        }
        __syncthreads();

        const __half* Kb = Ks + buf * 64 * KSTR;
        const __half* Vb = Vs + buf * 64 * VSTR;

        float sc[8][4];
        #pragma unroll
        for (int nf = 0; nf < 8; nf++)
            #pragma unroll
            for (int r = 0; r < 4; r++) sc[nf][r] = 0.f;

        #pragma unroll
        for (int kb = 0; kb < 4; kb++) {
            uint32_t aA[4], aB[4];
            {
                int tile = lane >> 3, rr = lane & 7;
                int mrw = w * 16 + (tile & 1) * 8 + rr;
                ldmx4(aA, &Qs[mrw * QSTR + kb * 32 + (tile >> 1) * 8]);
                ldmx4(aB, &Qs[mrw * QSTR + kb * 32 + 16 + (tile >> 1) * 8]);
            }
            int kk = (kb & 1) * 32;
            #pragma unroll
            for (int nf = 0; nf < 8; nf++) {
                uint32_t bb[4];
                ldmx4(bb, &Kb[(nf * 8 + (lane & 7)) * KSTR + kk + (lane >> 3) * 8]);
                mma16816(sc[nf], aA, bb[0], bb[1]);
                mma16816(sc[nf], aB, bb[2], bb[3]);
            }
        }

        bool full = (c0 + CH - 1 <= wminr) &&
                    ((c0 >= wmaxr - WIN + 1) || (c0 + CH - 1 < GLB));
        float cmax[2] = {-1e30f, -1e30f};
        if (full) {
            #pragma unroll
            for (int nf = 0; nf < 8; nf++)
                #pragma unroll
                for (int r = 0; r < 4; r++)
                    cmax[r >> 1] = fmaxf(cmax[r >> 1], sc[nf][r]);
        } else {
            #pragma unroll
            for (int nf = 0; nf < 8; nf++)
                #pragma unroll
                for (int r = 0; r < 4; r++) {
                    int j = c0 + nf * 8 + t2 + (r & 1);
                    int i = irow0 + (r >> 1) * 8;
                    bool a = (j <= i) && ((j > i - WIN) || (j < GLB) || (i < GLB));
                    float s = a ? sc[nf][r] : -1e30f;
                    sc[nf][r] = s;
                    cmax[r >> 1] = fmaxf(cmax[r >> 1], s);
                }
        }
        #pragma unroll
        for (int r2 = 0; r2 < 2; r2++) {
            cmax[r2] = fmaxf(cmax[r2], __shfl_xor_sync(0xffffffffu, cmax[r2], 1));
            cmax[r2] = fmaxf(cmax[r2], __shfl_xor_sync(0xffffffffu, cmax[r2], 2));
        }
        float scl[2], rsum[2] = {0.f, 0.f};
        #pragma unroll
        for (int r2 = 0; r2 < 2; r2++) {
            float mn = fmaxf(mrow[r2], cmax[r2]);
            scl[r2] = __expf(mrow[r2] - mn);
            mrow[r2] = mn;
        }
        #pragma unroll
        for (int nf = 0; nf < 8; nf++)
            #pragma unroll
            for (int r = 0; r < 4; r++) {
                float s = sc[nf][r];
                float p = (s > -5e29f) ? __expf(s - mrow[r >> 1]) : 0.f;
                sc[nf][r] = p;
                rsum[r >> 1] += p;
            }
        #pragma unroll
        for (int r2 = 0; r2 < 2; r2++) {
            rsum[r2] += __shfl_xor_sync(0xffffffffu, rsum[r2], 1);
            rsum[r2] += __shfl_xor_sync(0xffffffffu, rsum[r2], 2);
            lrow[r2] = lrow[r2] * scl[r2] + rsum[r2];
        }
        #pragma unroll
        for (int nf = 0; nf < 8; nf++) {
            O[nf][0] *= scl[0]; O[nf][1] *= scl[0];
            O[nf][2] *= scl[1]; O[nf][3] *= scl[1];
        }

        uint32_t Ph[4][4], Pl[4][4];
        #pragma unroll
        for (int f = 0; f < 4; f++) {
            float p0 = sc[2*f][0],   p1 = sc[2*f][1],   p2 = sc[2*f][2],   p3 = sc[2*f][3];
            float q0 = sc[2*f+1][0], q1 = sc[2*f+1][1], q2 = sc[2*f+1][2], q3 = sc[2*f+1][3];
            Ph[f][0] = packh2(p0, p1); Ph[f][1] = packh2(p2, p3);
            Ph[f][2] = packh2(q0, q1); Ph[f][3] = packh2(q2, q3);
            Pl[f][0] = packh2(p0 - __half2float(__float2half_rn(p0)),
                              p1 - __half2float(__float2half_rn(p1)));
            Pl[f][1] = packh2(p2 - __half2float(__float2half_rn(p2)),
                              p3 - __half2float(__float2half_rn(p3)));
            Pl[f][2] = packh2(q0 - __half2float(__float2half_rn(q0)),
                              q1 - __half2float(__float2half_rn(q1)));
            Pl[f][3] = packh2(q2 - __half2float(__float2half_rn(q2)),
                              q3 - __half2float(__float2half_rn(q3)));
        }

        #pragma unroll
        for (int nf = 0; nf < 8; nf++) {
            uint32_t va[4], vb[4];
            const __half* vrow = &Vb[(nf * 8 + (lane & 7)) * VSTR + (lane >> 3) * 8];
            ldmx4(va, vrow);
            ldmx4(vb, vrow + 32);
            mma16816(O[nf], Ph[0], va[0], va[1]);
            mma16816(O[nf], Ph[1], va[2], va[3]);
            mma16816(O[nf], Ph[2], vb[0], vb[1]);
            mma16816(O[nf], Ph[3], vb[2], vb[3]);
            mma16816(O[nf], Pl[0], va[0], va[1]);
            mma16816(O[nf], Pl[1], va[2], va[3]);
            mma16816(O[nf], Pl[2], vb[0], vb[1]);
            mma16816(O[nf], Pl[3], vb[2], vb[3]);
        }
        __syncthreads();
    }

    float inv0 = 1.0f / lrow[0], inv1 = 1.0f / lrow[1];
    size_t r0g = (size_t)b * T_ + irow0;
    size_t r1g = r0g + 8;
    #pragma unroll
    for (int nf = 0; nf < 8; nf++) {
        int col = h * DH + nf * 8 + t2;
        float v00 = O[nf][0] * inv0, v01 = O[nf][1] * inv0;
        float v10 = O[nf][2] * inv1, v11 = O[nf][3] * inv1;
        __half h00 = __float2half_rn(v00), h01 = __float2half_rn(v01);
        __half h10 = __float2half_rn(v10), h11 = __float2half_rn(v11);
        *reinterpret_cast<uint32_t*>(&ax[r0g * K2 + col]) = packh2(v00, v01);
        *reinterpret_cast<uint32_t*>(&ax[r1g * K2 + col]) = packh2(v10, v11);
        *reinterpret_cast<uint32_t*>(&ax[r0g * K2 + KW + col]) =
            packh2(v00 - __half2float(h00), v01 - __half2float(h01));
        *reinterpret_cast<uint32_t*>(&ax[r1g * K2 + KW + col]) =
            packh2(v10 - __half2float(h10), v11 - __half2float(h11));
    }
}

extern "C" void kernel_launch(void* const* d_in, const int* in_sizes, int n_in,
                              void* d_out, int out_size) {
    const float* x  = (const float*)d_in[0];
    const float* wq = (const float*)d_in[1];
    const float* wk = (const float*)d_in[2];
    const float* wv = (const float*)d_in[3];
    const float* wo = (const float*)d_in[4];
    float* out = (float*)d_out;

    __half *ax, *wt1, *wt2, *qsp, *ksp, *vt;
    float *kr, *vr;
    float2* ropet;
    cudaGetSymbolAddress((void**)&ax,    g_ax);
    cudaGetSymbolAddress((void**)&wt1,   g_wt1);
    cudaGetSymbolAddress((void**)&wt2,   g_wt2);
    cudaGetSymbolAddress((void**)&kr,    g_kr);
    cudaGetSymbolAddress((void**)&vr,    g_vr);
    cudaGetSymbolAddress((void**)&qsp,   g_qsp);
    cudaGetSymbolAddress((void**)&ksp,   g_ksp);
    cudaGetSymbolAddress((void**)&vt,    g_vt);
    cudaGetSymbolAddress((void**)&ropet, g_ropet);

    const int out_elems = B_ * T_ * DM;
    const int kv_elems  = B_ * NKV * T_ * DH;
    float* kout = kr; float* vout = vr;
    if (out_size >= out_elems + 2 * kv_elems) {
        kout = out + out_elems;
        vout = out + out_elems + kv_elems;
    }

    const int gemm1_smem = (2 * A1STG + 2 * B1STG) * 2;                    // 55296 B
    const int gemm2_smem = (2 * A2STG + 2 * B2STG) * 2;                    // 55296 B
    cudaFuncSetAttribute(gemm_qkv_kernel, cudaFuncAttributeMaxDynamicSharedMemorySize, gemm1_smem);
    cudaFuncSetAttribute(gemm_out_kernel, cudaFuncAttributeMaxDynamicSharedMemorySize, gemm2_smem);
    const int attn_smem = (64 * QSTR + 2 * 64 * KSTR + 2 * 64 * VSTR) * 2; // 54272 B
    cudaFuncSetAttribute(attn_mma_kernel, cudaFuncAttributeMaxDynamicSharedMemorySize, attn_smem);

    const int prep_total = N_ACT4 + N_W1 + N_W2 + N_TAB;
    prep_kernel<<<(prep_total + 255)/256, 256>>>(x, wq, wk, wv, wo, ax, wt1, wt2, ropet);

    gemm_qkv_kernel<<<dim3(1280/128, MROWS/64), 128, gemm1_smem>>>(ax, wt1, qsp, ksp,
                                                                   kout, vout, ropet);
    attn_mma_kernel<<<B_ * NH * (T_/64), 128, attn_smem>>>(qsp, ksp, vt, ax);
    gemm_out_kernel<<<dim3(DM/64, MROWS/128), 128, gemm2_smem>>>(ax, wt2, out, DM);
}